// round 1
// baseline (speedup 1.0000x reference)
#include <cuda_runtime.h>
#include <cuda_bf16.h>
#include <math.h>

// Problem constants
#define BATCH 4
#define CIN   3
#define HW    224
#define PATCH 16
#define DIM   256
#define HEADS 8
#define HD    32          // DIM/HEADS
#define HP    14          // HW/PATCH
#define NTOK  196         // HP*HP
#define DP    8192        // PATCH*PATCH*DIM/HEADS
#define PIX   50176       // HW*HW

// ---------------- scratch (device globals; no allocation allowed) ----------
__device__ float g_xe[BATCH * NTOK * DIM];                 // [b,n,c]
__device__ float g_q[BATCH * HEADS * NTOK * HD];           // [b,h,n,d]
__device__ float g_k[BATCH * HEADS * NTOK * HD];
__device__ float g_attn[BATCH * HEADS * NTOK * NTOK];      // [b,h,n,m]
__device__ float g_vu[(size_t)BATCH * HEADS * NTOK * DP];  // [b,h,m,d']  205MB
__device__ float g_pre[(size_t)BATCH * DIM * HW * HW];     // NCHW fold   205MB

// ---------------- 1) patch embed: strided conv -> xe[b,n,c] ----------------
__global__ void patch_embed_kernel(const float* __restrict__ x,
                                   const float* __restrict__ w,
                                   const float* __restrict__ bias) {
    int bn = blockIdx.x;            // b*196 + n
    int b = bn / NTOK, n = bn % NTOK;
    int hp = n / HP, wp = n % HP;
    __shared__ float sp[CIN * PATCH * PATCH];   // 768
    for (int i = threadIdx.x; i < CIN * PATCH * PATCH; i += blockDim.x) {
        int ci = i / (PATCH * PATCH);
        int r  = (i / PATCH) % PATCH;
        int cc = i % PATCH;
        sp[i] = x[(((size_t)b * CIN + ci) * HW + hp * PATCH + r) * HW + wp * PATCH + cc];
    }
    __syncthreads();
    int co = threadIdx.x;           // 256 threads
    float acc = bias[co];
    const float* wr = w + (size_t)co * (CIN * PATCH * PATCH);
#pragma unroll 8
    for (int j = 0; j < CIN * PATCH * PATCH; j++) acc = fmaf(sp[j], wr[j], acc);
    g_xe[(size_t)bn * DIM + co] = acc;
}

// ---------------- 2) qk projection -> q,k [b,h,n,d] -------------------------
__global__ void qk_kernel(const float* __restrict__ qkw) {
    int bn = blockIdx.x;
    int b = bn / NTOK, n = bn % NTOK;
    __shared__ float sx[DIM];
    sx[threadIdx.x] = g_xe[(size_t)bn * DIM + threadIdx.x];
    __syncthreads();
    int h = threadIdx.x / HD, d = threadIdx.x % HD;
#pragma unroll
    for (int s = 0; s < 2; s++) {
        int r = s * DIM + threadIdx.x;
        const float* wr = qkw + (size_t)r * DIM;
        float acc = 0.f;
#pragma unroll 8
        for (int j = 0; j < DIM; j++) acc = fmaf(sx[j], wr[j], acc);
        float* dst = (s == 0) ? g_q : g_k;
        dst[(((size_t)b * HEADS + h) * NTOK + n) * HD + d] = acc;
    }
}

// ---------------- 3) scores + softmax -> attn[b,h,n,m] ----------------------
__global__ void softmax_kernel() {
    int bhn = blockIdx.x;           // (b*8+h)*196 + n
    int bh = bhn / NTOK, n = bhn % NTOK;
    __shared__ float sq[HD];
    __shared__ float sk[NTOK * HD];     // 25088B
    __shared__ float red[256];
    const float* kb = g_k + (size_t)bh * NTOK * HD;
    for (int i = threadIdx.x; i < NTOK * HD; i += 256) sk[i] = kb[i];
    if (threadIdx.x < HD) sq[threadIdx.x] = g_q[((size_t)bh * NTOK + n) * HD + threadIdx.x];
    __syncthreads();
    int m = threadIdx.x;
    float s = -INFINITY;
    if (m < NTOK) {
        float acc = 0.f;
#pragma unroll
        for (int d = 0; d < HD; d++) acc = fmaf(sq[d], sk[m * HD + d], acc);
        s = acc * 0.17677669529663687f;   // 32^-0.5
    }
    red[threadIdx.x] = s;
    __syncthreads();
    for (int off = 128; off > 0; off >>= 1) {
        if (threadIdx.x < off) red[threadIdx.x] = fmaxf(red[threadIdx.x], red[threadIdx.x + off]);
        __syncthreads();
    }
    float mx = red[0];
    __syncthreads();
    float e = (m < NTOK) ? expf(s - mx) : 0.f;
    red[threadIdx.x] = e;
    __syncthreads();
    for (int off = 128; off > 0; off >>= 1) {
        if (threadIdx.x < off) red[threadIdx.x] += red[threadIdx.x + off];
        __syncthreads();
    }
    float inv = 1.f / red[0];
    if (m < NTOK) g_attn[(size_t)bhn * NTOK + m] = e * inv;
}

// ---------------- 4) conv3x3 (V) fused with unfold -> vu[b,h,m,d'] ----------
__global__ void convv_unfold_kernel(const float* __restrict__ x,
                                    const float* __restrict__ vw,
                                    const float* __restrict__ vb) {
    int y = blockIdx.x;     // 224
    int c = blockIdx.y;     // 256
    int b = blockIdx.z;     // 4
    __shared__ float sp[CIN][3][HW + 2];
    int tid = threadIdx.x;  // 224
    for (int i = tid; i < CIN * 3 * (HW + 2); i += HW) {
        int ci = i / (3 * (HW + 2));
        int r  = (i / (HW + 2)) % 3;
        int xx = i % (HW + 2);          // xcoord = xx - 1
        int yy = y + r - 1;
        int xc = xx - 1;
        float val = 0.f;
        if (yy >= 0 && yy < HW && xc >= 0 && xc < HW)
            val = x[(((size_t)b * CIN + ci) * HW + yy) * HW + xc];
        sp[ci][r][xx] = val;
    }
    __syncthreads();
    float acc = vb[c];
#pragma unroll
    for (int ci = 0; ci < CIN; ci++)
#pragma unroll
        for (int r = 0; r < 3; r++)
#pragma unroll
            for (int dx = 0; dx < 3; dx++)
                acc = fmaf(sp[ci][r][tid + dx], vw[((c * CIN + ci) * 3 + r) * 3 + dx], acc);
    // scatter into unfolded layout
    int hp = y >> 4, pi = y & 15;
    int wp = tid >> 4, pj = tid & 15;
    int n  = hp * HP + wp;
    int h  = c >> 5, cr = c & 31;
    int dp = cr * 256 + pi * PATCH + pj;
    g_vu[(((size_t)b * HEADS + h) * NTOK + n) * DP + dp] = acc;
}

// ---------------- 5) attn @ vu  -> pre (NCHW, fused fold) -------------------
// per (b,h): C[196,8192] = A[196,196] @ B[196,8192]
__global__ void gemm_attn_vu_kernel() {
    const int bh = blockIdx.z;
    const int b = bh >> 3, h = bh & 7;
    const float* A  = g_attn + (size_t)bh * NTOK * NTOK;
    const float* Bm = g_vu + (size_t)bh * NTOK * DP;
    const int row0 = blockIdx.y * 64;
    const int col0 = blockIdx.x * 64;
    __shared__ float As[64][17];
    __shared__ float Bs[16][64];
    const int t = threadIdx.x;
    const int tx = t & 15, ty = t >> 4;
    float acc[4][4] = {};
    for (int kk = 0; kk < NTOK; kk += 16) {
#pragma unroll
        for (int p = 0; p < 4; p++) {
            int idx = t + p * 256;
            int m = idx >> 4, kl = idx & 15;
            int gr = row0 + m, gk = kk + kl;
            As[m][kl] = (gr < NTOK && gk < NTOK) ? A[gr * NTOK + gk] : 0.f;
        }
#pragma unroll
        for (int p = 0; p < 4; p++) {
            int idx = t + p * 256;
            int kl = idx >> 6, nn = idx & 63;
            int gk = kk + kl;
            Bs[kl][nn] = (gk < NTOK) ? Bm[(size_t)gk * DP + col0 + nn] : 0.f;
        }
        __syncthreads();
#pragma unroll
        for (int kl = 0; kl < 16; kl++) {
            float a0 = As[ty * 4 + 0][kl];
            float a1 = As[ty * 4 + 1][kl];
            float a2 = As[ty * 4 + 2][kl];
            float a3 = As[ty * 4 + 3][kl];
            float4 bv = *(const float4*)&Bs[kl][tx * 4];
            acc[0][0] = fmaf(a0, bv.x, acc[0][0]); acc[0][1] = fmaf(a0, bv.y, acc[0][1]);
            acc[0][2] = fmaf(a0, bv.z, acc[0][2]); acc[0][3] = fmaf(a0, bv.w, acc[0][3]);
            acc[1][0] = fmaf(a1, bv.x, acc[1][0]); acc[1][1] = fmaf(a1, bv.y, acc[1][1]);
            acc[1][2] = fmaf(a1, bv.z, acc[1][2]); acc[1][3] = fmaf(a1, bv.w, acc[1][3]);
            acc[2][0] = fmaf(a2, bv.x, acc[2][0]); acc[2][1] = fmaf(a2, bv.y, acc[2][1]);
            acc[2][2] = fmaf(a2, bv.z, acc[2][2]); acc[2][3] = fmaf(a2, bv.w, acc[2][3]);
            acc[3][0] = fmaf(a3, bv.x, acc[3][0]); acc[3][1] = fmaf(a3, bv.y, acc[3][1]);
            acc[3][2] = fmaf(a3, bv.z, acc[3][2]); acc[3][3] = fmaf(a3, bv.w, acc[3][3]);
        }
        __syncthreads();
    }
    // epilogue: fold scatter into NCHW pre
#pragma unroll
    for (int i = 0; i < 4; i++) {
        int n = row0 + ty * 4 + i;
        if (n >= NTOK) continue;
        int hp = n / HP, wp = n % HP;
#pragma unroll
        for (int j = 0; j < 4; j++) {
            int dp = col0 + tx * 4 + j;
            int cr  = dp >> 8;
            int rem = dp & 255;
            int pi = rem >> 4, pj = rem & 15;
            int c = h * 32 + cr;
            int yy = hp * PATCH + pi, xx = wp * PATCH + pj;
            g_pre[(((size_t)b * DIM + c) * HW + yy) * HW + xx] = acc[i][j];
        }
    }
}

// ---------------- 6) 1x1 proj: out[co,pix] = proj_w @ pre + b ---------------
// per batch: C[256,50176] = A[256,256] @ B[256,50176]
__global__ void gemm_proj_kernel(const float* __restrict__ pw,
                                 const float* __restrict__ pb,
                                 float* __restrict__ out) {
    const int b = blockIdx.z;
    const float* Bm = g_pre + (size_t)b * DIM * PIX;
    float* C = out + (size_t)b * DIM * PIX;
    const int row0 = blockIdx.y * 64;   // co
    const int col0 = blockIdx.x * 64;   // pixel
    __shared__ float As[64][17];
    __shared__ float Bs[16][64];
    const int t = threadIdx.x;
    const int tx = t & 15, ty = t >> 4;
    float acc[4][4] = {};
    for (int kk = 0; kk < DIM; kk += 16) {
#pragma unroll
        for (int p = 0; p < 4; p++) {
            int idx = t + p * 256;
            int m = idx >> 4, kl = idx & 15;
            As[m][kl] = pw[(size_t)(row0 + m) * DIM + kk + kl];
        }
#pragma unroll
        for (int p = 0; p < 4; p++) {
            int idx = t + p * 256;
            int kl = idx >> 6, nn = idx & 63;
            Bs[kl][nn] = Bm[(size_t)(kk + kl) * PIX + col0 + nn];
        }
        __syncthreads();
#pragma unroll
        for (int kl = 0; kl < 16; kl++) {
            float a0 = As[ty * 4 + 0][kl];
            float a1 = As[ty * 4 + 1][kl];
            float a2 = As[ty * 4 + 2][kl];
            float a3 = As[ty * 4 + 3][kl];
            float4 bv = *(const float4*)&Bs[kl][tx * 4];
            acc[0][0] = fmaf(a0, bv.x, acc[0][0]); acc[0][1] = fmaf(a0, bv.y, acc[0][1]);
            acc[0][2] = fmaf(a0, bv.z, acc[0][2]); acc[0][3] = fmaf(a0, bv.w, acc[0][3]);
            acc[1][0] = fmaf(a1, bv.x, acc[1][0]); acc[1][1] = fmaf(a1, bv.y, acc[1][1]);
            acc[1][2] = fmaf(a1, bv.z, acc[1][2]); acc[1][3] = fmaf(a1, bv.w, acc[1][3]);
            acc[2][0] = fmaf(a2, bv.x, acc[2][0]); acc[2][1] = fmaf(a2, bv.y, acc[2][1]);
            acc[2][2] = fmaf(a2, bv.z, acc[2][2]); acc[2][3] = fmaf(a2, bv.w, acc[2][3]);
            acc[3][0] = fmaf(a3, bv.x, acc[3][0]); acc[3][1] = fmaf(a3, bv.y, acc[3][1]);
            acc[3][2] = fmaf(a3, bv.z, acc[3][2]); acc[3][3] = fmaf(a3, bv.w, acc[3][3]);
        }
        __syncthreads();
    }
#pragma unroll
    for (int i = 0; i < 4; i++) {
        int co = row0 + ty * 4 + i;
        float bias = pb[co];
        float4 v;
        v.x = acc[i][0] + bias; v.y = acc[i][1] + bias;
        v.z = acc[i][2] + bias; v.w = acc[i][3] + bias;
        *(float4*)&C[(size_t)co * PIX + col0 + tx * 4] = v;
    }
}

// ---------------- launch -----------------------------------------------------
extern "C" void kernel_launch(void* const* d_in, const int* in_sizes, int n_in,
                              void* d_out, int out_size) {
    const float* x       = (const float*)d_in[0];
    const float* patch_w = (const float*)d_in[1];
    const float* patch_b = (const float*)d_in[2];
    const float* qk_w    = (const float*)d_in[3];
    const float* v_w     = (const float*)d_in[4];
    const float* v_b     = (const float*)d_in[5];
    const float* proj_w  = (const float*)d_in[6];
    const float* proj_b  = (const float*)d_in[7];
    float* out = (float*)d_out;

    patch_embed_kernel<<<BATCH * NTOK, 256>>>(x, patch_w, patch_b);
    qk_kernel<<<BATCH * NTOK, 256>>>(qk_w);
    softmax_kernel<<<BATCH * HEADS * NTOK, 256>>>();
    convv_unfold_kernel<<<dim3(HW, DIM, BATCH), HW>>>(x, v_w, v_b);
    gemm_attn_vu_kernel<<<dim3(DP / 64, (NTOK + 63) / 64, BATCH * HEADS), 256>>>();
    gemm_proj_kernel<<<dim3(PIX / 64, DIM / 64, BATCH), 256>>>(proj_w, proj_b, out);
}

// round 3
// speedup vs baseline: 1.7278x; 1.7278x over previous
#include <cuda_runtime.h>
#include <cuda_bf16.h>
#include <math.h>

// Problem constants
#define BATCH 4
#define CIN   3
#define HW    224
#define PATCH 16
#define DIM   256
#define HEADS 8
#define HD    32          // DIM/HEADS
#define HP    14          // HW/PATCH
#define NTOK  196         // HP*HP
#define DP    8192        // PATCH*PATCH*DIM/HEADS
#define PIX   50176       // HW*HW

// ---------------- scratch (device globals; no allocation allowed) ----------
__device__ __align__(16) float g_xe[BATCH * NTOK * DIM];                 // [b,n,c]
__device__ __align__(16) float g_q[BATCH * HEADS * NTOK * HD];           // [b,h,n,d]
__device__ __align__(16) float g_k[BATCH * HEADS * NTOK * HD];
__device__ __align__(16) float g_attn[BATCH * HEADS * NTOK * NTOK];      // [b,h,n,m]
__device__ __align__(16) float g_vu[(size_t)BATCH * HEADS * NTOK * DP];  // [b,h,m,d']
__device__ __align__(16) float g_pre[(size_t)BATCH * DIM * HW * HW];     // NCHW fold

// ---------------- 1) patch embed: strided conv -> xe[b,n,c] ----------------
__global__ void patch_embed_kernel(const float* __restrict__ x,
                                   const float* __restrict__ w,
                                   const float* __restrict__ bias) {
    int bn = blockIdx.x;            // b*196 + n
    int b = bn / NTOK, n = bn % NTOK;
    int hp = n / HP, wp = n % HP;
    __shared__ float sp[CIN * PATCH * PATCH];   // 768
    for (int i = threadIdx.x; i < CIN * PATCH * PATCH; i += blockDim.x) {
        int ci = i / (PATCH * PATCH);
        int r  = (i / PATCH) % PATCH;
        int cc = i % PATCH;
        sp[i] = x[(((size_t)b * CIN + ci) * HW + hp * PATCH + r) * HW + wp * PATCH + cc];
    }
    __syncthreads();
    int co = threadIdx.x;           // 256 threads
    float acc = bias[co];
    const float* wr = w + (size_t)co * (CIN * PATCH * PATCH);
#pragma unroll 8
    for (int j = 0; j < CIN * PATCH * PATCH; j++) acc = fmaf(sp[j], wr[j], acc);
    g_xe[(size_t)bn * DIM + co] = acc;
}

// ---------------- 2) qk projection -> q,k [b,h,n,d] -------------------------
__global__ void qk_kernel(const float* __restrict__ qkw) {
    int bn = blockIdx.x;
    int b = bn / NTOK, n = bn % NTOK;
    __shared__ float sx[DIM];
    sx[threadIdx.x] = g_xe[(size_t)bn * DIM + threadIdx.x];
    __syncthreads();
    int h = threadIdx.x / HD, d = threadIdx.x % HD;
#pragma unroll
    for (int s = 0; s < 2; s++) {
        int r = s * DIM + threadIdx.x;
        const float* wr = qkw + (size_t)r * DIM;
        float acc = 0.f;
#pragma unroll 8
        for (int j = 0; j < DIM; j++) acc = fmaf(sx[j], wr[j], acc);
        float* dst = (s == 0) ? g_q : g_k;
        dst[(((size_t)b * HEADS + h) * NTOK + n) * HD + d] = acc;
    }
}

// ---------------- 3) scores + softmax -> attn[b,h,n,m] ----------------------
__global__ void softmax_kernel() {
    int bhn = blockIdx.x;           // (b*8+h)*196 + n
    int bh = bhn / NTOK, n = bhn % NTOK;
    __shared__ float sq[HD];
    __shared__ float sk[NTOK * HD];
    __shared__ float red[256];
    const float* kb = g_k + (size_t)bh * NTOK * HD;
    for (int i = threadIdx.x; i < NTOK * HD; i += 256) sk[i] = kb[i];
    if (threadIdx.x < HD) sq[threadIdx.x] = g_q[((size_t)bh * NTOK + n) * HD + threadIdx.x];
    __syncthreads();
    int m = threadIdx.x;
    float s = -INFINITY;
    if (m < NTOK) {
        float acc = 0.f;
#pragma unroll
        for (int d = 0; d < HD; d++) acc = fmaf(sq[d], sk[m * HD + d], acc);
        s = acc * 0.17677669529663687f;   // 32^-0.5
    }
    red[threadIdx.x] = s;
    __syncthreads();
    for (int off = 128; off > 0; off >>= 1) {
        if (threadIdx.x < off) red[threadIdx.x] = fmaxf(red[threadIdx.x], red[threadIdx.x + off]);
        __syncthreads();
    }
    float mx = red[0];
    __syncthreads();
    float e = (m < NTOK) ? expf(s - mx) : 0.f;
    red[threadIdx.x] = e;
    __syncthreads();
    for (int off = 128; off > 0; off >>= 1) {
        if (threadIdx.x < off) red[threadIdx.x] += red[threadIdx.x + off];
        __syncthreads();
    }
    float inv = 1.f / red[0];
    if (m < NTOK) g_attn[(size_t)bhn * NTOK + m] = e * inv;
}

// ---------------- 4) conv3x3 (V) fused with unfold -> vu[b,h,m,d'] ----------
__global__ __launch_bounds__(256) void convv_unfold_kernel(
        const float* __restrict__ x,
        const float* __restrict__ vw,
        const float* __restrict__ vb) {
    const int y = blockIdx.x;   // 224
    const int b = blockIdx.y;   // 4
    __shared__ __align__(16) float srow[CIN][3][226];
    __shared__ __align__(16) float sw[DIM][28];
    __shared__ float sb[DIM];
    const int t = threadIdx.x;

    // weights: thread t handles channel t
    {
#pragma unroll
        for (int j = 0; j < 27; j++) sw[t][j] = vw[t * 27 + j];
        sw[t][27] = 0.f;
        sb[t] = vb[t];
    }
    // input rows with halo
    for (int i = t; i < CIN * 3 * 226; i += 256) {
        int ci = i / (3 * 226);
        int r  = (i / 226) % 3;
        int xx = i % 226;
        int yy = y + r - 1;
        int xc = xx - 1;
        float v = 0.f;
        if (yy >= 0 && yy < HW && xc >= 0 && xc < HW)
            v = x[(((size_t)b * CIN + ci) * HW + yy) * HW + xc];
        srow[ci][r][xx] = v;
    }
    __syncthreads();
    if (t >= HW) return;

    float xv[28];
#pragma unroll
    for (int ci = 0; ci < CIN; ci++)
#pragma unroll
        for (int r = 0; r < 3; r++)
#pragma unroll
            for (int dx = 0; dx < 3; dx++)
                xv[(ci * 3 + r) * 3 + dx] = srow[ci][r][t + dx];
    xv[27] = 0.f;

    const int hp = y >> 4, pi = y & 15;
    const int wp = t >> 4, pj = t & 15;
    const int n = hp * HP + wp;
    const size_t outbase = ((size_t)b * HEADS) * ((size_t)NTOK * DP)
                         + (size_t)n * DP + pi * PATCH + pj;
#pragma unroll 1
    for (int h = 0; h < HEADS; h++) {
        const size_t hbase = outbase + (size_t)h * ((size_t)NTOK * DP);
#pragma unroll 4
        for (int cr = 0; cr < 32; cr++) {
            const int c = h * 32 + cr;
            float acc = sb[c];
#pragma unroll
            for (int q = 0; q < 7; q++) {
                float4 w4 = *(const float4*)&sw[c][q * 4];
                acc = fmaf(xv[q * 4 + 0], w4.x, acc);
                acc = fmaf(xv[q * 4 + 1], w4.y, acc);
                acc = fmaf(xv[q * 4 + 2], w4.z, acc);
                acc = fmaf(xv[q * 4 + 3], w4.w, acc);
            }
            g_vu[hbase + (size_t)cr * 256] = acc;
        }
    }
}

// 8x8 rank-1 FMA update on float4 fragments (no local-array casts)
#define RANK1_UPDATE(acc, a0, a1, b0, b1)                                     \
    do {                                                                      \
        acc[0][0] = fmaf(a0.x, b0.x, acc[0][0]); acc[0][1] = fmaf(a0.x, b0.y, acc[0][1]); \
        acc[0][2] = fmaf(a0.x, b0.z, acc[0][2]); acc[0][3] = fmaf(a0.x, b0.w, acc[0][3]); \
        acc[0][4] = fmaf(a0.x, b1.x, acc[0][4]); acc[0][5] = fmaf(a0.x, b1.y, acc[0][5]); \
        acc[0][6] = fmaf(a0.x, b1.z, acc[0][6]); acc[0][7] = fmaf(a0.x, b1.w, acc[0][7]); \
        acc[1][0] = fmaf(a0.y, b0.x, acc[1][0]); acc[1][1] = fmaf(a0.y, b0.y, acc[1][1]); \
        acc[1][2] = fmaf(a0.y, b0.z, acc[1][2]); acc[1][3] = fmaf(a0.y, b0.w, acc[1][3]); \
        acc[1][4] = fmaf(a0.y, b1.x, acc[1][4]); acc[1][5] = fmaf(a0.y, b1.y, acc[1][5]); \
        acc[1][6] = fmaf(a0.y, b1.z, acc[1][6]); acc[1][7] = fmaf(a0.y, b1.w, acc[1][7]); \
        acc[2][0] = fmaf(a0.z, b0.x, acc[2][0]); acc[2][1] = fmaf(a0.z, b0.y, acc[2][1]); \
        acc[2][2] = fmaf(a0.z, b0.z, acc[2][2]); acc[2][3] = fmaf(a0.z, b0.w, acc[2][3]); \
        acc[2][4] = fmaf(a0.z, b1.x, acc[2][4]); acc[2][5] = fmaf(a0.z, b1.y, acc[2][5]); \
        acc[2][6] = fmaf(a0.z, b1.z, acc[2][6]); acc[2][7] = fmaf(a0.z, b1.w, acc[2][7]); \
        acc[3][0] = fmaf(a0.w, b0.x, acc[3][0]); acc[3][1] = fmaf(a0.w, b0.y, acc[3][1]); \
        acc[3][2] = fmaf(a0.w, b0.z, acc[3][2]); acc[3][3] = fmaf(a0.w, b0.w, acc[3][3]); \
        acc[3][4] = fmaf(a0.w, b1.x, acc[3][4]); acc[3][5] = fmaf(a0.w, b1.y, acc[3][5]); \
        acc[3][6] = fmaf(a0.w, b1.z, acc[3][6]); acc[3][7] = fmaf(a0.w, b1.w, acc[3][7]); \
        acc[4][0] = fmaf(a1.x, b0.x, acc[4][0]); acc[4][1] = fmaf(a1.x, b0.y, acc[4][1]); \
        acc[4][2] = fmaf(a1.x, b0.z, acc[4][2]); acc[4][3] = fmaf(a1.x, b0.w, acc[4][3]); \
        acc[4][4] = fmaf(a1.x, b1.x, acc[4][4]); acc[4][5] = fmaf(a1.x, b1.y, acc[4][5]); \
        acc[4][6] = fmaf(a1.x, b1.z, acc[4][6]); acc[4][7] = fmaf(a1.x, b1.w, acc[4][7]); \
        acc[5][0] = fmaf(a1.y, b0.x, acc[5][0]); acc[5][1] = fmaf(a1.y, b0.y, acc[5][1]); \
        acc[5][2] = fmaf(a1.y, b0.z, acc[5][2]); acc[5][3] = fmaf(a1.y, b0.w, acc[5][3]); \
        acc[5][4] = fmaf(a1.y, b1.x, acc[5][4]); acc[5][5] = fmaf(a1.y, b1.y, acc[5][5]); \
        acc[5][6] = fmaf(a1.y, b1.z, acc[5][6]); acc[5][7] = fmaf(a1.y, b1.w, acc[5][7]); \
        acc[6][0] = fmaf(a1.z, b0.x, acc[6][0]); acc[6][1] = fmaf(a1.z, b0.y, acc[6][1]); \
        acc[6][2] = fmaf(a1.z, b0.z, acc[6][2]); acc[6][3] = fmaf(a1.z, b0.w, acc[6][3]); \
        acc[6][4] = fmaf(a1.z, b1.x, acc[6][4]); acc[6][5] = fmaf(a1.z, b1.y, acc[6][5]); \
        acc[6][6] = fmaf(a1.z, b1.z, acc[6][6]); acc[6][7] = fmaf(a1.z, b1.w, acc[6][7]); \
        acc[7][0] = fmaf(a1.w, b0.x, acc[7][0]); acc[7][1] = fmaf(a1.w, b0.y, acc[7][1]); \
        acc[7][2] = fmaf(a1.w, b0.z, acc[7][2]); acc[7][3] = fmaf(a1.w, b0.w, acc[7][3]); \
        acc[7][4] = fmaf(a1.w, b1.x, acc[7][4]); acc[7][5] = fmaf(a1.w, b1.y, acc[7][5]); \
        acc[7][6] = fmaf(a1.w, b1.z, acc[7][6]); acc[7][7] = fmaf(a1.w, b1.w, acc[7][7]); \
    } while (0)

// ---------------- 5) attn @ vu  -> pre (NCHW, fused fold) -------------------
// per (b,h): C[196,8192] = A[196,196] @ B[196,8192]
__global__ __launch_bounds__(256, 2) void gemm_attn_vu_kernel() {
    const int bh = blockIdx.z;
    const int b = bh >> 3, h = bh & 7;
    const float* __restrict__ A  = g_attn + (size_t)bh * NTOK * NTOK;
    const float* __restrict__ Bm = g_vu + (size_t)bh * NTOK * DP;
    const int row0 = blockIdx.y * 128;
    const int col0 = blockIdx.x * 128;
    __shared__ __align__(16) float As[2][8][128];
    __shared__ __align__(16) float Bs[2][8][128];
    const int t = threadIdx.x;
    const int tx = t & 15, ty = t >> 4;
    const int am = t >> 1, ak = (t & 1) * 4;
    const int bk = t >> 5, bn = (t & 31) * 4;
    float acc[8][8] = {};
    float rA0, rA1, rA2, rA3;
    float4 rB;
    {
        int gm = row0 + am;
        rA0 = (gm < NTOK && ak + 0 < NTOK) ? A[gm * NTOK + ak + 0] : 0.f;
        rA1 = (gm < NTOK && ak + 1 < NTOK) ? A[gm * NTOK + ak + 1] : 0.f;
        rA2 = (gm < NTOK && ak + 2 < NTOK) ? A[gm * NTOK + ak + 2] : 0.f;
        rA3 = (gm < NTOK && ak + 3 < NTOK) ? A[gm * NTOK + ak + 3] : 0.f;
        rB = (bk < NTOK) ? *(const float4*)&Bm[(size_t)bk * DP + col0 + bn]
                         : make_float4(0.f, 0.f, 0.f, 0.f);
        As[0][ak + 0][am] = rA0; As[0][ak + 1][am] = rA1;
        As[0][ak + 2][am] = rA2; As[0][ak + 3][am] = rA3;
        *(float4*)&Bs[0][bk][bn] = rB;
    }
    __syncthreads();
    const int NSTEP = 25;   // ceil(196/8)
    int cur = 0;
#pragma unroll 1
    for (int s = 0; s < NSTEP; s++) {
        const int kk2 = (s + 1) * 8;
        if (s + 1 < NSTEP) {
            int gm = row0 + am;
            rA0 = (gm < NTOK && kk2 + ak + 0 < NTOK) ? A[gm * NTOK + kk2 + ak + 0] : 0.f;
            rA1 = (gm < NTOK && kk2 + ak + 1 < NTOK) ? A[gm * NTOK + kk2 + ak + 1] : 0.f;
            rA2 = (gm < NTOK && kk2 + ak + 2 < NTOK) ? A[gm * NTOK + kk2 + ak + 2] : 0.f;
            rA3 = (gm < NTOK && kk2 + ak + 3 < NTOK) ? A[gm * NTOK + kk2 + ak + 3] : 0.f;
            int gk = kk2 + bk;
            rB = (gk < NTOK) ? *(const float4*)&Bm[(size_t)gk * DP + col0 + bn]
                             : make_float4(0.f, 0.f, 0.f, 0.f);
        }
#pragma unroll
        for (int k = 0; k < 8; k++) {
            float4 a0 = *(const float4*)&As[cur][k][ty * 4];
            float4 a1 = *(const float4*)&As[cur][k][64 + ty * 4];
            float4 b0 = *(const float4*)&Bs[cur][k][tx * 4];
            float4 b1 = *(const float4*)&Bs[cur][k][64 + tx * 4];
            RANK1_UPDATE(acc, a0, a1, b0, b1);
        }
        if (s + 1 < NSTEP) {
            As[cur ^ 1][ak + 0][am] = rA0; As[cur ^ 1][ak + 1][am] = rA1;
            As[cur ^ 1][ak + 2][am] = rA2; As[cur ^ 1][ak + 3][am] = rA3;
            *(float4*)&Bs[cur ^ 1][bk][bn] = rB;
            cur ^= 1;
        }
        __syncthreads();
    }
    // epilogue: fold scatter into NCHW pre (float4 per 4-col group)
#pragma unroll
    for (int rh = 0; rh < 2; rh++) {
#pragma unroll
        for (int i = 0; i < 4; i++) {
            int n = row0 + rh * 64 + ty * 4 + i;
            if (n >= NTOK) continue;
            int hp = n / HP, wp = n % HP;
#pragma unroll
            for (int ch = 0; ch < 2; ch++) {
                int dp = col0 + ch * 64 + tx * 4;
                int cr = dp >> 8;
                int rem = dp & 255;
                int pi = rem >> 4, pj = rem & 15;
                int c = h * 32 + cr;
                int yy = hp * PATCH + pi, xx = wp * PATCH + pj;
                float4 v;
                v.x = acc[rh * 4 + i][ch * 4 + 0];
                v.y = acc[rh * 4 + i][ch * 4 + 1];
                v.z = acc[rh * 4 + i][ch * 4 + 2];
                v.w = acc[rh * 4 + i][ch * 4 + 3];
                *(float4*)&g_pre[(((size_t)b * DIM + c) * HW + yy) * HW + xx] = v;
            }
        }
    }
}

// ---------------- 6) 1x1 proj: out[co,pix] = proj_w @ pre + b ---------------
// per batch: C[256,50176] = A[256,256] @ B[256,50176]
__global__ __launch_bounds__(256, 2) void gemm_proj_kernel(
        const float* __restrict__ pw,
        const float* __restrict__ pb,
        float* __restrict__ out) {
    const int b = blockIdx.z;
    const float* __restrict__ Bm = g_pre + (size_t)b * DIM * PIX;
    float* __restrict__ C = out + (size_t)b * DIM * PIX;
    const int row0 = blockIdx.y * 128;
    const int col0 = blockIdx.x * 128;
    __shared__ __align__(16) float As[2][8][128];
    __shared__ __align__(16) float Bs[2][8][128];
    const int t = threadIdx.x;
    const int tx = t & 15, ty = t >> 4;
    const int am = t >> 1, ak = (t & 1) * 4;
    const int bk = t >> 5, bn = (t & 31) * 4;
    float acc[8][8] = {};
    float4 rA, rB;
    {
        rA = *(const float4*)&pw[(size_t)(row0 + am) * DIM + ak];
        rB = *(const float4*)&Bm[(size_t)bk * PIX + col0 + bn];
        As[0][ak + 0][am] = rA.x; As[0][ak + 1][am] = rA.y;
        As[0][ak + 2][am] = rA.z; As[0][ak + 3][am] = rA.w;
        *(float4*)&Bs[0][bk][bn] = rB;
    }
    __syncthreads();
    const int NSTEP = 32;   // 256/8
    int cur = 0;
#pragma unroll 1
    for (int s = 0; s < NSTEP; s++) {
        const int kk2 = (s + 1) * 8;
        if (s + 1 < NSTEP) {
            rA = *(const float4*)&pw[(size_t)(row0 + am) * DIM + kk2 + ak];
            rB = *(const float4*)&Bm[(size_t)(kk2 + bk) * PIX + col0 + bn];
        }
#pragma unroll
        for (int k = 0; k < 8; k++) {
            float4 a0 = *(const float4*)&As[cur][k][ty * 4];
            float4 a1 = *(const float4*)&As[cur][k][64 + ty * 4];
            float4 b0 = *(const float4*)&Bs[cur][k][tx * 4];
            float4 b1 = *(const float4*)&Bs[cur][k][64 + tx * 4];
            RANK1_UPDATE(acc, a0, a1, b0, b1);
        }
        if (s + 1 < NSTEP) {
            As[cur ^ 1][ak + 0][am] = rA.x; As[cur ^ 1][ak + 1][am] = rA.y;
            As[cur ^ 1][ak + 2][am] = rA.z; As[cur ^ 1][ak + 3][am] = rA.w;
            *(float4*)&Bs[cur ^ 1][bk][bn] = rB;
            cur ^= 1;
        }
        __syncthreads();
    }
#pragma unroll
    for (int rh = 0; rh < 2; rh++) {
#pragma unroll
        for (int i = 0; i < 4; i++) {
            int co = row0 + rh * 64 + ty * 4 + i;
            float bias = pb[co];
#pragma unroll
            for (int ch = 0; ch < 2; ch++) {
                int col = col0 + ch * 64 + tx * 4;
                float4 v;
                v.x = acc[rh * 4 + i][ch * 4 + 0] + bias;
                v.y = acc[rh * 4 + i][ch * 4 + 1] + bias;
                v.z = acc[rh * 4 + i][ch * 4 + 2] + bias;
                v.w = acc[rh * 4 + i][ch * 4 + 3] + bias;
                *(float4*)&C[(size_t)co * PIX + col] = v;
            }
        }
    }
}

// ---------------- launch -----------------------------------------------------
extern "C" void kernel_launch(void* const* d_in, const int* in_sizes, int n_in,
                              void* d_out, int out_size) {
    const float* x       = (const float*)d_in[0];
    const float* patch_w = (const float*)d_in[1];
    const float* patch_b = (const float*)d_in[2];
    const float* qk_w    = (const float*)d_in[3];
    const float* v_w     = (const float*)d_in[4];
    const float* v_b     = (const float*)d_in[5];
    const float* proj_w  = (const float*)d_in[6];
    const float* proj_b  = (const float*)d_in[7];
    float* out = (float*)d_out;

    patch_embed_kernel<<<BATCH * NTOK, 256>>>(x, patch_w, patch_b);
    qk_kernel<<<BATCH * NTOK, 256>>>(qk_w);
    softmax_kernel<<<BATCH * HEADS * NTOK, 256>>>();
    convv_unfold_kernel<<<dim3(HW, BATCH), 256>>>(x, v_w, v_b);
    gemm_attn_vu_kernel<<<dim3(DP / 128, 2, BATCH * HEADS), 256>>>();
    gemm_proj_kernel<<<dim3(PIX / 128, DIM / 128, BATCH), 256>>>(proj_w, proj_b, out);
}

// round 5
// speedup vs baseline: 2.2772x; 1.3180x over previous
#include <cuda_runtime.h>
#include <cuda_bf16.h>
#include <math.h>
#include <cstdint>

// Problem constants
#define BATCH 4
#define CIN   3
#define HW    224
#define PATCH 16
#define DIM   256
#define HEADS 8
#define HD    32          // DIM/HEADS
#define HP    14          // HW/PATCH
#define NTOK  196         // HP*HP
#define DP    8192        // PATCH*PATCH*DIM/HEADS
#define PIX   50176       // HW*HW

// ---------------- scratch (device globals; no allocation allowed) ----------
__device__ __align__(16) float g_xe[BATCH * NTOK * DIM];                 // [b,n,c]
__device__ __align__(16) float g_q[BATCH * HEADS * NTOK * HD];           // [b,h,n,d]
__device__ __align__(16) float g_k[BATCH * HEADS * NTOK * HD];
__device__ __align__(16) float g_attn[BATCH * HEADS * NTOK * NTOK];      // [b,h,n,m]
__device__ __align__(16) float g_vu[(size_t)BATCH * HEADS * NTOK * DP];  // [b,h,m,d']
__device__ __align__(16) float g_pre[(size_t)BATCH * DIM * HW * HW];     // NCHW fold

__device__ __forceinline__ uint32_t cvt_tf32(float f) {
    uint32_t u; asm("cvt.rna.tf32.f32 %0, %1;" : "=r"(u) : "f"(f)); return u;
}
__device__ __forceinline__ void mma_tf32(float d[4],
        uint32_t a0, uint32_t a1, uint32_t a2, uint32_t a3,
        uint32_t b0, uint32_t b1) {
    asm volatile(
        "mma.sync.aligned.m16n8k8.row.col.f32.tf32.tf32.f32 "
        "{%0,%1,%2,%3}, {%4,%5,%6,%7}, {%8,%9}, {%0,%1,%2,%3};"
        : "+f"(d[0]), "+f"(d[1]), "+f"(d[2]), "+f"(d[3])
        : "r"(a0), "r"(a1), "r"(a2), "r"(a3), "r"(b0), "r"(b1));
}

// ---------------- 1) patch embed: strided conv -> xe[b,n,c] ----------------
__global__ void patch_embed_kernel(const float* __restrict__ x,
                                   const float* __restrict__ w,
                                   const float* __restrict__ bias) {
    int bn = blockIdx.x;            // b*196 + n
    int b = bn / NTOK, n = bn % NTOK;
    int hp = n / HP, wp = n % HP;
    __shared__ float sp[CIN * PATCH * PATCH];   // 768
    for (int i = threadIdx.x; i < CIN * PATCH * PATCH; i += blockDim.x) {
        int ci = i / (PATCH * PATCH);
        int r  = (i / PATCH) % PATCH;
        int cc = i % PATCH;
        sp[i] = x[(((size_t)b * CIN + ci) * HW + hp * PATCH + r) * HW + wp * PATCH + cc];
    }
    __syncthreads();
    int co = threadIdx.x;           // 256 threads
    float acc = bias[co];
    const float* wr = w + (size_t)co * (CIN * PATCH * PATCH);
#pragma unroll 8
    for (int j = 0; j < CIN * PATCH * PATCH; j++) acc = fmaf(sp[j], wr[j], acc);
    g_xe[(size_t)bn * DIM + co] = acc;
}

// ---------------- 2) qk projection -> q,k [b,h,n,d] -------------------------
__global__ void qk_kernel(const float* __restrict__ qkw) {
    int bn = blockIdx.x;
    int b = bn / NTOK, n = bn % NTOK;
    __shared__ float sx[DIM];
    sx[threadIdx.x] = g_xe[(size_t)bn * DIM + threadIdx.x];
    __syncthreads();
    int h = threadIdx.x / HD, d = threadIdx.x % HD;
#pragma unroll
    for (int s = 0; s < 2; s++) {
        int r = s * DIM + threadIdx.x;
        const float* wr = qkw + (size_t)r * DIM;
        float acc = 0.f;
#pragma unroll 8
        for (int j = 0; j < DIM; j++) acc = fmaf(sx[j], wr[j], acc);
        float* dst = (s == 0) ? g_q : g_k;
        dst[(((size_t)b * HEADS + h) * NTOK + n) * HD + d] = acc;
    }
}

// ---------------- 3) scores + softmax -> attn[b,h,n,m] ----------------------
__global__ void softmax_kernel() {
    int bhn = blockIdx.x;           // (b*8+h)*196 + n
    int bh = bhn / NTOK, n = bhn % NTOK;
    __shared__ float sq[HD];
    __shared__ float sk[NTOK * HD];
    __shared__ float red[256];
    const float* kb = g_k + (size_t)bh * NTOK * HD;
    for (int i = threadIdx.x; i < NTOK * HD; i += 256) sk[i] = kb[i];
    if (threadIdx.x < HD) sq[threadIdx.x] = g_q[((size_t)bh * NTOK + n) * HD + threadIdx.x];
    __syncthreads();
    int m = threadIdx.x;
    float s = -INFINITY;
    if (m < NTOK) {
        float acc = 0.f;
#pragma unroll
        for (int d = 0; d < HD; d++) acc = fmaf(sq[d], sk[m * HD + d], acc);
        s = acc * 0.17677669529663687f;   // 32^-0.5
    }
    red[threadIdx.x] = s;
    __syncthreads();
    for (int off = 128; off > 0; off >>= 1) {
        if (threadIdx.x < off) red[threadIdx.x] = fmaxf(red[threadIdx.x], red[threadIdx.x + off]);
        __syncthreads();
    }
    float mx = red[0];
    __syncthreads();
    float e = (m < NTOK) ? expf(s - mx) : 0.f;
    red[threadIdx.x] = e;
    __syncthreads();
    for (int off = 128; off > 0; off >>= 1) {
        if (threadIdx.x < off) red[threadIdx.x] += red[threadIdx.x + off];
        __syncthreads();
    }
    float inv = 1.f / red[0];
    if (m < NTOK) g_attn[(size_t)bhn * NTOK + m] = e * inv;
}

// ---------------- 4) conv3x3 (V) fused with unfold -> vu[b,h,m,d'] ----------
__global__ __launch_bounds__(256) void convv_unfold_kernel(
        const float* __restrict__ x,
        const float* __restrict__ vw,
        const float* __restrict__ vb) {
    const int y = blockIdx.x;   // 224
    const int b = blockIdx.y;   // 4
    __shared__ __align__(16) float srow[CIN][3][226];
    __shared__ __align__(16) float sw[DIM][28];
    __shared__ float sb[DIM];
    const int t = threadIdx.x;

    {
#pragma unroll
        for (int j = 0; j < 27; j++) sw[t][j] = vw[t * 27 + j];
        sw[t][27] = 0.f;
        sb[t] = vb[t];
    }
    for (int i = t; i < CIN * 3 * 226; i += 256) {
        int ci = i / (3 * 226);
        int r  = (i / 226) % 3;
        int xx = i % 226;
        int yy = y + r - 1;
        int xc = xx - 1;
        float v = 0.f;
        if (yy >= 0 && yy < HW && xc >= 0 && xc < HW)
            v = x[(((size_t)b * CIN + ci) * HW + yy) * HW + xc];
        srow[ci][r][xx] = v;
    }
    __syncthreads();
    if (t >= HW) return;

    float xv[28];
#pragma unroll
    for (int ci = 0; ci < CIN; ci++)
#pragma unroll
        for (int r = 0; r < 3; r++)
#pragma unroll
            for (int dx = 0; dx < 3; dx++)
                xv[(ci * 3 + r) * 3 + dx] = srow[ci][r][t + dx];
    xv[27] = 0.f;

    const int hp = y >> 4, pi = y & 15;
    const int wp = t >> 4, pj = t & 15;
    const int n = hp * HP + wp;
    const size_t outbase = ((size_t)b * HEADS) * ((size_t)NTOK * DP)
                         + (size_t)n * DP + pi * PATCH + pj;
#pragma unroll 1
    for (int h = 0; h < HEADS; h++) {
        const size_t hbase = outbase + (size_t)h * ((size_t)NTOK * DP);
#pragma unroll 4
        for (int cr = 0; cr < 32; cr++) {
            const int c = h * 32 + cr;
            float acc = sb[c];
#pragma unroll
            for (int q = 0; q < 7; q++) {
                float4 w4 = *(const float4*)&sw[c][q * 4];
                acc = fmaf(xv[q * 4 + 0], w4.x, acc);
                acc = fmaf(xv[q * 4 + 1], w4.y, acc);
                acc = fmaf(xv[q * 4 + 2], w4.z, acc);
                acc = fmaf(xv[q * 4 + 3], w4.w, acc);
            }
            g_vu[hbase + (size_t)cr * 256] = acc;
        }
    }
}

// ============ shared GEMM machinery (mma.sync tf32, 128x128x16) =============
// 256 threads = 8 warps in 2(m) x 4(n); warp tile 64x32; 4x4 m16n8 tiles.
// Smem stride 136 floats: frag LDS bank = 8*tg + g -> conflict-free.

#define SMEM_STRIDE 136

#define MMA_COMPUTE(As_, Bs_, cur_)                                           \
    do {                                                                      \
        _Pragma("unroll")                                                     \
        for (int kb = 0; kb < 16; kb += 8) {                                  \
            uint32_t af[4][4], bf[4][2];                                      \
            _Pragma("unroll")                                                 \
            for (int mi = 0; mi < 4; mi++) {                                  \
                int m = wm * 64 + mi * 16 + fg;                               \
                af[mi][0] = As_[cur_][kb + ftg][m];                           \
                af[mi][1] = As_[cur_][kb + ftg][m + 8];                       \
                af[mi][2] = As_[cur_][kb + ftg + 4][m];                       \
                af[mi][3] = As_[cur_][kb + ftg + 4][m + 8];                   \
            }                                                                 \
            _Pragma("unroll")                                                 \
            for (int ni = 0; ni < 4; ni++) {                                  \
                int n = wn * 32 + ni * 8 + fg;                                \
                bf[ni][0] = Bs_[cur_][kb + ftg][n];                           \
                bf[ni][1] = Bs_[cur_][kb + ftg + 4][n];                       \
            }                                                                 \
            _Pragma("unroll")                                                 \
            for (int mi = 0; mi < 4; mi++)                                    \
                _Pragma("unroll")                                             \
                for (int ni = 0; ni < 4; ni++)                                \
                    mma_tf32(acc[mi][ni], af[mi][0], af[mi][1], af[mi][2],    \
                             af[mi][3], bf[ni][0], bf[ni][1]);                \
        }                                                                     \
    } while (0)

// ---------------- 5) attn @ vu  -> pre (NCHW, fused fold) -------------------
// per (b,h): C[196,8192] = A[196,196] @ B[196,8192]
__global__ __launch_bounds__(256) void gemm_attn_vu_tc() {
    const int bh = blockIdx.z;
    const int b = bh >> 3, h = bh & 7;
    const float* __restrict__ A  = g_attn + (size_t)bh * NTOK * NTOK;
    const float* __restrict__ Bm = g_vu + (size_t)bh * NTOK * DP;
    const int row0 = blockIdx.y * 128;
    const int col0 = blockIdx.x * 128;
    __shared__ __align__(16) uint32_t As[2][16][SMEM_STRIDE];
    __shared__ __align__(16) uint32_t Bs[2][16][SMEM_STRIDE];
    const int t = threadIdx.x;
    const int lane = t & 31, w = t >> 5;
    const int wm = w & 1, wn = w >> 1;
    const int fg = lane >> 2, ftg = lane & 3;
    const int am = t >> 1, akq = (t & 1) * 8;   // A: row am, k-cols akq..akq+7
    const int bkk = t >> 5, bnf = t & 31;       // B: k-rows bkk,bkk+8, col nf*4
    float acc[4][4][4] = {};
    float ra[8]; float4 rb0, rb1;

#define AVU_LOAD(k0_)                                                         \
    do {                                                                      \
        int gm = row0 + am;                                                   \
        _Pragma("unroll")                                                     \
        for (int j = 0; j < 8; j++) {                                         \
            int k = (k0_) + akq + j;                                          \
            ra[j] = (gm < NTOK && k < NTOK) ? A[gm * NTOK + k] : 0.f;         \
        }                                                                     \
        int gk0 = (k0_) + bkk, gk1 = (k0_) + bkk + 8;                         \
        rb0 = (gk0 < NTOK) ? *(const float4*)&Bm[(size_t)gk0 * DP + col0 + bnf * 4] \
                           : make_float4(0.f, 0.f, 0.f, 0.f);                 \
        rb1 = (gk1 < NTOK) ? *(const float4*)&Bm[(size_t)gk1 * DP + col0 + bnf * 4] \
                           : make_float4(0.f, 0.f, 0.f, 0.f);                 \
    } while (0)

#define GEMM_STORE(buf_)                                                      \
    do {                                                                      \
        _Pragma("unroll")                                                     \
        for (int j = 0; j < 8; j++) As[buf_][akq + j][am] = cvt_tf32(ra[j]);  \
        uint4 u0 = make_uint4(cvt_tf32(rb0.x), cvt_tf32(rb0.y),               \
                              cvt_tf32(rb0.z), cvt_tf32(rb0.w));              \
        uint4 u1 = make_uint4(cvt_tf32(rb1.x), cvt_tf32(rb1.y),               \
                              cvt_tf32(rb1.z), cvt_tf32(rb1.w));              \
        *(uint4*)&Bs[buf_][bkk][bnf * 4]     = u0;                            \
        *(uint4*)&Bs[buf_][bkk + 8][bnf * 4] = u1;                            \
    } while (0)

    AVU_LOAD(0);
    GEMM_STORE(0);
    __syncthreads();
    const int NK = 13;   // ceil(196/16)
    int cur = 0;
#pragma unroll 1
    for (int s = 0; s < NK; s++) {
        if (s + 1 < NK) AVU_LOAD((s + 1) * 16);
        MMA_COMPUTE(As, Bs, cur);
        if (s + 1 < NK) { GEMM_STORE(cur ^ 1); cur ^= 1; }
        __syncthreads();
    }
#undef AVU_LOAD

    // epilogue: fold scatter into NCHW pre (float2 stores; dp even)
#pragma unroll
    for (int mi = 0; mi < 4; mi++) {
#pragma unroll
        for (int half = 0; half < 2; half++) {
            int m = row0 + wm * 64 + mi * 16 + fg + half * 8;
            if (m >= NTOK) continue;
            int hp = m / HP, wp = m % HP;
#pragma unroll
            for (int ni = 0; ni < 4; ni++) {
                int dp = col0 + wn * 32 + ni * 8 + ftg * 2;
                int cr = dp >> 8, rem = dp & 255;
                int pi = rem >> 4, pj = rem & 15;
                int c = h * 32 + cr;
                float2 v = make_float2(acc[mi][ni][half * 2 + 0],
                                       acc[mi][ni][half * 2 + 1]);
                *(float2*)&g_pre[(((size_t)b * DIM + c) * HW + hp * PATCH + pi) * HW
                                 + wp * PATCH + pj] = v;
            }
        }
    }
}

// ---------------- 6) 1x1 proj via mma.sync tf32 ------------------------------
// per batch: C[256,50176] = proj_w[256,256] @ pre[256,50176] + bias
__global__ __launch_bounds__(256) void gemm_proj_tc(
        const float* __restrict__ pw,
        const float* __restrict__ pb,
        float* __restrict__ out) {
    const int b = blockIdx.z;
    const float* __restrict__ Bm = g_pre + (size_t)b * DIM * PIX;
    float* __restrict__ C = out + (size_t)b * DIM * PIX;
    const int row0 = blockIdx.y * 128;
    const int col0 = blockIdx.x * 128;
    __shared__ __align__(16) uint32_t As[2][16][SMEM_STRIDE];
    __shared__ __align__(16) uint32_t Bs[2][16][SMEM_STRIDE];
    const int t = threadIdx.x;
    const int lane = t & 31, w = t >> 5;
    const int wm = w & 1, wn = w >> 1;
    const int fg = lane >> 2, ftg = lane & 3;
    const int am = t >> 1, akq = (t & 1) * 8;
    const int bkk = t >> 5, bnf = t & 31;
    float acc[4][4][4] = {};
    float ra[8]; float4 rb0, rb1;

#define PROJ_LOAD(k0_)                                                        \
    do {                                                                      \
        const float* ar = &pw[(size_t)(row0 + am) * DIM + (k0_) + akq];       \
        float4 a0 = *(const float4*)&ar[0];                                   \
        float4 a1 = *(const float4*)&ar[4];                                   \
        ra[0] = a0.x; ra[1] = a0.y; ra[2] = a0.z; ra[3] = a0.w;               \
        ra[4] = a1.x; ra[5] = a1.y; ra[6] = a1.z; ra[7] = a1.w;               \
        rb0 = *(const float4*)&Bm[(size_t)((k0_) + bkk) * PIX + col0 + bnf * 4];      \
        rb1 = *(const float4*)&Bm[(size_t)((k0_) + bkk + 8) * PIX + col0 + bnf * 4];  \
    } while (0)

    PROJ_LOAD(0);
    GEMM_STORE(0);
    __syncthreads();
    const int NK = 16;   // 256/16
    int cur = 0;
#pragma unroll 1
    for (int s = 0; s < NK; s++) {
        if (s + 1 < NK) PROJ_LOAD((s + 1) * 16);
        MMA_COMPUTE(As, Bs, cur);
        if (s + 1 < NK) { GEMM_STORE(cur ^ 1); cur ^= 1; }
        __syncthreads();
    }
#undef PROJ_LOAD

#pragma unroll
    for (int mi = 0; mi < 4; mi++) {
#pragma unroll
        for (int half = 0; half < 2; half++) {
            int co = row0 + wm * 64 + mi * 16 + fg + half * 8;
            float bias = pb[co];
            float* crow = &C[(size_t)co * PIX + col0 + wn * 32 + ftg * 2];
#pragma unroll
            for (int ni = 0; ni < 4; ni++) {
                float2 v = make_float2(acc[mi][ni][half * 2 + 0] + bias,
                                       acc[mi][ni][half * 2 + 1] + bias);
                *(float2*)&crow[ni * 8] = v;
            }
        }
    }
}

// ---------------- launch -----------------------------------------------------
extern "C" void kernel_launch(void* const* d_in, const int* in_sizes, int n_in,
                              void* d_out, int out_size) {
    const float* x       = (const float*)d_in[0];
    const float* patch_w = (const float*)d_in[1];
    const float* patch_b = (const float*)d_in[2];
    const float* qk_w    = (const float*)d_in[3];
    const float* v_w     = (const float*)d_in[4];
    const float* v_b     = (const float*)d_in[5];
    const float* proj_w  = (const float*)d_in[6];
    const float* proj_b  = (const float*)d_in[7];
    float* out = (float*)d_out;

    patch_embed_kernel<<<BATCH * NTOK, 256>>>(x, patch_w, patch_b);
    qk_kernel<<<BATCH * NTOK, 256>>>(qk_w);
    softmax_kernel<<<BATCH * HEADS * NTOK, 256>>>();
    convv_unfold_kernel<<<dim3(HW, BATCH), 256>>>(x, v_w, v_b);
    gemm_attn_vu_tc<<<dim3(DP / 128, 2, BATCH * HEADS), 256>>>();
    gemm_proj_tc<<<dim3(PIX / 128, DIM / 128, BATCH), 256>>>(proj_w, proj_b, out);
}

// round 6
// speedup vs baseline: 2.3626x; 1.0375x over previous
#include <cuda_runtime.h>
#include <cuda_bf16.h>
#include <math.h>
#include <cstdint>

// Problem constants
#define BATCH 4
#define CIN   3
#define HW    224
#define PATCH 16
#define DIM   256
#define HEADS 8
#define HD    32          // DIM/HEADS
#define HP    14          // HW/PATCH
#define NTOK  196         // HP*HP
#define DP    8192        // PATCH*PATCH*DIM/HEADS
#define PIX   50176       // HW*HW

// ---------------- scratch (device globals; no allocation allowed) ----------
__device__ __align__(16) float g_q[BATCH * HEADS * NTOK * HD];           // [b,h,n,d]
__device__ __align__(16) float g_k[BATCH * HEADS * NTOK * HD];
__device__ __align__(16) float g_attn[BATCH * HEADS * NTOK * NTOK];      // [b,h,n,m]
__device__ __align__(16) float g_vu[(size_t)BATCH * HEADS * NTOK * DP];  // [b,h,m,d']
__device__ __align__(16) float g_pre[(size_t)BATCH * DIM * HW * HW];     // NCHW fold

__device__ __forceinline__ uint32_t cvt_tf32(float f) {
    uint32_t u; asm("cvt.rna.tf32.f32 %0, %1;" : "=r"(u) : "f"(f)); return u;
}
__device__ __forceinline__ uint32_t smem_u32(const void* p) {
    uint32_t a;
    asm("{ .reg .u64 t; cvta.to.shared.u64 t, %1; cvt.u32.u64 %0, t; }" : "=r"(a) : "l"(p));
    return a;
}
__device__ __forceinline__ void mma_tf32(float d[4],
        uint32_t a0, uint32_t a1, uint32_t a2, uint32_t a3,
        uint32_t b0, uint32_t b1) {
    asm volatile(
        "mma.sync.aligned.m16n8k8.row.col.f32.tf32.tf32.f32 "
        "{%0,%1,%2,%3}, {%4,%5,%6,%7}, {%8,%9}, {%0,%1,%2,%3};"
        : "+f"(d[0]), "+f"(d[1]), "+f"(d[2]), "+f"(d[3])
        : "r"(a0), "r"(a1), "r"(a2), "r"(a3), "r"(b0), "r"(b1));
}
__device__ __forceinline__ void cp16(uint32_t dst, const float* src, bool pred) {
    asm volatile("cp.async.cg.shared.global [%0], [%1], 16, %2;"
                 :: "r"(dst), "l"(src), "r"(pred ? 16 : 0) : "memory");
}
#define CP_COMMIT() asm volatile("cp.async.commit_group;" ::: "memory")
#define CP_WAIT2()  asm volatile("cp.async.wait_group 2;" ::: "memory")

// ---------------- 1) fused patch embed + qk -> g_q/g_k ----------------------
__global__ void patchqk_kernel(const float* __restrict__ x,
                               const float* __restrict__ w,
                               const float* __restrict__ bias,
                               const float* __restrict__ qkw) {
    int bn = blockIdx.x;            // b*196 + n
    int b = bn / NTOK, n = bn % NTOK;
    int hp = n / HP, wp = n % HP;
    __shared__ float sp[CIN * PATCH * PATCH];   // 768
    __shared__ float sx[DIM];
    for (int i = threadIdx.x; i < CIN * PATCH * PATCH; i += blockDim.x) {
        int ci = i / (PATCH * PATCH);
        int r  = (i / PATCH) % PATCH;
        int cc = i % PATCH;
        sp[i] = x[(((size_t)b * CIN + ci) * HW + hp * PATCH + r) * HW + wp * PATCH + cc];
    }
    __syncthreads();
    int co = threadIdx.x;           // 256 threads
    {
        float acc = bias[co];
        const float* wr = w + (size_t)co * (CIN * PATCH * PATCH);
#pragma unroll 8
        for (int j = 0; j < CIN * PATCH * PATCH; j++) acc = fmaf(sp[j], wr[j], acc);
        sx[co] = acc;
    }
    __syncthreads();
    int h = threadIdx.x / HD, d = threadIdx.x % HD;
#pragma unroll
    for (int s = 0; s < 2; s++) {
        int r = s * DIM + threadIdx.x;
        const float* wr = qkw + (size_t)r * DIM;
        float acc = 0.f;
#pragma unroll 8
        for (int j = 0; j < DIM; j++) acc = fmaf(sx[j], wr[j], acc);
        float* dst = (s == 0) ? g_q : g_k;
        dst[(((size_t)b * HEADS + h) * NTOK + n) * HD + d] = acc;
    }
}

// ---------------- 2) conv3x3 (V) fused with unfold -> vu[b,h,m,d'] ----------
__global__ __launch_bounds__(256) void convv_unfold_kernel(
        const float* __restrict__ x,
        const float* __restrict__ vw,
        const float* __restrict__ vb) {
    const int y = blockIdx.x;   // 224
    const int b = blockIdx.y;   // 4
    __shared__ __align__(16) float srow[CIN][3][226];
    __shared__ __align__(16) float sw[DIM][28];
    __shared__ float sb[DIM];
    const int t = threadIdx.x;
    {
#pragma unroll
        for (int j = 0; j < 27; j++) sw[t][j] = vw[t * 27 + j];
        sw[t][27] = 0.f;
        sb[t] = vb[t];
    }
    for (int i = t; i < CIN * 3 * 226; i += 256) {
        int ci = i / (3 * 226);
        int r  = (i / 226) % 3;
        int xx = i % 226;
        int yy = y + r - 1;
        int xc = xx - 1;
        float v = 0.f;
        if (yy >= 0 && yy < HW && xc >= 0 && xc < HW)
            v = x[(((size_t)b * CIN + ci) * HW + yy) * HW + xc];
        srow[ci][r][xx] = v;
    }
    __syncthreads();
    if (t >= HW) return;

    float xv[28];
#pragma unroll
    for (int ci = 0; ci < CIN; ci++)
#pragma unroll
        for (int r = 0; r < 3; r++)
#pragma unroll
            for (int dx = 0; dx < 3; dx++)
                xv[(ci * 3 + r) * 3 + dx] = srow[ci][r][t + dx];
    xv[27] = 0.f;

    const int hp = y >> 4, pi = y & 15;
    const int wp = t >> 4, pj = t & 15;
    const int n = hp * HP + wp;
    const size_t outbase = ((size_t)b * HEADS) * ((size_t)NTOK * DP)
                         + (size_t)n * DP + pi * PATCH + pj;
#pragma unroll 1
    for (int h = 0; h < HEADS; h++) {
        const size_t hbase = outbase + (size_t)h * ((size_t)NTOK * DP);
#pragma unroll 4
        for (int cr = 0; cr < 32; cr++) {
            const int c = h * 32 + cr;
            float acc = sb[c];
#pragma unroll
            for (int q = 0; q < 7; q++) {
                float4 w4 = *(const float4*)&sw[c][q * 4];
                acc = fmaf(xv[q * 4 + 0], w4.x, acc);
                acc = fmaf(xv[q * 4 + 1], w4.y, acc);
                acc = fmaf(xv[q * 4 + 2], w4.z, acc);
                acc = fmaf(xv[q * 4 + 3], w4.w, acc);
            }
            g_vu[hbase + (size_t)cr * 256] = acc;
        }
    }
}

// ---------------- 3) scores + softmax -> attn[b,h,n,m] ----------------------
__global__ void softmax_kernel() {
    int bhn = blockIdx.x;           // (b*8+h)*196 + n
    int bh = bhn / NTOK, n = bhn % NTOK;
    __shared__ float sq[HD];
    __shared__ float sk[NTOK * HD];
    __shared__ float red[256];
    const float* kb = g_k + (size_t)bh * NTOK * HD;
    for (int i = threadIdx.x; i < NTOK * HD; i += 256) sk[i] = kb[i];
    if (threadIdx.x < HD) sq[threadIdx.x] = g_q[((size_t)bh * NTOK + n) * HD + threadIdx.x];
    __syncthreads();
    int m = threadIdx.x;
    float s = -INFINITY;
    if (m < NTOK) {
        float acc = 0.f;
#pragma unroll
        for (int d = 0; d < HD; d++) acc = fmaf(sq[d], sk[m * HD + d], acc);
        s = acc * 0.17677669529663687f;   // 32^-0.5
    }
    red[threadIdx.x] = s;
    __syncthreads();
    for (int off = 128; off > 0; off >>= 1) {
        if (threadIdx.x < off) red[threadIdx.x] = fmaxf(red[threadIdx.x], red[threadIdx.x + off]);
        __syncthreads();
    }
    float mx = red[0];
    __syncthreads();
    float e = (m < NTOK) ? expf(s - mx) : 0.f;
    red[threadIdx.x] = e;
    __syncthreads();
    for (int off = 128; off > 0; off >>= 1) {
        if (threadIdx.x < off) red[threadIdx.x] += red[threadIdx.x + off];
        __syncthreads();
    }
    float inv = 1.f / red[0];
    if (m < NTOK) g_attn[(size_t)bhn * NTOK + m] = e * inv;
}

// ============ GEMM machinery: mma.sync tf32, 128x128x16, cp.async 4-stage ====
// A smem: [stage][128 m][20] (16 k + pad4). B smem: [stage][16 k][136].
// 8 warps 2(m)x4(n), warp tile 64x32, fragments cvt.rna'd at load.
#define STAGES    4
#define A_STAGE_F 2560      // 128*20 floats
#define B_STAGE_F 2176      // 16*136 floats
#define GEMM_SMEM ((STAGES * (A_STAGE_F + B_STAGE_F)) * 4)   // 75776 B

#define GEMM_COMPUTE(Ast_, Bst_)                                              \
    do {                                                                      \
        _Pragma("unroll")                                                     \
        for (int kb = 0; kb < 16; kb += 8) {                                  \
            uint32_t af[4][4], bf[4][2];                                      \
            _Pragma("unroll")                                                 \
            for (int mi = 0; mi < 4; mi++) {                                  \
                int m = wm * 64 + mi * 16 + fg;                               \
                af[mi][0] = cvt_tf32(Ast_[m * 20 + kb + ftg]);                \
                af[mi][1] = cvt_tf32(Ast_[(m + 8) * 20 + kb + ftg]);          \
                af[mi][2] = cvt_tf32(Ast_[m * 20 + kb + ftg + 4]);            \
                af[mi][3] = cvt_tf32(Ast_[(m + 8) * 20 + kb + ftg + 4]);      \
            }                                                                 \
            _Pragma("unroll")                                                 \
            for (int ni = 0; ni < 4; ni++) {                                  \
                int n = wn * 32 + ni * 8 + fg;                                \
                bf[ni][0] = cvt_tf32(Bst_[(kb + ftg) * 136 + n]);             \
                bf[ni][1] = cvt_tf32(Bst_[(kb + ftg + 4) * 136 + n]);         \
            }                                                                 \
            _Pragma("unroll")                                                 \
            for (int mi = 0; mi < 4; mi++)                                    \
                _Pragma("unroll")                                             \
                for (int ni = 0; ni < 4; ni++)                                \
                    mma_tf32(acc[mi][ni], af[mi][0], af[mi][1], af[mi][2],    \
                             af[mi][3], bf[ni][0], bf[ni][1]);                \
        }                                                                     \
    } while (0)

// ---------------- 4) attn @ vu  -> pre (NCHW, fused fold) -------------------
// per (b,h): C[196,8192] = A[196,196] @ B[196,8192]
__global__ __launch_bounds__(256) void gemm_attn_vu_tc() {
    extern __shared__ __align__(16) float dynsmem[];
    float* As = dynsmem;
    float* Bs = dynsmem + STAGES * A_STAGE_F;
    const uint32_t a_u32 = smem_u32(As);
    const uint32_t b_u32 = smem_u32(Bs);

    const int bh = blockIdx.z;
    const int b = bh >> 3, h = bh & 7;
    const float* __restrict__ A  = g_attn + (size_t)bh * NTOK * NTOK;
    const float* __restrict__ Bm = g_vu + (size_t)bh * NTOK * DP;
    const int row0 = blockIdx.y * 128;
    const int col0 = blockIdx.x * 128;
    const int t = threadIdx.x;
    const int lane = t & 31, w = t >> 5;
    const int wm = w & 1, wn = w >> 1;
    const int fg = lane >> 2, ftg = lane & 3;
    const int am = t >> 1, akq = (t & 1) * 8;   // A loader: row am, 8 k's
    const int krow = t >> 4, n0 = (t & 15) * 8; // B loader: row krow, 8 n's
    float acc[4][4][4] = {};

#define AVU_ISSUE(st_, kt_)                                                   \
    do {                                                                      \
        int k0 = (kt_) * 16;                                                  \
        int gm = row0 + am;                                                   \
        const float* asrc = A + (size_t)gm * NTOK + k0 + akq;                 \
        bool pm = (gm < NTOK);                                                \
        uint32_t ad = a_u32 + (st_) * (A_STAGE_F * 4) + am * 80 + akq * 4;    \
        cp16(ad,      asrc,     pm && (k0 + akq) < NTOK);                     \
        cp16(ad + 16, asrc + 4, pm && (k0 + akq + 4) < NTOK);                 \
        int gk = k0 + krow;                                                   \
        const float* bsrc = Bm + (size_t)gk * DP + col0 + n0;                 \
        bool pk = (gk < NTOK);                                                \
        uint32_t bd = b_u32 + (st_) * (B_STAGE_F * 4) + krow * 544 + n0 * 4;  \
        cp16(bd,      bsrc,     pk);                                          \
        cp16(bd + 16, bsrc + 4, pk);                                          \
    } while (0)

    const int NK = 13;   // ceil(196/16)
#pragma unroll
    for (int p = 0; p < STAGES - 1; p++) {
        AVU_ISSUE(p, p);
        CP_COMMIT();
    }
    CP_WAIT2();
    __syncthreads();
#pragma unroll 1
    for (int it = 0; it < NK; it++) {
        int pf = it + STAGES - 1;
        if (pf < NK) AVU_ISSUE(pf & 3, pf);
        CP_COMMIT();
        const float* Ast = As + (it & 3) * A_STAGE_F;
        const float* Bst = Bs + (it & 3) * B_STAGE_F;
        GEMM_COMPUTE(Ast, Bst);
        CP_WAIT2();
        __syncthreads();
    }
#undef AVU_ISSUE

    // epilogue: fold scatter into NCHW pre (float2 stores; dp even)
#pragma unroll
    for (int mi = 0; mi < 4; mi++) {
#pragma unroll
        for (int half = 0; half < 2; half++) {
            int m = row0 + wm * 64 + mi * 16 + fg + half * 8;
            if (m >= NTOK) continue;
            int hp = m / HP, wp = m % HP;
#pragma unroll
            for (int ni = 0; ni < 4; ni++) {
                int dp = col0 + wn * 32 + ni * 8 + ftg * 2;
                int cr = dp >> 8, rem = dp & 255;
                int pi = rem >> 4, pj = rem & 15;
                int c = h * 32 + cr;
                float2 v = make_float2(acc[mi][ni][half * 2 + 0],
                                       acc[mi][ni][half * 2 + 1]);
                *(float2*)&g_pre[(((size_t)b * DIM + c) * HW + hp * PATCH + pi) * HW
                                 + wp * PATCH + pj] = v;
            }
        }
    }
}

// ---------------- 5) 1x1 proj via mma.sync tf32 ------------------------------
// per batch: C[256,50176] = proj_w[256,256] @ pre[256,50176] + bias
__global__ __launch_bounds__(256) void gemm_proj_tc(
        const float* __restrict__ pw,
        const float* __restrict__ pb,
        float* __restrict__ out) {
    extern __shared__ __align__(16) float dynsmem[];
    float* As = dynsmem;
    float* Bs = dynsmem + STAGES * A_STAGE_F;
    const uint32_t a_u32 = smem_u32(As);
    const uint32_t b_u32 = smem_u32(Bs);

    const int b = blockIdx.z;
    const float* __restrict__ Bm = g_pre + (size_t)b * DIM * PIX;
    float* __restrict__ C = out + (size_t)b * DIM * PIX;
    const int row0 = blockIdx.y * 128;
    const int col0 = blockIdx.x * 128;
    const int t = threadIdx.x;
    const int lane = t & 31, w = t >> 5;
    const int wm = w & 1, wn = w >> 1;
    const int fg = lane >> 2, ftg = lane & 3;
    const int am = t >> 1, akq = (t & 1) * 8;
    const int krow = t >> 4, n0 = (t & 15) * 8;
    float acc[4][4][4] = {};

#define PROJ_ISSUE(st_, kt_)                                                  \
    do {                                                                      \
        int k0 = (kt_) * 16;                                                  \
        const float* asrc = pw + (size_t)(row0 + am) * DIM + k0 + akq;        \
        uint32_t ad = a_u32 + (st_) * (A_STAGE_F * 4) + am * 80 + akq * 4;    \
        cp16(ad,      asrc,     true);                                        \
        cp16(ad + 16, asrc + 4, true);                                        \
        const float* bsrc = Bm + (size_t)(k0 + krow) * PIX + col0 + n0;       \
        uint32_t bd = b_u32 + (st_) * (B_STAGE_F * 4) + krow * 544 + n0 * 4;  \
        cp16(bd,      bsrc,     true);                                        \
        cp16(bd + 16, bsrc + 4, true);                                        \
    } while (0)

    const int NK = 16;   // 256/16
#pragma unroll
    for (int p = 0; p < STAGES - 1; p++) {
        PROJ_ISSUE(p, p);
        CP_COMMIT();
    }
    CP_WAIT2();
    __syncthreads();
#pragma unroll 1
    for (int it = 0; it < NK; it++) {
        int pf = it + STAGES - 1;
        if (pf < NK) PROJ_ISSUE(pf & 3, pf);
        CP_COMMIT();
        const float* Ast = As + (it & 3) * A_STAGE_F;
        const float* Bst = Bs + (it & 3) * B_STAGE_F;
        GEMM_COMPUTE(Ast, Bst);
        CP_WAIT2();
        __syncthreads();
    }
#undef PROJ_ISSUE

#pragma unroll
    for (int mi = 0; mi < 4; mi++) {
#pragma unroll
        for (int half = 0; half < 2; half++) {
            int co = row0 + wm * 64 + mi * 16 + fg + half * 8;
            float bias = pb[co];
            float* crow = &C[(size_t)co * PIX + col0 + wn * 32 + ftg * 2];
#pragma unroll
            for (int ni = 0; ni < 4; ni++) {
                float2 v = make_float2(acc[mi][ni][half * 2 + 0] + bias,
                                       acc[mi][ni][half * 2 + 1] + bias);
                *(float2*)&crow[ni * 8] = v;
            }
        }
    }
}

// ---------------- launch -----------------------------------------------------
extern "C" void kernel_launch(void* const* d_in, const int* in_sizes, int n_in,
                              void* d_out, int out_size) {
    const float* x       = (const float*)d_in[0];
    const float* patch_w = (const float*)d_in[1];
    const float* patch_b = (const float*)d_in[2];
    const float* qk_w    = (const float*)d_in[3];
    const float* v_w     = (const float*)d_in[4];
    const float* v_b     = (const float*)d_in[5];
    const float* proj_w  = (const float*)d_in[6];
    const float* proj_b  = (const float*)d_in[7];
    float* out = (float*)d_out;

    cudaFuncSetAttribute(gemm_attn_vu_tc,
                         cudaFuncAttributeMaxDynamicSharedMemorySize, GEMM_SMEM);
    cudaFuncSetAttribute(gemm_proj_tc,
                         cudaFuncAttributeMaxDynamicSharedMemorySize, GEMM_SMEM);

    patchqk_kernel<<<BATCH * NTOK, 256>>>(x, patch_w, patch_b, qk_w);
    convv_unfold_kernel<<<dim3(HW, BATCH), 256>>>(x, v_w, v_b);
    softmax_kernel<<<BATCH * HEADS * NTOK, 256>>>();
    gemm_attn_vu_tc<<<dim3(DP / 128, 2, BATCH * HEADS), 256, GEMM_SMEM>>>();
    gemm_proj_tc<<<dim3(PIX / 128, DIM / 128, BATCH), 256, GEMM_SMEM>>>(proj_w, proj_b, out);
}

// round 7
// speedup vs baseline: 3.4956x; 1.4796x over previous
#include <cuda_runtime.h>
#include <cuda_bf16.h>
#include <math.h>
#include <cstdint>

// Problem constants
#define BATCH 4
#define CIN   3
#define HW    224
#define PATCH 16
#define DIM   256
#define HEADS 8
#define HD    32          // DIM/HEADS
#define HP    14          // HW/PATCH
#define NTOK  196         // HP*HP
#define DP    8192        // PATCH*PATCH*DIM/HEADS
#define PIX   50176       // HW*HW

// ---------------- scratch (device globals; no allocation allowed) ----------
__device__ __align__(16) float g_xe[BATCH * NTOK * DIM];                 // [b,n,c]
__device__ __align__(16) float g_q[BATCH * HEADS * NTOK * HD];           // [b,h,n,d]
__device__ __align__(16) float g_k[BATCH * HEADS * NTOK * HD];
__device__ __align__(16) float g_attn[BATCH * HEADS * NTOK * NTOK];      // [b,h,n,m] (tf32-rounded)
__device__ __align__(16) float g_vu[(size_t)BATCH * HEADS * NTOK * DP];  // [b,h,m,d'] (tf32-rounded)
__device__ __align__(16) float g_pre[(size_t)BATCH * DIM * HW * HW];     // NCHW fold (tf32-rounded)
__device__ __align__(16) float g_pw[DIM * DIM];                          // tf32-rounded proj_w

__device__ __forceinline__ uint32_t cvt_tf32(float f) {
    uint32_t u; asm("cvt.rna.tf32.f32 %0, %1;" : "=r"(u) : "f"(f)); return u;
}
__device__ __forceinline__ float tf32r(float f) { return __uint_as_float(cvt_tf32(f)); }
__device__ __forceinline__ uint32_t smem_u32(const void* p) {
    uint32_t a;
    asm("{ .reg .u64 t; cvta.to.shared.u64 t, %1; cvt.u32.u64 %0, t; }" : "=r"(a) : "l"(p));
    return a;
}
__device__ __forceinline__ void mma_tf32(float d[4],
        uint32_t a0, uint32_t a1, uint32_t a2, uint32_t a3,
        uint32_t b0, uint32_t b1) {
    asm volatile(
        "mma.sync.aligned.m16n8k8.row.col.f32.tf32.tf32.f32 "
        "{%0,%1,%2,%3}, {%4,%5,%6,%7}, {%8,%9}, {%0,%1,%2,%3};"
        : "+f"(d[0]), "+f"(d[1]), "+f"(d[2]), "+f"(d[3])
        : "r"(a0), "r"(a1), "r"(a2), "r"(a3), "r"(b0), "r"(b1));
}
__device__ __forceinline__ void cp16(uint32_t dst, const float* src, bool pred) {
    asm volatile("cp.async.cg.shared.global [%0], [%1], 16, %2;"
                 :: "r"(dst), "l"(src), "r"(pred ? 16 : 0) : "memory");
}
#define CP_COMMIT() asm volatile("cp.async.commit_group;" ::: "memory")
#define CP_WAIT2()  asm volatile("cp.async.wait_group 2;" ::: "memory")

// ---------------- 0) round proj_w to tf32 ------------------------------------
__global__ void cvt_pw_kernel(const float* __restrict__ pw) {
    int i = blockIdx.x * 256 + threadIdx.x;
    g_pw[i] = tf32r(pw[i]);
}

// ---------------- 1) patch embed, 16 tokens per block -> g_xe ---------------
__global__ __launch_bounds__(256) void patch_embed16(const float* __restrict__ x,
                                                     const float* __restrict__ w,
                                                     const float* __restrict__ bias) {
    const int bn0 = blockIdx.x * 16;           // 49 blocks
    __shared__ __align__(16) float sp[16][768];
    for (int idx = threadIdx.x; idx < 16 * 768; idx += 256) {
        int i = idx / 768, j = idx - (idx / 768) * 768;
        int bn = bn0 + i;
        int b = bn / NTOK, n = bn % NTOK;
        int hp = n / HP, wp = n % HP;
        int ci = j >> 8, r = (j >> 4) & 15, cc = j & 15;
        sp[i][j] = x[(((size_t)b * CIN + ci) * HW + hp * PATCH + r) * HW + wp * PATCH + cc];
    }
    __syncthreads();
    const int co = threadIdx.x;
    const float4* wr = (const float4*)(w + (size_t)co * 768);
    float acc[16] = {};
#pragma unroll 2
    for (int j4 = 0; j4 < 192; j4++) {
        float4 w4 = wr[j4];
#pragma unroll
        for (int i = 0; i < 16; i++) {
            float4 s4 = *(const float4*)&sp[i][j4 * 4];
            acc[i] = fmaf(s4.x, w4.x, acc[i]);
            acc[i] = fmaf(s4.y, w4.y, acc[i]);
            acc[i] = fmaf(s4.z, w4.z, acc[i]);
            acc[i] = fmaf(s4.w, w4.w, acc[i]);
        }
    }
    float bco = bias[co];
#pragma unroll
    for (int i = 0; i < 16; i++)
        g_xe[(size_t)(bn0 + i) * DIM + co] = acc[i] + bco;
}

// ---------------- 2) qk projection, 16 tokens per block ----------------------
__global__ __launch_bounds__(256) void qk16(const float* __restrict__ qkw) {
    const int bn0 = blockIdx.x * 16;           // 49 blocks
    __shared__ __align__(16) float sx[16][256];
    for (int idx = threadIdx.x; idx < 16 * 256; idx += 256) {
        int i = idx >> 8, c = idx & 255;
        sx[i][c] = g_xe[(size_t)(bn0 + i) * DIM + c];
    }
    __syncthreads();
    const int t = threadIdx.x;
    const float4* w0 = (const float4*)(qkw + (size_t)t * DIM);
    const float4* w1 = (const float4*)(qkw + (size_t)(DIM + t) * DIM);
    float acc0[16] = {}, acc1[16] = {};
#pragma unroll 2
    for (int j4 = 0; j4 < 64; j4++) {
        float4 a = w0[j4];
        float4 bq = w1[j4];
#pragma unroll
        for (int i = 0; i < 16; i++) {
            float4 s4 = *(const float4*)&sx[i][j4 * 4];
            acc0[i] = fmaf(s4.x, a.x,  fmaf(s4.y, a.y,  fmaf(s4.z, a.z,  fmaf(s4.w, a.w,  acc0[i]))));
            acc1[i] = fmaf(s4.x, bq.x, fmaf(s4.y, bq.y, fmaf(s4.z, bq.z, fmaf(s4.w, bq.w, acc1[i]))));
        }
    }
    const int h = t >> 5, d = t & 31;
#pragma unroll
    for (int i = 0; i < 16; i++) {
        int bn = bn0 + i;
        int b = bn / NTOK, n = bn % NTOK;
        size_t off = (((size_t)b * HEADS + h) * NTOK + n) * HD + d;
        g_q[off] = acc0[i];
        g_k[off] = acc1[i];
    }
}

// ---------------- 3) conv3x3 (V) fused with unfold -> vu (tf32-rounded) -----
__global__ __launch_bounds__(256) void convv_unfold_kernel(
        const float* __restrict__ x,
        const float* __restrict__ vw,
        const float* __restrict__ vb) {
    const int y = blockIdx.x;   // 224
    const int b = blockIdx.y;   // 4
    __shared__ __align__(16) float srow[CIN][3][226];
    __shared__ __align__(16) float sw[DIM][28];
    __shared__ float sb[DIM];
    const int t = threadIdx.x;
    {
#pragma unroll
        for (int j = 0; j < 27; j++) sw[t][j] = vw[t * 27 + j];
        sw[t][27] = 0.f;
        sb[t] = vb[t];
    }
    for (int i = t; i < CIN * 3 * 226; i += 256) {
        int ci = i / (3 * 226);
        int r  = (i / 226) % 3;
        int xx = i % 226;
        int yy = y + r - 1;
        int xc = xx - 1;
        float v = 0.f;
        if (yy >= 0 && yy < HW && xc >= 0 && xc < HW)
            v = x[(((size_t)b * CIN + ci) * HW + yy) * HW + xc];
        srow[ci][r][xx] = v;
    }
    __syncthreads();
    if (t >= HW) return;

    float xv[28];
#pragma unroll
    for (int ci = 0; ci < CIN; ci++)
#pragma unroll
        for (int r = 0; r < 3; r++)
#pragma unroll
            for (int dx = 0; dx < 3; dx++)
                xv[(ci * 3 + r) * 3 + dx] = srow[ci][r][t + dx];
    xv[27] = 0.f;

    const int hp = y >> 4, pi = y & 15;
    const int wp = t >> 4, pj = t & 15;
    const int n = hp * HP + wp;
    const size_t outbase = ((size_t)b * HEADS) * ((size_t)NTOK * DP)
                         + (size_t)n * DP + pi * PATCH + pj;
#pragma unroll 1
    for (int h = 0; h < HEADS; h++) {
        const size_t hbase = outbase + (size_t)h * ((size_t)NTOK * DP);
#pragma unroll 4
        for (int cr = 0; cr < 32; cr++) {
            const int c = h * 32 + cr;
            float acc = sb[c];
#pragma unroll
            for (int q = 0; q < 7; q++) {
                float4 w4 = *(const float4*)&sw[c][q * 4];
                acc = fmaf(xv[q * 4 + 0], w4.x, acc);
                acc = fmaf(xv[q * 4 + 1], w4.y, acc);
                acc = fmaf(xv[q * 4 + 2], w4.z, acc);
                acc = fmaf(xv[q * 4 + 3], w4.w, acc);
            }
            g_vu[hbase + (size_t)cr * 256] = tf32r(acc);
        }
    }
}

// ---------------- 4) scores + softmax -> attn (tf32-rounded) ----------------
__global__ void softmax_kernel() {
    int bhn = blockIdx.x;           // (b*8+h)*196 + n
    int bh = bhn / NTOK, n = bhn % NTOK;
    __shared__ float sq[HD];
    __shared__ float sk[NTOK * HD];
    __shared__ float red[256];
    const float* kb = g_k + (size_t)bh * NTOK * HD;
    for (int i = threadIdx.x; i < NTOK * HD; i += 256) sk[i] = kb[i];
    if (threadIdx.x < HD) sq[threadIdx.x] = g_q[((size_t)bh * NTOK + n) * HD + threadIdx.x];
    __syncthreads();
    int m = threadIdx.x;
    float s = -INFINITY;
    if (m < NTOK) {
        float acc = 0.f;
#pragma unroll
        for (int d = 0; d < HD; d++) acc = fmaf(sq[d], sk[m * HD + d], acc);
        s = acc * 0.17677669529663687f;   // 32^-0.5
    }
    red[threadIdx.x] = s;
    __syncthreads();
    for (int off = 128; off > 0; off >>= 1) {
        if (threadIdx.x < off) red[threadIdx.x] = fmaxf(red[threadIdx.x], red[threadIdx.x + off]);
        __syncthreads();
    }
    float mx = red[0];
    __syncthreads();
    float e = (m < NTOK) ? expf(s - mx) : 0.f;
    red[threadIdx.x] = e;
    __syncthreads();
    for (int off = 128; off > 0; off >>= 1) {
        if (threadIdx.x < off) red[threadIdx.x] += red[threadIdx.x + off];
        __syncthreads();
    }
    float inv = 1.f / red[0];
    if (m < NTOK) g_attn[(size_t)bhn * NTOK + m] = tf32r(e * inv);
}

// ============ GEMM machinery: mma.sync tf32, 128x128x16, cp.async 4-stage ====
// Operands are pre-rounded to tf32 in producers -> fragment loads are raw LDS.
#define STAGES    4
#define A_STAGE_F 2560      // 128*20 floats
#define B_STAGE_F 2176      // 16*136 floats
#define GEMM_SMEM ((STAGES * (A_STAGE_F + B_STAGE_F)) * 4)   // 75776 B

#define GEMM_COMPUTE(Ast_, Bst_)                                              \
    do {                                                                      \
        _Pragma("unroll")                                                     \
        for (int kb = 0; kb < 16; kb += 8) {                                  \
            uint32_t af[4][4], bf[4][2];                                      \
            _Pragma("unroll")                                                 \
            for (int mi = 0; mi < 4; mi++) {                                  \
                int m = wm * 64 + mi * 16 + fg;                               \
                af[mi][0] = __float_as_uint(Ast_[m * 20 + kb + ftg]);         \
                af[mi][1] = __float_as_uint(Ast_[(m + 8) * 20 + kb + ftg]);   \
                af[mi][2] = __float_as_uint(Ast_[m * 20 + kb + ftg + 4]);     \
                af[mi][3] = __float_as_uint(Ast_[(m + 8) * 20 + kb + ftg + 4]); \
            }                                                                 \
            _Pragma("unroll")                                                 \
            for (int ni = 0; ni < 4; ni++) {                                  \
                int n = wn * 32 + ni * 8 + fg;                                \
                bf[ni][0] = __float_as_uint(Bst_[(kb + ftg) * 136 + n]);      \
                bf[ni][1] = __float_as_uint(Bst_[(kb + ftg + 4) * 136 + n]);  \
            }                                                                 \
            _Pragma("unroll")                                                 \
            for (int mi = 0; mi < 4; mi++)                                    \
                _Pragma("unroll")                                             \
                for (int ni = 0; ni < 4; ni++)                                \
                    mma_tf32(acc[mi][ni], af[mi][0], af[mi][1], af[mi][2],    \
                             af[mi][3], bf[ni][0], bf[ni][1]);                \
        }                                                                     \
    } while (0)

// ---------------- 5) attn @ vu  -> pre (NCHW, fused fold, tf32-rounded) -----
__global__ __launch_bounds__(256) void gemm_attn_vu_tc() {
    extern __shared__ __align__(16) float dynsmem[];
    float* As = dynsmem;
    float* Bs = dynsmem + STAGES * A_STAGE_F;
    const uint32_t a_u32 = smem_u32(As);
    const uint32_t b_u32 = smem_u32(Bs);

    const int bh = blockIdx.z;
    const int b = bh >> 3, h = bh & 7;
    const float* __restrict__ A  = g_attn + (size_t)bh * NTOK * NTOK;
    const float* __restrict__ Bm = g_vu + (size_t)bh * NTOK * DP;
    const int row0 = blockIdx.y * 128;
    const int col0 = blockIdx.x * 128;
    const int t = threadIdx.x;
    const int lane = t & 31, w = t >> 5;
    const int wm = w & 1, wn = w >> 1;
    const int fg = lane >> 2, ftg = lane & 3;
    const int am = t >> 1, akq = (t & 1) * 8;
    const int krow = t >> 4, n0 = (t & 15) * 8;
    float acc[4][4][4] = {};

#define AVU_ISSUE(st_, kt_)                                                   \
    do {                                                                      \
        int k0 = (kt_) * 16;                                                  \
        int gm = row0 + am;                                                   \
        const float* asrc = A + (size_t)gm * NTOK + k0 + akq;                 \
        bool pm = (gm < NTOK);                                                \
        uint32_t ad = a_u32 + (st_) * (A_STAGE_F * 4) + am * 80 + akq * 4;    \
        cp16(ad,      asrc,     pm && (k0 + akq) < NTOK);                     \
        cp16(ad + 16, asrc + 4, pm && (k0 + akq + 4) < NTOK);                 \
        int gk = k0 + krow;                                                   \
        const float* bsrc = Bm + (size_t)gk * DP + col0 + n0;                 \
        bool pk = (gk < NTOK);                                                \
        uint32_t bd = b_u32 + (st_) * (B_STAGE_F * 4) + krow * 544 + n0 * 4;  \
        cp16(bd,      bsrc,     pk);                                          \
        cp16(bd + 16, bsrc + 4, pk);                                          \
    } while (0)

    const int NK = 13;   // ceil(196/16)
#pragma unroll
    for (int p = 0; p < STAGES - 1; p++) {
        AVU_ISSUE(p, p);
        CP_COMMIT();
    }
    CP_WAIT2();
    __syncthreads();
#pragma unroll 1
    for (int it = 0; it < NK; it++) {
        int pf = it + STAGES - 1;
        if (pf < NK) AVU_ISSUE(pf & 3, pf);
        CP_COMMIT();
        const float* Ast = As + (it & 3) * A_STAGE_F;
        const float* Bst = Bs + (it & 3) * B_STAGE_F;
        GEMM_COMPUTE(Ast, Bst);
        CP_WAIT2();
        __syncthreads();
    }
#undef AVU_ISSUE

    // epilogue: fold scatter into NCHW pre (float2 stores; tf32-rounded)
#pragma unroll
    for (int mi = 0; mi < 4; mi++) {
#pragma unroll
        for (int half = 0; half < 2; half++) {
            int m = row0 + wm * 64 + mi * 16 + fg + half * 8;
            if (m >= NTOK) continue;
            int hp = m / HP, wp = m % HP;
#pragma unroll
            for (int ni = 0; ni < 4; ni++) {
                int dp = col0 + wn * 32 + ni * 8 + ftg * 2;
                int cr = dp >> 8, rem = dp & 255;
                int pi = rem >> 4, pj = rem & 15;
                int c = h * 32 + cr;
                float2 v = make_float2(tf32r(acc[mi][ni][half * 2 + 0]),
                                       tf32r(acc[mi][ni][half * 2 + 1]));
                *(float2*)&g_pre[(((size_t)b * DIM + c) * HW + hp * PATCH + pi) * HW
                                 + wp * PATCH + pj] = v;
            }
        }
    }
}

// ---------------- 6) 1x1 proj via mma.sync tf32 ------------------------------
__global__ __launch_bounds__(256) void gemm_proj_tc(
        const float* __restrict__ pb,
        float* __restrict__ out) {
    extern __shared__ __align__(16) float dynsmem[];
    float* As = dynsmem;
    float* Bs = dynsmem + STAGES * A_STAGE_F;
    const uint32_t a_u32 = smem_u32(As);
    const uint32_t b_u32 = smem_u32(Bs);

    const int b = blockIdx.z;
    const float* __restrict__ Bm = g_pre + (size_t)b * DIM * PIX;
    float* __restrict__ C = out + (size_t)b * DIM * PIX;
    const int row0 = blockIdx.y * 128;
    const int col0 = blockIdx.x * 128;
    const int t = threadIdx.x;
    const int lane = t & 31, w = t >> 5;
    const int wm = w & 1, wn = w >> 1;
    const int fg = lane >> 2, ftg = lane & 3;
    const int am = t >> 1, akq = (t & 1) * 8;
    const int krow = t >> 4, n0 = (t & 15) * 8;
    float acc[4][4][4] = {};

#define PROJ_ISSUE(st_, kt_)                                                  \
    do {                                                                      \
        int k0 = (kt_) * 16;                                                  \
        const float* asrc = g_pw + (size_t)(row0 + am) * DIM + k0 + akq;      \
        uint32_t ad = a_u32 + (st_) * (A_STAGE_F * 4) + am * 80 + akq * 4;    \
        cp16(ad,      asrc,     true);                                        \
        cp16(ad + 16, asrc + 4, true);                                        \
        const float* bsrc = Bm + (size_t)(k0 + krow) * PIX + col0 + n0;       \
        uint32_t bd = b_u32 + (st_) * (B_STAGE_F * 4) + krow * 544 + n0 * 4;  \
        cp16(bd,      bsrc,     true);                                        \
        cp16(bd + 16, bsrc + 4, true);                                        \
    } while (0)

    const int NK = 16;   // 256/16
#pragma unroll
    for (int p = 0; p < STAGES - 1; p++) {
        PROJ_ISSUE(p, p);
        CP_COMMIT();
    }
    CP_WAIT2();
    __syncthreads();
#pragma unroll 1
    for (int it = 0; it < NK; it++) {
        int pf = it + STAGES - 1;
        if (pf < NK) PROJ_ISSUE(pf & 3, pf);
        CP_COMMIT();
        const float* Ast = As + (it & 3) * A_STAGE_F;
        const float* Bst = Bs + (it & 3) * B_STAGE_F;
        GEMM_COMPUTE(Ast, Bst);
        CP_WAIT2();
        __syncthreads();
    }
#undef PROJ_ISSUE

#pragma unroll
    for (int mi = 0; mi < 4; mi++) {
#pragma unroll
        for (int half = 0; half < 2; half++) {
            int co = row0 + wm * 64 + mi * 16 + fg + half * 8;
            float bias = pb[co];
            float* crow = &C[(size_t)co * PIX + col0 + wn * 32 + ftg * 2];
#pragma unroll
            for (int ni = 0; ni < 4; ni++) {
                float2 v = make_float2(acc[mi][ni][half * 2 + 0] + bias,
                                       acc[mi][ni][half * 2 + 1] + bias);
                *(float2*)&crow[ni * 8] = v;
            }
        }
    }
}

// ---------------- launch -----------------------------------------------------
extern "C" void kernel_launch(void* const* d_in, const int* in_sizes, int n_in,
                              void* d_out, int out_size) {
    const float* x       = (const float*)d_in[0];
    const float* patch_w = (const float*)d_in[1];
    const float* patch_b = (const float*)d_in[2];
    const float* qk_w    = (const float*)d_in[3];
    const float* v_w     = (const float*)d_in[4];
    const float* v_b     = (const float*)d_in[5];
    const float* proj_w  = (const float*)d_in[6];
    const float* proj_b  = (const float*)d_in[7];
    float* out = (float*)d_out;

    cudaFuncSetAttribute(gemm_attn_vu_tc,
                         cudaFuncAttributeMaxDynamicSharedMemorySize, GEMM_SMEM);
    cudaFuncSetAttribute(gemm_proj_tc,
                         cudaFuncAttributeMaxDynamicSharedMemorySize, GEMM_SMEM);

    convv_unfold_kernel<<<dim3(HW, BATCH), 256>>>(x, v_w, v_b);
    patch_embed16<<<BATCH * NTOK / 16, 256>>>(x, patch_w, patch_b);
    qk16<<<BATCH * NTOK / 16, 256>>>(qk_w);
    softmax_kernel<<<BATCH * HEADS * NTOK, 256>>>();
    cvt_pw_kernel<<<DIM * DIM / 256, 256>>>(proj_w);
    gemm_attn_vu_tc<<<dim3(DP / 128, 2, BATCH * HEADS), 256, GEMM_SMEM>>>();
    gemm_proj_tc<<<dim3(PIX / 128, DIM / 128, BATCH), 256, GEMM_SMEM>>>(proj_b, out);
}

// round 8
// speedup vs baseline: 5.4731x; 1.5657x over previous
#include <cuda_runtime.h>
#include <cuda_bf16.h>
#include <math.h>
#include <cstdint>

// Problem constants
#define BATCH 4
#define CIN   3
#define HW    224
#define PATCH 16
#define DIM   256
#define HEADS 8
#define HD    32          // DIM/HEADS
#define HP    14          // HW/PATCH
#define NTOK  196         // HP*HP
#define DP    8192        // PATCH*PATCH*DIM/HEADS
#define PIX   50176       // HW*HW

// ---------------- scratch (device globals; no allocation allowed) ----------
__device__ __align__(16) float g_q[BATCH * HEADS * NTOK * HD];           // [b,h,n,d]
__device__ __align__(16) float g_k[BATCH * HEADS * NTOK * HD];
__device__ __align__(16) float g_attn[BATCH * HEADS * NTOK * NTOK];      // tf32-rounded
__device__ __align__(16) float g_vu[(size_t)BATCH * HEADS * NTOK * DP];  // tf32-rounded
__device__ __align__(16) float g_pre[(size_t)BATCH * DIM * HW * HW];     // tf32-rounded
__device__ __align__(16) float g_pw[DIM * DIM];                          // tf32-rounded proj_w

__device__ __forceinline__ uint32_t cvt_tf32(float f) {
    uint32_t u; asm("cvt.rna.tf32.f32 %0, %1;" : "=r"(u) : "f"(f)); return u;
}
__device__ __forceinline__ float tf32r(float f) { return __uint_as_float(cvt_tf32(f)); }
__device__ __forceinline__ uint32_t smem_u32(const void* p) {
    uint32_t a;
    asm("{ .reg .u64 t; cvta.to.shared.u64 t, %1; cvt.u32.u64 %0, t; }" : "=r"(a) : "l"(p));
    return a;
}
__device__ __forceinline__ void mma_tf32(float d[4],
        uint32_t a0, uint32_t a1, uint32_t a2, uint32_t a3,
        uint32_t b0, uint32_t b1) {
    asm volatile(
        "mma.sync.aligned.m16n8k8.row.col.f32.tf32.tf32.f32 "
        "{%0,%1,%2,%3}, {%4,%5,%6,%7}, {%8,%9}, {%0,%1,%2,%3};"
        : "+f"(d[0]), "+f"(d[1]), "+f"(d[2]), "+f"(d[3])
        : "r"(a0), "r"(a1), "r"(a2), "r"(a3), "r"(b0), "r"(b1));
}
__device__ __forceinline__ void cp16(uint32_t dst, const float* src, bool pred) {
    asm volatile("cp.async.cg.shared.global [%0], [%1], 16, %2;"
                 :: "r"(dst), "l"(src), "r"(pred ? 16 : 0) : "memory");
}
#define CP_COMMIT() asm volatile("cp.async.commit_group;" ::: "memory")
#define CP_WAIT2()  asm volatile("cp.async.wait_group 2;" ::: "memory")

// ---------------- 0) round proj_w to tf32 ------------------------------------
__global__ void cvt_pw_kernel(const float* __restrict__ pw) {
    int i = blockIdx.x * 256 + threadIdx.x;
    g_pw[i] = tf32r(pw[i]);
}

// ---------------- 1) fused patch embed + qk, 8 tokens per block -------------
__global__ __launch_bounds__(256) void patchqk16(const float* __restrict__ x,
                                                 const float* __restrict__ w,
                                                 const float* __restrict__ bias,
                                                 const float* __restrict__ qkw) {
    const int bn0 = blockIdx.x * 8;            // 98 blocks
    __shared__ __align__(16) float sp[8][768];
    __shared__ __align__(16) float sx[8][256];
    for (int idx = threadIdx.x; idx < 8 * 768; idx += 256) {
        int i = idx / 768, j = idx - (idx / 768) * 768;
        int bn = bn0 + i;
        int b = bn / NTOK, n = bn % NTOK;
        int hp = n / HP, wp = n % HP;
        int ci = j >> 8, r = (j >> 4) & 15, cc = j & 15;
        sp[i][j] = x[(((size_t)b * CIN + ci) * HW + hp * PATCH + r) * HW + wp * PATCH + cc];
    }
    __syncthreads();
    const int co = threadIdx.x;
    {
        const float4* wr = (const float4*)(w + (size_t)co * 768);
        float acc[8] = {};
#pragma unroll 2
        for (int j4 = 0; j4 < 192; j4++) {
            float4 w4 = wr[j4];
#pragma unroll
            for (int i = 0; i < 8; i++) {
                float4 s4 = *(const float4*)&sp[i][j4 * 4];
                acc[i] = fmaf(s4.x, w4.x, fmaf(s4.y, w4.y, fmaf(s4.z, w4.z, fmaf(s4.w, w4.w, acc[i]))));
            }
        }
        float bco = bias[co];
#pragma unroll
        for (int i = 0; i < 8; i++) sx[i][co] = acc[i] + bco;
    }
    __syncthreads();
    {
        const float4* w0 = (const float4*)(qkw + (size_t)co * DIM);
        const float4* w1 = (const float4*)(qkw + (size_t)(DIM + co) * DIM);
        float acc0[8] = {}, acc1[8] = {};
#pragma unroll 2
        for (int j4 = 0; j4 < 64; j4++) {
            float4 a = w0[j4];
            float4 bq = w1[j4];
#pragma unroll
            for (int i = 0; i < 8; i++) {
                float4 s4 = *(const float4*)&sx[i][j4 * 4];
                acc0[i] = fmaf(s4.x, a.x,  fmaf(s4.y, a.y,  fmaf(s4.z, a.z,  fmaf(s4.w, a.w,  acc0[i]))));
                acc1[i] = fmaf(s4.x, bq.x, fmaf(s4.y, bq.y, fmaf(s4.z, bq.z, fmaf(s4.w, bq.w, acc1[i]))));
            }
        }
        const int h = co >> 5, d = co & 31;
#pragma unroll
        for (int i = 0; i < 8; i++) {
            int bn = bn0 + i;
            int b = bn / NTOK, n = bn % NTOK;
            size_t off = (((size_t)b * HEADS + h) * NTOK + n) * HD + d;
            g_q[off] = acc0[i];
            g_k[off] = acc1[i];
        }
    }
}

// ---------------- 2) scores + softmax, one block per (b,h) ------------------
__global__ __launch_bounds__(256) void softmax_v2() {
    const int bh = blockIdx.x;                  // 32 blocks
    __shared__ float sk[NTOK][33];
    const float* kb = g_k + (size_t)bh * NTOK * HD;
    for (int i = threadIdx.x; i < NTOK * HD; i += 256) {
        sk[i >> 5][i & 31] = kb[i];
    }
    __syncthreads();
    const int wid = threadIdx.x >> 5, lane = threadIdx.x & 31;
    for (int n = wid; n < NTOK; n += 8) {
        float qd = g_q[((size_t)bh * NTOK + n) * HD + lane];
        float acc[7] = {};
#pragma unroll
        for (int d = 0; d < HD; d++) {
            float qv = __shfl_sync(0xffffffffu, qd, d);
#pragma unroll
            for (int j = 0; j < 7; j++) {
                int m = j * 32 + lane;
                int mc = m < NTOK ? m : NTOK - 1;
                acc[j] = fmaf(qv, sk[mc][d], acc[j]);
            }
        }
        float sc[7], mx = -INFINITY;
#pragma unroll
        for (int j = 0; j < 7; j++) {
            int m = j * 32 + lane;
            sc[j] = (m < NTOK) ? acc[j] * 0.17677669529663687f : -INFINITY;
            mx = fmaxf(mx, sc[j]);
        }
#pragma unroll
        for (int off = 16; off > 0; off >>= 1)
            mx = fmaxf(mx, __shfl_xor_sync(0xffffffffu, mx, off));
        float sum = 0.f;
#pragma unroll
        for (int j = 0; j < 7; j++) {
            sc[j] = expf(sc[j] - mx);           // invalid lanes: exp(-inf)=0
            sum += sc[j];
        }
#pragma unroll
        for (int off = 16; off > 0; off >>= 1)
            sum += __shfl_xor_sync(0xffffffffu, sum, off);
        float inv = 1.f / sum;
        float* arow = g_attn + ((size_t)bh * NTOK + n) * NTOK;
#pragma unroll
        for (int j = 0; j < 7; j++) {
            int m = j * 32 + lane;
            if (m < NTOK) arow[m] = tf32r(sc[j] * inv);
        }
    }
}

// ---------------- 3) conv3x3 (V) fused with unfold -> vu (tf32-rounded) -----
__global__ __launch_bounds__(256) void convv_unfold_kernel(
        const float* __restrict__ x,
        const float* __restrict__ vw,
        const float* __restrict__ vb) {
    const int y = blockIdx.x;   // 224
    const int b = blockIdx.y;   // 4
    __shared__ __align__(16) float srow[CIN][3][226];
    __shared__ __align__(16) float sw[DIM][28];
    __shared__ float sb[DIM];
    const int t = threadIdx.x;
    {
#pragma unroll
        for (int j = 0; j < 27; j++) sw[t][j] = vw[t * 27 + j];
        sw[t][27] = 0.f;
        sb[t] = vb[t];
    }
    for (int i = t; i < CIN * 3 * 226; i += 256) {
        int ci = i / (3 * 226);
        int r  = (i / 226) % 3;
        int xx = i % 226;
        int yy = y + r - 1;
        int xc = xx - 1;
        float v = 0.f;
        if (yy >= 0 && yy < HW && xc >= 0 && xc < HW)
            v = x[(((size_t)b * CIN + ci) * HW + yy) * HW + xc];
        srow[ci][r][xx] = v;
    }
    __syncthreads();
    if (t >= HW) return;

    float xv[28];
#pragma unroll
    for (int ci = 0; ci < CIN; ci++)
#pragma unroll
        for (int r = 0; r < 3; r++)
#pragma unroll
            for (int dx = 0; dx < 3; dx++)
                xv[(ci * 3 + r) * 3 + dx] = srow[ci][r][t + dx];
    xv[27] = 0.f;

    const int hp = y >> 4, pi = y & 15;
    const int wp = t >> 4, pj = t & 15;
    const int n = hp * HP + wp;
    const size_t outbase = ((size_t)b * HEADS) * ((size_t)NTOK * DP)
                         + (size_t)n * DP + pi * PATCH + pj;
#pragma unroll 1
    for (int h = 0; h < HEADS; h++) {
        const size_t hbase = outbase + (size_t)h * ((size_t)NTOK * DP);
#pragma unroll 4
        for (int cr = 0; cr < 32; cr++) {
            const int c = h * 32 + cr;
            float acc = sb[c];
#pragma unroll
            for (int q = 0; q < 7; q++) {
                float4 w4 = *(const float4*)&sw[c][q * 4];
                acc = fmaf(xv[q * 4 + 0], w4.x, acc);
                acc = fmaf(xv[q * 4 + 1], w4.y, acc);
                acc = fmaf(xv[q * 4 + 2], w4.z, acc);
                acc = fmaf(xv[q * 4 + 3], w4.w, acc);
            }
            g_vu[hbase + (size_t)cr * 256] = tf32r(acc);
        }
    }
}

// ============ GEMM: mma.sync tf32, 256x128x16 tile, 512 thr, cp.async 4-stage
// 16 warps 4(m)x4(n), warp tile 64x32. A smem [256 m][20]; B smem [16 k][136].
#define STAGES    4
#define A_STAGE_F 5120      // 256*20 floats
#define B_STAGE_F 2176      // 16*136 floats
#define GEMM_SMEM ((STAGES * (A_STAGE_F + B_STAGE_F)) * 4)   // 116736 B

#define GEMM_COMPUTE(Ast_, Bst_)                                              \
    do {                                                                      \
        _Pragma("unroll")                                                     \
        for (int kb = 0; kb < 16; kb += 8) {                                  \
            uint32_t af[4][4], bf[4][2];                                      \
            _Pragma("unroll")                                                 \
            for (int mi = 0; mi < 4; mi++) {                                  \
                int m = wm * 64 + mi * 16 + fg;                               \
                af[mi][0] = __float_as_uint(Ast_[m * 20 + kb + ftg]);         \
                af[mi][1] = __float_as_uint(Ast_[(m + 8) * 20 + kb + ftg]);   \
                af[mi][2] = __float_as_uint(Ast_[m * 20 + kb + ftg + 4]);     \
                af[mi][3] = __float_as_uint(Ast_[(m + 8) * 20 + kb + ftg + 4]); \
            }                                                                 \
            _Pragma("unroll")                                                 \
            for (int ni = 0; ni < 4; ni++) {                                  \
                int n = wn * 32 + ni * 8 + fg;                                \
                bf[ni][0] = __float_as_uint(Bst_[(kb + ftg) * 136 + n]);      \
                bf[ni][1] = __float_as_uint(Bst_[(kb + ftg + 4) * 136 + n]);  \
            }                                                                 \
            _Pragma("unroll")                                                 \
            for (int mi = 0; mi < 4; mi++)                                    \
                _Pragma("unroll")                                             \
                for (int ni = 0; ni < 4; ni++)                                \
                    mma_tf32(acc[mi][ni], af[mi][0], af[mi][1], af[mi][2],    \
                             af[mi][3], bf[ni][0], bf[ni][1]);                \
        }                                                                     \
    } while (0)

// ---------------- 4) attn @ vu -> pre (NCHW fused fold) ---------------------
// per (b,h): C[256(196 used),8192] = A[196,196] @ B[196,8192]
__global__ __launch_bounds__(512) void gemm_attn_vu_tc() {
    extern __shared__ __align__(16) float dynsmem[];
    float* As = dynsmem;
    float* Bs = dynsmem + STAGES * A_STAGE_F;
    const uint32_t a_u32 = smem_u32(As);
    const uint32_t b_u32 = smem_u32(Bs);

    const int bh = blockIdx.y;
    const int b = bh >> 3, h = bh & 7;
    const float* __restrict__ A  = g_attn + (size_t)bh * NTOK * NTOK;
    const float* __restrict__ Bm = g_vu + (size_t)bh * NTOK * DP;
    const int col0 = blockIdx.x * 128;
    const int t = threadIdx.x;
    const int lane = t & 31, w = t >> 5;
    const int wm = w & 3, wn = w >> 2;
    const int fg = lane >> 2, ftg = lane & 3;
    const int am = t >> 1, akq = (t & 1) * 8;   // A loader: 256 rows x 16 k
    const int krow = t >> 5, n0 = lane * 4;     // B loader: 16 rows x 128 n
    float acc[4][4][4] = {};

#define AVU_ISSUE(st_, kt_)                                                   \
    do {                                                                      \
        int k0 = (kt_) * 16;                                                  \
        const float* asrc = A + (size_t)am * NTOK + k0 + akq;                 \
        bool pm = (am < NTOK);                                                \
        uint32_t ad = a_u32 + (st_) * (A_STAGE_F * 4) + am * 80 + akq * 4;    \
        cp16(ad,      asrc,     pm && (k0 + akq) < NTOK);                     \
        cp16(ad + 16, asrc + 4, pm && (k0 + akq + 4) < NTOK);                 \
        int gk = k0 + krow;                                                   \
        const float* bsrc = Bm + (size_t)gk * DP + col0 + n0;                 \
        uint32_t bd = b_u32 + (st_) * (B_STAGE_F * 4) + krow * 544 + n0 * 4;  \
        cp16(bd, bsrc, gk < NTOK);                                            \
    } while (0)

    const int NK = 13;   // ceil(196/16)
#pragma unroll
    for (int p = 0; p < STAGES - 1; p++) {
        AVU_ISSUE(p, p);
        CP_COMMIT();
    }
    CP_WAIT2();
    __syncthreads();
#pragma unroll 1
    for (int it = 0; it < NK; it++) {
        int pf = it + STAGES - 1;
        if (pf < NK) AVU_ISSUE(pf & 3, pf);
        CP_COMMIT();
        const float* Ast = As + (it & 3) * A_STAGE_F;
        const float* Bst = Bs + (it & 3) * B_STAGE_F;
        GEMM_COMPUTE(Ast, Bst);
        CP_WAIT2();
        __syncthreads();
    }
#undef AVU_ISSUE

    // epilogue: fold scatter into NCHW pre (float2 stores; tf32-rounded)
#pragma unroll
    for (int mi = 0; mi < 4; mi++) {
#pragma unroll
        for (int half = 0; half < 2; half++) {
            int m = wm * 64 + mi * 16 + fg + half * 8;
            if (m >= NTOK) continue;
            int hp = m / HP, wp = m % HP;
#pragma unroll
            for (int ni = 0; ni < 4; ni++) {
                int dp = col0 + wn * 32 + ni * 8 + ftg * 2;
                int cr = dp >> 8, rem = dp & 255;
                int pi = rem >> 4, pj = rem & 15;
                int c = h * 32 + cr;
                float2 v = make_float2(tf32r(acc[mi][ni][half * 2 + 0]),
                                       tf32r(acc[mi][ni][half * 2 + 1]));
                *(float2*)&g_pre[(((size_t)b * DIM + c) * HW + hp * PATCH + pi) * HW
                                 + wp * PATCH + pj] = v;
            }
        }
    }
}

// ---------------- 5) 1x1 proj via mma.sync tf32 ------------------------------
// per batch: C[256,50176] = g_pw[256,256] @ pre[256,50176] + bias
__global__ __launch_bounds__(512) void gemm_proj_tc(
        const float* __restrict__ pb,
        float* __restrict__ out) {
    extern __shared__ __align__(16) float dynsmem[];
    float* As = dynsmem;
    float* Bs = dynsmem + STAGES * A_STAGE_F;
    const uint32_t a_u32 = smem_u32(As);
    const uint32_t b_u32 = smem_u32(Bs);

    const int b = blockIdx.y;
    const float* __restrict__ Bm = g_pre + (size_t)b * DIM * PIX;
    float* __restrict__ C = out + (size_t)b * DIM * PIX;
    const int col0 = blockIdx.x * 128;
    const int t = threadIdx.x;
    const int lane = t & 31, w = t >> 5;
    const int wm = w & 3, wn = w >> 2;
    const int fg = lane >> 2, ftg = lane & 3;
    const int am = t >> 1, akq = (t & 1) * 8;
    const int krow = t >> 5, n0 = lane * 4;
    float acc[4][4][4] = {};

#define PROJ_ISSUE(st_, kt_)                                                  \
    do {                                                                      \
        int k0 = (kt_) * 16;                                                  \
        const float* asrc = g_pw + (size_t)am * DIM + k0 + akq;               \
        uint32_t ad = a_u32 + (st_) * (A_STAGE_F * 4) + am * 80 + akq * 4;    \
        cp16(ad,      asrc,     true);                                        \
        cp16(ad + 16, asrc + 4, true);                                        \
        const float* bsrc = Bm + (size_t)(k0 + krow) * PIX + col0 + n0;       \
        uint32_t bd = b_u32 + (st_) * (B_STAGE_F * 4) + krow * 544 + n0 * 4;  \
        cp16(bd, bsrc, true);                                                 \
    } while (0)

    const int NK = 16;   // 256/16
#pragma unroll
    for (int p = 0; p < STAGES - 1; p++) {
        PROJ_ISSUE(p, p);
        CP_COMMIT();
    }
    CP_WAIT2();
    __syncthreads();
#pragma unroll 1
    for (int it = 0; it < NK; it++) {
        int pf = it + STAGES - 1;
        if (pf < NK) PROJ_ISSUE(pf & 3, pf);
        CP_COMMIT();
        const float* Ast = As + (it & 3) * A_STAGE_F;
        const float* Bst = Bs + (it & 3) * B_STAGE_F;
        GEMM_COMPUTE(Ast, Bst);
        CP_WAIT2();
        __syncthreads();
    }
#undef PROJ_ISSUE

#pragma unroll
    for (int mi = 0; mi < 4; mi++) {
#pragma unroll
        for (int half = 0; half < 2; half++) {
            int co = wm * 64 + mi * 16 + fg + half * 8;
            float bias = pb[co];
            float* crow = &C[(size_t)co * PIX + col0 + wn * 32 + ftg * 2];
#pragma unroll
            for (int ni = 0; ni < 4; ni++) {
                float2 v = make_float2(acc[mi][ni][half * 2 + 0] + bias,
                                       acc[mi][ni][half * 2 + 1] + bias);
                *(float2*)&crow[ni * 8] = v;
            }
        }
    }
}

// ---------------- launch -----------------------------------------------------
extern "C" void kernel_launch(void* const* d_in, const int* in_sizes, int n_in,
                              void* d_out, int out_size) {
    const float* x       = (const float*)d_in[0];
    const float* patch_w = (const float*)d_in[1];
    const float* patch_b = (const float*)d_in[2];
    const float* qk_w    = (const float*)d_in[3];
    const float* v_w     = (const float*)d_in[4];
    const float* v_b     = (const float*)d_in[5];
    const float* proj_w  = (const float*)d_in[6];
    const float* proj_b  = (const float*)d_in[7];
    float* out = (float*)d_out;

    cudaFuncSetAttribute(gemm_attn_vu_tc,
                         cudaFuncAttributeMaxDynamicSharedMemorySize, GEMM_SMEM);
    cudaFuncSetAttribute(gemm_proj_tc,
                         cudaFuncAttributeMaxDynamicSharedMemorySize, GEMM_SMEM);

    patchqk16<<<BATCH * NTOK / 8, 256>>>(x, patch_w, patch_b, qk_w);
    softmax_v2<<<BATCH * HEADS, 256>>>();
    convv_unfold_kernel<<<dim3(HW, BATCH), 256>>>(x, v_w, v_b);
    gemm_attn_vu_tc<<<dim3(DP / 128, BATCH * HEADS), 512, GEMM_SMEM>>>();
    cvt_pw_kernel<<<DIM * DIM / 256, 256>>>(proj_w);
    gemm_proj_tc<<<dim3(PIX / 128, BATCH), 512, GEMM_SMEM>>>(proj_b, out);
}

// round 9
// speedup vs baseline: 6.9167x; 1.2638x over previous
#include <cuda_runtime.h>
#include <cuda_fp16.h>
#include <math.h>
#include <cstdint>

// Problem constants
#define BATCH 4
#define CIN   3
#define HW    224
#define PATCH 16
#define DIM   256
#define HEADS 8
#define HD    32
#define HP    14
#define NTOK  196
#define DP    8192
#define PIX   50176
#define AK    208          // padded k-stride for g_attn rows (halves)

// ---------------- scratch (device globals) ----------------------------------
__device__ __align__(16) float  g_q[BATCH * HEADS * NTOK * HD];
__device__ __align__(16) float  g_k[BATCH * HEADS * NTOK * HD];
__device__ __align__(16) __half g_attn[(size_t)BATCH * HEADS * NTOK * AK];          // [n][k] pad-208, pad zeroed
__device__ __align__(16) __half g_vu[(size_t)BATCH * HEADS * 98 * DP * 2];          // [m/2][d'][2] k-interleaved
__device__ __align__(16) __half g_pre[(size_t)BATCH * 128 * PIX * 2];               // [c/2][pix][2] k-interleaved
__device__ __align__(16) __half g_pw[DIM * DIM];                                    // [co][c]

__device__ __forceinline__ uint32_t smem_u32(const void* p) {
    uint32_t a;
    asm("{ .reg .u64 t; cvta.to.shared.u64 t, %1; cvt.u32.u64 %0, t; }" : "=r"(a) : "l"(p));
    return a;
}
__device__ __forceinline__ void mma_f16(float d[4],
        uint32_t a0, uint32_t a1, uint32_t a2, uint32_t a3,
        uint32_t b0, uint32_t b1) {
    asm volatile(
        "mma.sync.aligned.m16n8k16.row.col.f32.f16.f16.f32 "
        "{%0,%1,%2,%3}, {%4,%5,%6,%7}, {%8,%9}, {%0,%1,%2,%3};"
        : "+f"(d[0]), "+f"(d[1]), "+f"(d[2]), "+f"(d[3])
        : "r"(a0), "r"(a1), "r"(a2), "r"(a3), "r"(b0), "r"(b1));
}
__device__ __forceinline__ void cp16(uint32_t dst, const void* src, bool pred) {
    asm volatile("cp.async.cg.shared.global [%0], [%1], 16, %2;"
                 :: "r"(dst), "l"(src), "r"(pred ? 16 : 0) : "memory");
}
#define CP_COMMIT() asm volatile("cp.async.commit_group;" ::: "memory")
#define CP_WAIT3()  asm volatile("cp.async.wait_group 3;" ::: "memory")

// ---------------- 0) round proj_w to fp16 ------------------------------------
__global__ void cvt_pw_kernel(const float* __restrict__ pw) {
    int i = blockIdx.x * 256 + threadIdx.x;
    g_pw[i] = __float2half(pw[i]);
}

// ---------------- 1) fused patch embed + qk ----------------------------------
__global__ __launch_bounds__(256) void patchqk16(const float* __restrict__ x,
                                                 const float* __restrict__ w,
                                                 const float* __restrict__ bias,
                                                 const float* __restrict__ qkw) {
    const int bn0 = blockIdx.x * 8;
    __shared__ __align__(16) float sp[8][768];
    __shared__ __align__(16) float sx[8][256];
    for (int idx = threadIdx.x; idx < 8 * 768; idx += 256) {
        int i = idx / 768, j = idx - (idx / 768) * 768;
        int bn = bn0 + i;
        int b = bn / NTOK, n = bn % NTOK;
        int hp = n / HP, wp = n % HP;
        int ci = j >> 8, r = (j >> 4) & 15, cc = j & 15;
        sp[i][j] = x[(((size_t)b * CIN + ci) * HW + hp * PATCH + r) * HW + wp * PATCH + cc];
    }
    __syncthreads();
    const int co = threadIdx.x;
    {
        const float4* wr = (const float4*)(w + (size_t)co * 768);
        float acc[8] = {};
#pragma unroll 2
        for (int j4 = 0; j4 < 192; j4++) {
            float4 w4 = wr[j4];
#pragma unroll
            for (int i = 0; i < 8; i++) {
                float4 s4 = *(const float4*)&sp[i][j4 * 4];
                acc[i] = fmaf(s4.x, w4.x, fmaf(s4.y, w4.y, fmaf(s4.z, w4.z, fmaf(s4.w, w4.w, acc[i]))));
            }
        }
        float bco = bias[co];
#pragma unroll
        for (int i = 0; i < 8; i++) sx[i][co] = acc[i] + bco;
    }
    __syncthreads();
    {
        const float4* w0 = (const float4*)(qkw + (size_t)co * DIM);
        const float4* w1 = (const float4*)(qkw + (size_t)(DIM + co) * DIM);
        float acc0[8] = {}, acc1[8] = {};
#pragma unroll 2
        for (int j4 = 0; j4 < 64; j4++) {
            float4 a = w0[j4];
            float4 bq = w1[j4];
#pragma unroll
            for (int i = 0; i < 8; i++) {
                float4 s4 = *(const float4*)&sx[i][j4 * 4];
                acc0[i] = fmaf(s4.x, a.x,  fmaf(s4.y, a.y,  fmaf(s4.z, a.z,  fmaf(s4.w, a.w,  acc0[i]))));
                acc1[i] = fmaf(s4.x, bq.x, fmaf(s4.y, bq.y, fmaf(s4.z, bq.z, fmaf(s4.w, bq.w, acc1[i]))));
            }
        }
        const int h = co >> 5, d = co & 31;
#pragma unroll
        for (int i = 0; i < 8; i++) {
            int bn = bn0 + i;
            int b = bn / NTOK, n = bn % NTOK;
            size_t off = (((size_t)b * HEADS + h) * NTOK + n) * HD + d;
            g_q[off] = acc0[i];
            g_k[off] = acc1[i];
        }
    }
}

// ---------------- 2) scores + softmax -> attn (fp16, pad zeroed) -------------
__global__ __launch_bounds__(256) void softmax_v2() {
    const int bh = blockIdx.x;
    __shared__ float sk[NTOK][33];
    const float* kb = g_k + (size_t)bh * NTOK * HD;
    for (int i = threadIdx.x; i < NTOK * HD; i += 256)
        sk[i >> 5][i & 31] = kb[i];
    __syncthreads();
    const int wid = threadIdx.x >> 5, lane = threadIdx.x & 31;
    for (int n = wid; n < NTOK; n += 8) {
        float qd = g_q[((size_t)bh * NTOK + n) * HD + lane];
        float acc[7] = {};
#pragma unroll
        for (int d = 0; d < HD; d++) {
            float qv = __shfl_sync(0xffffffffu, qd, d);
#pragma unroll
            for (int j = 0; j < 7; j++) {
                int m = j * 32 + lane;
                int mc = m < NTOK ? m : NTOK - 1;
                acc[j] = fmaf(qv, sk[mc][d], acc[j]);
            }
        }
        float sc[7], mx = -INFINITY;
#pragma unroll
        for (int j = 0; j < 7; j++) {
            int m = j * 32 + lane;
            sc[j] = (m < NTOK) ? acc[j] * 0.17677669529663687f : -INFINITY;
            mx = fmaxf(mx, sc[j]);
        }
#pragma unroll
        for (int off = 16; off > 0; off >>= 1)
            mx = fmaxf(mx, __shfl_xor_sync(0xffffffffu, mx, off));
        float sum = 0.f;
#pragma unroll
        for (int j = 0; j < 7; j++) {
            sc[j] = expf(sc[j] - mx);
            sum += sc[j];
        }
#pragma unroll
        for (int off = 16; off > 0; off >>= 1)
            sum += __shfl_xor_sync(0xffffffffu, sum, off);
        float inv = 1.f / sum;
        __half* arow = g_attn + ((size_t)bh * NTOK + n) * AK;
#pragma unroll
        for (int j = 0; j < 7; j++) {
            int m = j * 32 + lane;
            if (m < NTOK)      arow[m] = __float2half(sc[j] * inv);
            else if (m < AK)   arow[m] = __float2half(0.f);
        }
    }
}

// ---------------- 3) conv3x3 (V) + unfold -> vu (fp16, k-pair interleaved) ---
__global__ __launch_bounds__(256) void convv_unfold_kernel(
        const float* __restrict__ x,
        const float* __restrict__ vw,
        const float* __restrict__ vb) {
    const int y = blockIdx.x;
    const int b = blockIdx.y;
    __shared__ __align__(16) float srow[CIN][3][226];
    __shared__ __align__(16) float sw[DIM][28];
    __shared__ float sb[DIM];
    const int t = threadIdx.x;
    {
#pragma unroll
        for (int j = 0; j < 27; j++) sw[t][j] = vw[t * 27 + j];
        sw[t][27] = 0.f;
        sb[t] = vb[t];
    }
    for (int i = t; i < CIN * 3 * 226; i += 256) {
        int ci = i / (3 * 226);
        int r  = (i / 226) % 3;
        int xx = i % 226;
        int yy = y + r - 1;
        int xc = xx - 1;
        float v = 0.f;
        if (yy >= 0 && yy < HW && xc >= 0 && xc < HW)
            v = x[(((size_t)b * CIN + ci) * HW + yy) * HW + xc];
        srow[ci][r][xx] = v;
    }
    __syncthreads();
    if (t >= HW) return;

    float xv[28];
#pragma unroll
    for (int ci = 0; ci < CIN; ci++)
#pragma unroll
        for (int r = 0; r < 3; r++)
#pragma unroll
            for (int dx = 0; dx < 3; dx++)
                xv[(ci * 3 + r) * 3 + dx] = srow[ci][r][t + dx];
    xv[27] = 0.f;

    const int hp = y >> 4, pi = y & 15;
    const int wp = t >> 4, pj = t & 15;
    const int n = hp * HP + wp;
    const int m2 = n >> 1, ms = n & 1;
#pragma unroll 1
    for (int h = 0; h < HEADS; h++) {
        const int bh = b * HEADS + h;
        size_t base = (((size_t)bh * 98 + m2) * DP + pi * PATCH + pj) * 2 + ms;
#pragma unroll 4
        for (int cr = 0; cr < 32; cr++) {
            const int c = h * 32 + cr;
            float acc = sb[c];
#pragma unroll
            for (int q = 0; q < 7; q++) {
                float4 w4 = *(const float4*)&sw[c][q * 4];
                acc = fmaf(xv[q * 4 + 0], w4.x, acc);
                acc = fmaf(xv[q * 4 + 1], w4.y, acc);
                acc = fmaf(xv[q * 4 + 2], w4.z, acc);
                acc = fmaf(xv[q * 4 + 3], w4.w, acc);
            }
            g_vu[base + (size_t)cr * 512] = __float2half(acc);
        }
    }
}

// ============ fp16 GEMM: m16n8k16, 256x128 tile, 512 thr, 5-stage cp.async ===
// A smem: [256 m][12 words] (8 data + 4 pad; words = 2 halves k-adjacent)
// B smem: [8 k2][136 words]  (word = k-pair at fixed n)
#define STAGES  5
#define A_ST_W  3072        // 256*12
#define B_ST_W  1088        // 8*136
#define GEMM_SMEM (STAGES * (A_ST_W + B_ST_W) * 4)   // 83200 B

#define GEMM_COMPUTE16(AsW_, BsW_)                                            \
    do {                                                                      \
        uint32_t af[4][4], bf[4][2];                                          \
        _Pragma("unroll")                                                     \
        for (int mi = 0; mi < 4; mi++) {                                      \
            int m = wm * 64 + mi * 16 + fg;                                   \
            af[mi][0] = AsW_[m * 12 + ftg];                                   \
            af[mi][1] = AsW_[(m + 8) * 12 + ftg];                             \
            af[mi][2] = AsW_[m * 12 + ftg + 4];                               \
            af[mi][3] = AsW_[(m + 8) * 12 + ftg + 4];                         \
        }                                                                     \
        _Pragma("unroll")                                                     \
        for (int ni = 0; ni < 4; ni++) {                                      \
            int n = wn * 32 + ni * 8 + fg;                                    \
            bf[ni][0] = BsW_[ftg * 136 + n];                                  \
            bf[ni][1] = BsW_[(ftg + 4) * 136 + n];                            \
        }                                                                     \
        _Pragma("unroll")                                                     \
        for (int mi = 0; mi < 4; mi++)                                        \
            _Pragma("unroll")                                                 \
            for (int ni = 0; ni < 4; ni++)                                    \
                mma_f16(acc[mi][ni], af[mi][0], af[mi][1], af[mi][2],         \
                        af[mi][3], bf[ni][0], bf[ni][1]);                     \
    } while (0)

// ---------------- 4) attn @ vu -> pre ----------------------------------------
__global__ __launch_bounds__(512) void gemm_attn_vu_f16() {
    extern __shared__ __align__(16) uint32_t dynw[];
    uint32_t* AsW = dynw;
    uint32_t* BsW = dynw + STAGES * A_ST_W;
    const uint32_t a_u32 = smem_u32(AsW);
    const uint32_t b_u32 = smem_u32(BsW);

    const int bh = blockIdx.y;
    const int b = bh >> 3, h = bh & 7;
    const __half* __restrict__ Ah = g_attn + (size_t)bh * NTOK * AK;
    const uint32_t* __restrict__ BmW = (const uint32_t*)g_vu + (size_t)bh * 98 * DP;
    const int col0 = blockIdx.x * 128;
    const int t = threadIdx.x;
    const int lane = t & 31, w = t >> 5;
    const int wm = w & 3, wn = w >> 2;
    const int fg = lane >> 2, ftg = lane & 3;
    const int arow = t >> 1, a16 = t & 1;       // A loader
    const int k2r = t >> 5, nw = lane * 4;      // B loader (t<256)
    float acc[4][4][4] = {};

#define AVU_ISSUE(st_, kt_)                                                   \
    do {                                                                      \
        uint32_t ad = a_u32 + ((st_) * A_ST_W + arow * 12 + a16 * 4) * 4;     \
        const char* asrc = (const char*)Ah + arow * (AK * 2) + (kt_) * 32 + a16 * 16; \
        cp16(ad, asrc, arow < NTOK);                                          \
        if (t < 256) {                                                        \
            int k2 = (kt_) * 8 + k2r;                                         \
            uint32_t bd = b_u32 + ((st_) * B_ST_W + k2r * 136 + nw) * 4;      \
            cp16(bd, BmW + (size_t)k2 * DP + col0 + nw, k2 < 98);             \
        }                                                                     \
    } while (0)

    const int NK = 13;
#pragma unroll
    for (int p = 0; p < STAGES - 1; p++) { AVU_ISSUE(p, p); CP_COMMIT(); }
    CP_WAIT3();
    __syncthreads();
#pragma unroll 1
    for (int it = 0; it < NK; it++) {
        int pf = it + STAGES - 1;
        if (pf < NK) { int st = pf % STAGES; AVU_ISSUE(st, pf); }
        CP_COMMIT();
        const uint32_t* Ast = AsW + (it % STAGES) * A_ST_W;
        const uint32_t* Bst = BsW + (it % STAGES) * B_ST_W;
        GEMM_COMPUTE16(Ast, Bst);
        CP_WAIT3();
        __syncthreads();
    }
#undef AVU_ISSUE

    // epilogue: fold-scatter into k-interleaved fp16 pre
#pragma unroll
    for (int mi = 0; mi < 4; mi++) {
#pragma unroll
        for (int half = 0; half < 2; half++) {
            int m = wm * 64 + mi * 16 + fg + half * 8;
            if (m >= NTOK) continue;
            int hp = m / HP, wp = m % HP;
#pragma unroll
            for (int ni = 0; ni < 4; ni++) {
                int dp = col0 + wn * 32 + ni * 8 + ftg * 2;
                int cr = dp >> 8, rem = dp & 255;
                int pi = rem >> 4, pj = rem & 15;
                int c = h * 32 + cr;
                int pix = (hp * PATCH + pi) * HW + wp * PATCH + pj;
                size_t o = (((size_t)b * 128 + (c >> 1)) * PIX + pix) * 2 + (c & 1);
                g_pre[o]     = __float2half(acc[mi][ni][half * 2 + 0]);
                g_pre[o + 2] = __float2half(acc[mi][ni][half * 2 + 1]);
            }
        }
    }
}

// ---------------- 5) 1x1 proj -------------------------------------------------
__global__ __launch_bounds__(512) void gemm_proj_f16(
        const float* __restrict__ pb,
        float* __restrict__ out) {
    extern __shared__ __align__(16) uint32_t dynw[];
    uint32_t* AsW = dynw;
    uint32_t* BsW = dynw + STAGES * A_ST_W;
    const uint32_t a_u32 = smem_u32(AsW);
    const uint32_t b_u32 = smem_u32(BsW);

    const int b = blockIdx.y;
    const uint32_t* __restrict__ BmW = (const uint32_t*)g_pre + (size_t)b * 128 * PIX;
    float* __restrict__ C = out + (size_t)b * DIM * PIX;
    const int col0 = blockIdx.x * 128;
    const int t = threadIdx.x;
    const int lane = t & 31, w = t >> 5;
    const int wm = w & 3, wn = w >> 2;
    const int fg = lane >> 2, ftg = lane & 3;
    const int arow = t >> 1, a16 = t & 1;
    const int k2r = t >> 5, nw = lane * 4;
    float acc[4][4][4] = {};

#define PROJ_ISSUE(st_, kt_)                                                  \
    do {                                                                      \
        uint32_t ad = a_u32 + ((st_) * A_ST_W + arow * 12 + a16 * 4) * 4;     \
        const char* asrc = (const char*)g_pw + arow * (DIM * 2) + (kt_) * 32 + a16 * 16; \
        cp16(ad, asrc, true);                                                 \
        if (t < 256) {                                                        \
            int k2 = (kt_) * 8 + k2r;                                         \
            uint32_t bd = b_u32 + ((st_) * B_ST_W + k2r * 136 + nw) * 4;      \
            cp16(bd, BmW + (size_t)k2 * PIX + col0 + nw, true);               \
        }                                                                     \
    } while (0)

    const int NK = 16;
#pragma unroll
    for (int p = 0; p < STAGES - 1; p++) { PROJ_ISSUE(p, p); CP_COMMIT(); }
    CP_WAIT3();
    __syncthreads();
#pragma unroll 1
    for (int it = 0; it < NK; it++) {
        int pf = it + STAGES - 1;
        if (pf < NK) { int st = pf % STAGES; PROJ_ISSUE(st, pf); }
        CP_COMMIT();
        const uint32_t* Ast = AsW + (it % STAGES) * A_ST_W;
        const uint32_t* Bst = BsW + (it % STAGES) * B_ST_W;
        GEMM_COMPUTE16(Ast, Bst);
        CP_WAIT3();
        __syncthreads();
    }
#undef PROJ_ISSUE

#pragma unroll
    for (int mi = 0; mi < 4; mi++) {
#pragma unroll
        for (int half = 0; half < 2; half++) {
            int co = wm * 64 + mi * 16 + fg + half * 8;
            float bias = pb[co];
            float* crow = &C[(size_t)co * PIX + col0 + wn * 32 + ftg * 2];
#pragma unroll
            for (int ni = 0; ni < 4; ni++) {
                float2 v = make_float2(acc[mi][ni][half * 2 + 0] + bias,
                                       acc[mi][ni][half * 2 + 1] + bias);
                *(float2*)&crow[ni * 8] = v;
            }
        }
    }
}

// ---------------- launch -----------------------------------------------------
extern "C" void kernel_launch(void* const* d_in, const int* in_sizes, int n_in,
                              void* d_out, int out_size) {
    const float* x       = (const float*)d_in[0];
    const float* patch_w = (const float*)d_in[1];
    const float* patch_b = (const float*)d_in[2];
    const float* qk_w    = (const float*)d_in[3];
    const float* v_w     = (const float*)d_in[4];
    const float* v_b     = (const float*)d_in[5];
    const float* proj_w  = (const float*)d_in[6];
    const float* proj_b  = (const float*)d_in[7];
    float* out = (float*)d_out;

    cudaFuncSetAttribute(gemm_attn_vu_f16,
                         cudaFuncAttributeMaxDynamicSharedMemorySize, GEMM_SMEM);
    cudaFuncSetAttribute(gemm_proj_f16,
                         cudaFuncAttributeMaxDynamicSharedMemorySize, GEMM_SMEM);

    patchqk16<<<BATCH * NTOK / 8, 256>>>(x, patch_w, patch_b, qk_w);
    softmax_v2<<<BATCH * HEADS, 256>>>();
    convv_unfold_kernel<<<dim3(HW, BATCH), 256>>>(x, v_w, v_b);
    gemm_attn_vu_f16<<<dim3(DP / 128, BATCH * HEADS), 512, GEMM_SMEM>>>();
    cvt_pw_kernel<<<DIM * DIM / 256, 256>>>(proj_w);
    gemm_proj_f16<<<dim3(PIX / 128, BATCH), 512, GEMM_SMEM>>>(proj_b, out);
}

// round 10
// speedup vs baseline: 7.6135x; 1.1007x over previous
#include <cuda_runtime.h>
#include <cuda_fp16.h>
#include <math.h>
#include <cstdint>

// Problem constants
#define BATCH 4
#define CIN   3
#define HW    224
#define PATCH 16
#define DIM   256
#define HEADS 8
#define HD    32
#define HP    14
#define NTOK  196
#define DP    8192
#define PIX   50176
#define AK    208          // padded k-stride for g_attn rows (halves), zero-filled

// ---------------- scratch (device globals) ----------------------------------
__device__ __align__(16) float  g_q[BATCH * HEADS * NTOK * HD];
__device__ __align__(16) float  g_k[BATCH * HEADS * NTOK * HD];
__device__ __align__(16) __half g_attn[(size_t)BATCH * HEADS * NTOK * AK];   // [n][k]
__device__ __align__(16) __half g_vu[(size_t)BATCH * HEADS * NTOK * DP];     // [m][d']
__device__ __align__(16) __half g_pre[(size_t)BATCH * DIM * PIX];            // [c][pix]
__device__ __align__(16) __half g_pw[DIM * DIM];                             // [co][c]

__device__ __forceinline__ uint32_t smem_u32(const void* p) {
    uint32_t a;
    asm("{ .reg .u64 t; cvta.to.shared.u64 t, %1; cvt.u32.u64 %0, t; }" : "=r"(a) : "l"(p));
    return a;
}
__device__ __forceinline__ void mma_f16(float d[4],
        uint32_t a0, uint32_t a1, uint32_t a2, uint32_t a3,
        uint32_t b0, uint32_t b1) {
    asm volatile(
        "mma.sync.aligned.m16n8k16.row.col.f32.f16.f16.f32 "
        "{%0,%1,%2,%3}, {%4,%5,%6,%7}, {%8,%9}, {%0,%1,%2,%3};"
        : "+f"(d[0]), "+f"(d[1]), "+f"(d[2]), "+f"(d[3])
        : "r"(a0), "r"(a1), "r"(a2), "r"(a3), "r"(b0), "r"(b1));
}
__device__ __forceinline__ void ldsm_x4(uint32_t& r0, uint32_t& r1,
                                        uint32_t& r2, uint32_t& r3, uint32_t addr) {
    asm volatile("ldmatrix.sync.aligned.m8n8.x4.shared.b16 {%0,%1,%2,%3}, [%4];"
                 : "=r"(r0), "=r"(r1), "=r"(r2), "=r"(r3) : "r"(addr));
}
__device__ __forceinline__ void ldsm_x4_t(uint32_t& r0, uint32_t& r1,
                                          uint32_t& r2, uint32_t& r3, uint32_t addr) {
    asm volatile("ldmatrix.sync.aligned.m8n8.x4.trans.shared.b16 {%0,%1,%2,%3}, [%4];"
                 : "=r"(r0), "=r"(r1), "=r"(r2), "=r"(r3) : "r"(addr));
}
__device__ __forceinline__ void cp16(uint32_t dst, const void* src, bool pred) {
    asm volatile("cp.async.cg.shared.global [%0], [%1], 16, %2;"
                 :: "r"(dst), "l"(src), "r"(pred ? 16 : 0) : "memory");
}
#define CP_COMMIT() asm volatile("cp.async.commit_group;" ::: "memory")
#define CP_WAIT3()  asm volatile("cp.async.wait_group 3;" ::: "memory")

// ---------------- 0) round proj_w to fp16 ------------------------------------
__global__ void cvt_pw_kernel(const float* __restrict__ pw) {
    int i = blockIdx.x * 256 + threadIdx.x;
    g_pw[i] = __float2half(pw[i]);
}

// ---------------- 1) fused patch embed + qk ----------------------------------
__global__ __launch_bounds__(256) void patchqk16(const float* __restrict__ x,
                                                 const float* __restrict__ w,
                                                 const float* __restrict__ bias,
                                                 const float* __restrict__ qkw) {
    const int bn0 = blockIdx.x * 8;
    __shared__ __align__(16) float sp[8][768];
    __shared__ __align__(16) float sx[8][256];
    for (int idx = threadIdx.x; idx < 8 * 768; idx += 256) {
        int i = idx / 768, j = idx - (idx / 768) * 768;
        int bn = bn0 + i;
        int b = bn / NTOK, n = bn % NTOK;
        int hp = n / HP, wp = n % HP;
        int ci = j >> 8, r = (j >> 4) & 15, cc = j & 15;
        sp[i][j] = x[(((size_t)b * CIN + ci) * HW + hp * PATCH + r) * HW + wp * PATCH + cc];
    }
    __syncthreads();
    const int co = threadIdx.x;
    {
        const float4* wr = (const float4*)(w + (size_t)co * 768);
        float acc[8] = {};
#pragma unroll 2
        for (int j4 = 0; j4 < 192; j4++) {
            float4 w4 = wr[j4];
#pragma unroll
            for (int i = 0; i < 8; i++) {
                float4 s4 = *(const float4*)&sp[i][j4 * 4];
                acc[i] = fmaf(s4.x, w4.x, fmaf(s4.y, w4.y, fmaf(s4.z, w4.z, fmaf(s4.w, w4.w, acc[i]))));
            }
        }
        float bco = bias[co];
#pragma unroll
        for (int i = 0; i < 8; i++) sx[i][co] = acc[i] + bco;
    }
    __syncthreads();
    {
        const float4* w0 = (const float4*)(qkw + (size_t)co * DIM);
        const float4* w1 = (const float4*)(qkw + (size_t)(DIM + co) * DIM);
        float acc0[8] = {}, acc1[8] = {};
#pragma unroll 2
        for (int j4 = 0; j4 < 64; j4++) {
            float4 a = w0[j4];
            float4 bq = w1[j4];
#pragma unroll
            for (int i = 0; i < 8; i++) {
                float4 s4 = *(const float4*)&sx[i][j4 * 4];
                acc0[i] = fmaf(s4.x, a.x,  fmaf(s4.y, a.y,  fmaf(s4.z, a.z,  fmaf(s4.w, a.w,  acc0[i]))));
                acc1[i] = fmaf(s4.x, bq.x, fmaf(s4.y, bq.y, fmaf(s4.z, bq.z, fmaf(s4.w, bq.w, acc1[i]))));
            }
        }
        const int h = co >> 5, d = co & 31;
#pragma unroll
        for (int i = 0; i < 8; i++) {
            int bn = bn0 + i;
            int b = bn / NTOK, n = bn % NTOK;
            size_t off = (((size_t)b * HEADS + h) * NTOK + n) * HD + d;
            g_q[off] = acc0[i];
            g_k[off] = acc1[i];
        }
    }
}

// ---------------- 2) scores + softmax -> attn (fp16, pad zeroed) -------------
__global__ __launch_bounds__(256) void softmax_v2() {
    const int bh = blockIdx.x;
    __shared__ float sk[NTOK][33];
    const float* kb = g_k + (size_t)bh * NTOK * HD;
    for (int i = threadIdx.x; i < NTOK * HD; i += 256)
        sk[i >> 5][i & 31] = kb[i];
    __syncthreads();
    const int wid = threadIdx.x >> 5, lane = threadIdx.x & 31;
    for (int n = wid; n < NTOK; n += 8) {
        float qd = g_q[((size_t)bh * NTOK + n) * HD + lane];
        float acc[7] = {};
#pragma unroll
        for (int d = 0; d < HD; d++) {
            float qv = __shfl_sync(0xffffffffu, qd, d);
#pragma unroll
            for (int j = 0; j < 7; j++) {
                int m = j * 32 + lane;
                int mc = m < NTOK ? m : NTOK - 1;
                acc[j] = fmaf(qv, sk[mc][d], acc[j]);
            }
        }
        float sc[7], mx = -INFINITY;
#pragma unroll
        for (int j = 0; j < 7; j++) {
            int m = j * 32 + lane;
            sc[j] = (m < NTOK) ? acc[j] * 0.17677669529663687f : -INFINITY;
            mx = fmaxf(mx, sc[j]);
        }
#pragma unroll
        for (int off = 16; off > 0; off >>= 1)
            mx = fmaxf(mx, __shfl_xor_sync(0xffffffffu, mx, off));
        float sum = 0.f;
#pragma unroll
        for (int j = 0; j < 7; j++) {
            sc[j] = expf(sc[j] - mx);
            sum += sc[j];
        }
#pragma unroll
        for (int off = 16; off > 0; off >>= 1)
            sum += __shfl_xor_sync(0xffffffffu, sum, off);
        float inv = 1.f / sum;
        __half* arow = g_attn + ((size_t)bh * NTOK + n) * AK;
#pragma unroll
        for (int j = 0; j < 7; j++) {
            int m = j * 32 + lane;
            if (m < NTOK)      arow[m] = __float2half(sc[j] * inv);
            else if (m < AK)   arow[m] = __float2half(0.f);
        }
    }
}

// ---------------- 3) conv3x3 (V) + unfold -> vu (fp16, [m][d']) --------------
__global__ __launch_bounds__(256) void convv_unfold_kernel(
        const float* __restrict__ x,
        const float* __restrict__ vw,
        const float* __restrict__ vb) {
    const int y = blockIdx.x;
    const int b = blockIdx.y;
    __shared__ __align__(16) float srow[CIN][3][226];
    __shared__ __align__(16) float sw[DIM][28];
    __shared__ float sb[DIM];
    const int t = threadIdx.x;
    {
#pragma unroll
        for (int j = 0; j < 27; j++) sw[t][j] = vw[t * 27 + j];
        sw[t][27] = 0.f;
        sb[t] = vb[t];
    }
    for (int i = t; i < CIN * 3 * 226; i += 256) {
        int ci = i / (3 * 226);
        int r  = (i / 226) % 3;
        int xx = i % 226;
        int yy = y + r - 1;
        int xc = xx - 1;
        float v = 0.f;
        if (yy >= 0 && yy < HW && xc >= 0 && xc < HW)
            v = x[(((size_t)b * CIN + ci) * HW + yy) * HW + xc];
        srow[ci][r][xx] = v;
    }
    __syncthreads();
    if (t >= HW) return;

    float xv[28];
#pragma unroll
    for (int ci = 0; ci < CIN; ci++)
#pragma unroll
        for (int r = 0; r < 3; r++)
#pragma unroll
            for (int dx = 0; dx < 3; dx++)
                xv[(ci * 3 + r) * 3 + dx] = srow[ci][r][t + dx];
    xv[27] = 0.f;

    const int hp = y >> 4, pi = y & 15;
    const int wp = t >> 4, pj = t & 15;
    const int n = hp * HP + wp;
#pragma unroll 1
    for (int h = 0; h < HEADS; h++) {
        const int bh = b * HEADS + h;
        size_t base = ((size_t)bh * NTOK + n) * DP + pi * PATCH + pj;
#pragma unroll 4
        for (int cr = 0; cr < 32; cr++) {
            const int c = h * 32 + cr;
            float acc = sb[c];
#pragma unroll
            for (int q = 0; q < 7; q++) {
                float4 w4 = *(const float4*)&sw[c][q * 4];
                acc = fmaf(xv[q * 4 + 0], w4.x, acc);
                acc = fmaf(xv[q * 4 + 1], w4.y, acc);
                acc = fmaf(xv[q * 4 + 2], w4.z, acc);
                acc = fmaf(xv[q * 4 + 3], w4.w, acc);
            }
            g_vu[base + (size_t)cr * 256] = __float2half(acc);
        }
    }
}

// ======== fp16 GEMM: m16n8k16, 256x128 tile, 512 thr, 5-stage, ldmatrix ======
// A smem: [256 m][12 words] = halves k0..k15 in words 0..7, pad 4 words.
// B smem: [16 k][68 words]  = halves n0..n127 in words 0..63, pad 4 words.
#define STAGES  5
#define A_ST_W  3072        // 256*12
#define B_ST_W  1088        // 16*68
#define GEMM_SMEM (STAGES * (A_ST_W + B_ST_W) * 4)   // 83200 B

#define GEMM_COMPUTE16(a_st_, b_st_)                                          \
    do {                                                                      \
        uint32_t af[4][4], bf[4][2];                                          \
        _Pragma("unroll")                                                     \
        for (int mi = 0; mi < 4; mi++) {                                      \
            uint32_t ad = (a_st_) + (((wm * 64 + mi * 16) * 12 + a_lane) << 2); \
            ldsm_x4(af[mi][0], af[mi][1], af[mi][2], af[mi][3], ad);          \
        }                                                                     \
        {                                                                     \
            uint32_t bd0 = (b_st_) + ((b_lane + wn * 16) << 2);               \
            ldsm_x4_t(bf[0][0], bf[0][1], bf[1][0], bf[1][1], bd0);           \
            ldsm_x4_t(bf[2][0], bf[2][1], bf[3][0], bf[3][1], bd0 + 32);      \
        }                                                                     \
        _Pragma("unroll")                                                     \
        for (int mi = 0; mi < 4; mi++)                                        \
            _Pragma("unroll")                                                 \
            for (int ni = 0; ni < 4; ni++)                                    \
                mma_f16(acc[mi][ni], af[mi][0], af[mi][1], af[mi][2],         \
                        af[mi][3], bf[ni][0], bf[ni][1]);                     \
    } while (0)

// lane offsets (words):
//  A (non-trans x4): matrices (m0..7,k0-7),(m8..15,k0-7),(m0..7,k8-15),(m8..15,k8-15)
//   a_lane = ((lane&7) + ((lane>>3)&1)*8)*12 + ((lane>>4)&1)*4
//  B (trans x4):     matrices (k0-7,n0-7),(k8-15,n0-7),(k0-7,n8-15),(k8-15,n8-15)
//   b_lane = ((lane&7) + ((lane>>3)&1)*8)*68 + ((lane>>4)&1)*4

// ---------------- 4) attn @ vu -> pre ----------------------------------------
__global__ __launch_bounds__(512) void gemm_attn_vu_f16() {
    extern __shared__ __align__(16) uint32_t dynw[];
    const uint32_t a_u32 = smem_u32(dynw);
    const uint32_t b_u32 = a_u32 + STAGES * A_ST_W * 4;

    const int bh = blockIdx.y;
    const int b = bh >> 3, h = bh & 7;
    const __half* __restrict__ Ah = g_attn + (size_t)bh * NTOK * AK;
    const __half* __restrict__ Bh = g_vu + (size_t)bh * NTOK * DP;
    const int col0 = blockIdx.x * 128;
    const int t = threadIdx.x;
    const int lane = t & 31, w = t >> 5;
    const int wm = w & 3, wn = w >> 2;
    const int fg = lane >> 2, ftg = lane & 3;
    const int a_lane = ((lane & 7) + ((lane >> 3) & 1) * 8) * 12 + ((lane >> 4) & 1) * 4;
    const int b_lane = ((lane & 7) + ((lane >> 3) & 1) * 8) * 68 + ((lane >> 4) & 1) * 4;
    const int arow = t >> 1, a16 = t & 1;         // A loader: 256 rows x 2 chunks
    const int bkr = t >> 4, bnc = t & 15;         // B loader (t<256): 16 rows x 16 chunks
    float acc[4][4][4] = {};

#define AVU_ISSUE(st_, kt_)                                                   \
    do {                                                                      \
        uint32_t ad = a_u32 + ((st_) * A_ST_W + arow * 12 + a16 * 4) * 4;     \
        const char* asrc = (const char*)Ah + arow * (AK * 2) + (kt_) * 32 + a16 * 16; \
        cp16(ad, asrc, arow < NTOK);                                          \
        if (t < 256) {                                                        \
            int gk = (kt_) * 16 + bkr;                                        \
            uint32_t bd = b_u32 + ((st_) * B_ST_W + bkr * 68 + bnc * 4) * 4;  \
            cp16(bd, Bh + (size_t)gk * DP + col0 + bnc * 8, gk < NTOK);       \
        }                                                                     \
    } while (0)

    const int NK = 13;
#pragma unroll
    for (int p = 0; p < STAGES - 1; p++) { AVU_ISSUE(p, p); CP_COMMIT(); }
    CP_WAIT3();
    __syncthreads();
#pragma unroll 1
    for (int it = 0; it < NK; it++) {
        int pf = it + STAGES - 1;
        if (pf < NK) { int st = pf % STAGES; AVU_ISSUE(st, pf); }
        CP_COMMIT();
        uint32_t a_st = a_u32 + (it % STAGES) * A_ST_W * 4;
        uint32_t b_st = b_u32 + (it % STAGES) * B_ST_W * 4;
        GEMM_COMPUTE16(a_st, b_st);
        CP_WAIT3();
        __syncthreads();
    }
#undef AVU_ISSUE

    // epilogue: fold-scatter into fp16 NCHW pre (__half2 per dp-pair)
#pragma unroll
    for (int mi = 0; mi < 4; mi++) {
#pragma unroll
        for (int half = 0; half < 2; half++) {
            int m = wm * 64 + mi * 16 + fg + half * 8;
            if (m >= NTOK) continue;
            int hp = m / HP, wp = m % HP;
#pragma unroll
            for (int ni = 0; ni < 4; ni++) {
                int dp = col0 + wn * 32 + ni * 8 + ftg * 2;
                int cr = dp >> 8, rem = dp & 255;
                int pi = rem >> 4, pj = rem & 15;
                int c = h * 32 + cr;
                int pix = (hp * PATCH + pi) * HW + wp * PATCH + pj;
                __half2 v = __floats2half2_rn(acc[mi][ni][half * 2 + 0],
                                              acc[mi][ni][half * 2 + 1]);
                *(__half2*)&g_pre[((size_t)b * DIM + c) * PIX + pix] = v;
            }
        }
    }
}

// ---------------- 5) 1x1 proj -------------------------------------------------
__global__ __launch_bounds__(512) void gemm_proj_f16(
        const float* __restrict__ pb,
        float* __restrict__ out) {
    extern __shared__ __align__(16) uint32_t dynw[];
    const uint32_t a_u32 = smem_u32(dynw);
    const uint32_t b_u32 = a_u32 + STAGES * A_ST_W * 4;

    const int b = blockIdx.y;
    const __half* __restrict__ Bh = g_pre + (size_t)b * DIM * PIX;
    float* __restrict__ C = out + (size_t)b * DIM * PIX;
    const int col0 = blockIdx.x * 128;
    const int t = threadIdx.x;
    const int lane = t & 31, w = t >> 5;
    const int wm = w & 3, wn = w >> 2;
    const int fg = lane >> 2, ftg = lane & 3;
    const int a_lane = ((lane & 7) + ((lane >> 3) & 1) * 8) * 12 + ((lane >> 4) & 1) * 4;
    const int b_lane = ((lane & 7) + ((lane >> 3) & 1) * 8) * 68 + ((lane >> 4) & 1) * 4;
    const int arow = t >> 1, a16 = t & 1;
    const int bkr = t >> 4, bnc = t & 15;
    float acc[4][4][4] = {};

#define PROJ_ISSUE(st_, kt_)                                                  \
    do {                                                                      \
        uint32_t ad = a_u32 + ((st_) * A_ST_W + arow * 12 + a16 * 4) * 4;     \
        const char* asrc = (const char*)g_pw + arow * (DIM * 2) + (kt_) * 32 + a16 * 16; \
        cp16(ad, asrc, true);                                                 \
        if (t < 256) {                                                        \
            int gk = (kt_) * 16 + bkr;                                        \
            uint32_t bd = b_u32 + ((st_) * B_ST_W + bkr * 68 + bnc * 4) * 4;  \
            cp16(bd, Bh + (size_t)gk * PIX + col0 + bnc * 8, true);           \
        }                                                                     \
    } while (0)

    const int NK = 16;
#pragma unroll
    for (int p = 0; p < STAGES - 1; p++) { PROJ_ISSUE(p, p); CP_COMMIT(); }
    CP_WAIT3();
    __syncthreads();
#pragma unroll 1
    for (int it = 0; it < NK; it++) {
        int pf = it + STAGES - 1;
        if (pf < NK) { int st = pf % STAGES; PROJ_ISSUE(st, pf); }
        CP_COMMIT();
        uint32_t a_st = a_u32 + (it % STAGES) * A_ST_W * 4;
        uint32_t b_st = b_u32 + (it % STAGES) * B_ST_W * 4;
        GEMM_COMPUTE16(a_st, b_st);
        CP_WAIT3();
        __syncthreads();
    }
#undef PROJ_ISSUE

#pragma unroll
    for (int mi = 0; mi < 4; mi++) {
#pragma unroll
        for (int half = 0; half < 2; half++) {
            int co = wm * 64 + mi * 16 + fg + half * 8;
            float bias = pb[co];
            float* crow = &C[(size_t)co * PIX + col0 + wn * 32 + ftg * 2];
#pragma unroll
            for (int ni = 0; ni < 4; ni++) {
                float2 v = make_float2(acc[mi][ni][half * 2 + 0] + bias,
                                       acc[mi][ni][half * 2 + 1] + bias);
                *(float2*)&crow[ni * 8] = v;
            }
        }
    }
}

// ---------------- launch -----------------------------------------------------
extern "C" void kernel_launch(void* const* d_in, const int* in_sizes, int n_in,
                              void* d_out, int out_size) {
    const float* x       = (const float*)d_in[0];
    const float* patch_w = (const float*)d_in[1];
    const float* patch_b = (const float*)d_in[2];
    const float* qk_w    = (const float*)d_in[3];
    const float* v_w     = (const float*)d_in[4];
    const float* v_b     = (const float*)d_in[5];
    const float* proj_w  = (const float*)d_in[6];
    const float* proj_b  = (const float*)d_in[7];
    float* out = (float*)d_out;

    cudaFuncSetAttribute(gemm_attn_vu_f16,
                         cudaFuncAttributeMaxDynamicSharedMemorySize, GEMM_SMEM);
    cudaFuncSetAttribute(gemm_proj_f16,
                         cudaFuncAttributeMaxDynamicSharedMemorySize, GEMM_SMEM);

    patchqk16<<<BATCH * NTOK / 8, 256>>>(x, patch_w, patch_b, qk_w);
    softmax_v2<<<BATCH * HEADS, 256>>>();
    convv_unfold_kernel<<<dim3(HW, BATCH), 256>>>(x, v_w, v_b);
    gemm_attn_vu_f16<<<dim3(DP / 128, BATCH * HEADS), 512, GEMM_SMEM>>>();
    cvt_pw_kernel<<<DIM * DIM / 256, 256>>>(proj_w);
    gemm_proj_f16<<<dim3(PIX / 128, BATCH), 512, GEMM_SMEM>>>(proj_b, out);
}

// round 11
// speedup vs baseline: 7.7884x; 1.0230x over previous
#include <cuda_runtime.h>
#include <cuda_fp16.h>
#include <math.h>
#include <cstdint>

// Problem constants
#define BATCH 4
#define CIN   3
#define HW    224
#define PATCH 16
#define DIM   256
#define HEADS 8
#define HD    32
#define HP    14
#define NTOK  196
#define DP    8192
#define PIX   50176
#define AK    208          // padded k-stride for g_attn rows (halves), zero-filled

// ---------------- scratch (device globals) ----------------------------------
__device__ __align__(16) float  g_q[BATCH * HEADS * NTOK * HD];
__device__ __align__(16) float  g_k[BATCH * HEADS * NTOK * HD];
__device__ __align__(16) __half g_attn[(size_t)BATCH * HEADS * NTOK * AK];   // [n][k]
__device__ __align__(16) __half g_vu[(size_t)BATCH * HEADS * NTOK * DP];     // [m][d']
__device__ __align__(16) __half g_pre[(size_t)BATCH * DIM * PIX];            // [c][pix]
__device__ __align__(16) __half g_pw[DIM * DIM];                             // [co][c]

__device__ __forceinline__ uint32_t smem_u32(const void* p) {
    uint32_t a;
    asm("{ .reg .u64 t; cvta.to.shared.u64 t, %1; cvt.u32.u64 %0, t; }" : "=r"(a) : "l"(p));
    return a;
}
__device__ __forceinline__ void mma_f16(float d[4],
        uint32_t a0, uint32_t a1, uint32_t a2, uint32_t a3,
        uint32_t b0, uint32_t b1) {
    asm volatile(
        "mma.sync.aligned.m16n8k16.row.col.f32.f16.f16.f32 "
        "{%0,%1,%2,%3}, {%4,%5,%6,%7}, {%8,%9}, {%0,%1,%2,%3};"
        : "+f"(d[0]), "+f"(d[1]), "+f"(d[2]), "+f"(d[3])
        : "r"(a0), "r"(a1), "r"(a2), "r"(a3), "r"(b0), "r"(b1));
}
__device__ __forceinline__ void ldsm_x4(uint32_t& r0, uint32_t& r1,
                                        uint32_t& r2, uint32_t& r3, uint32_t addr) {
    asm volatile("ldmatrix.sync.aligned.m8n8.x4.shared.b16 {%0,%1,%2,%3}, [%4];"
                 : "=r"(r0), "=r"(r1), "=r"(r2), "=r"(r3) : "r"(addr));
}
__device__ __forceinline__ void ldsm_x4_t(uint32_t& r0, uint32_t& r1,
                                          uint32_t& r2, uint32_t& r3, uint32_t addr) {
    asm volatile("ldmatrix.sync.aligned.m8n8.x4.trans.shared.b16 {%0,%1,%2,%3}, [%4];"
                 : "=r"(r0), "=r"(r1), "=r"(r2), "=r"(r3) : "r"(addr));
}
__device__ __forceinline__ void cp16(uint32_t dst, const void* src, bool pred) {
    asm volatile("cp.async.cg.shared.global [%0], [%1], 16, %2;"
                 :: "r"(dst), "l"(src), "r"(pred ? 16 : 0) : "memory");
}
#define CP_COMMIT() asm volatile("cp.async.commit_group;" ::: "memory")
#define CP_WAIT2()  asm volatile("cp.async.wait_group 2;" ::: "memory")

// ---------------- 0) round proj_w to fp16 ------------------------------------
__global__ void cvt_pw_kernel(const float* __restrict__ pw) {
    int i = blockIdx.x * 256 + threadIdx.x;
    g_pw[i] = __float2half(pw[i]);
}

// ---------------- 1) fused patch embed + qk ----------------------------------
__global__ __launch_bounds__(256) void patchqk16(const float* __restrict__ x,
                                                 const float* __restrict__ w,
                                                 const float* __restrict__ bias,
                                                 const float* __restrict__ qkw) {
    const int bn0 = blockIdx.x * 8;
    __shared__ __align__(16) float sp[8][768];
    __shared__ __align__(16) float sx[8][256];
    for (int idx = threadIdx.x; idx < 8 * 768; idx += 256) {
        int i = idx / 768, j = idx - (idx / 768) * 768;
        int bn = bn0 + i;
        int b = bn / NTOK, n = bn % NTOK;
        int hp = n / HP, wp = n % HP;
        int ci = j >> 8, r = (j >> 4) & 15, cc = j & 15;
        sp[i][j] = x[(((size_t)b * CIN + ci) * HW + hp * PATCH + r) * HW + wp * PATCH + cc];
    }
    __syncthreads();
    const int co = threadIdx.x;
    {
        const float4* wr = (const float4*)(w + (size_t)co * 768);
        float acc[8] = {};
#pragma unroll 2
        for (int j4 = 0; j4 < 192; j4++) {
            float4 w4 = wr[j4];
#pragma unroll
            for (int i = 0; i < 8; i++) {
                float4 s4 = *(const float4*)&sp[i][j4 * 4];
                acc[i] = fmaf(s4.x, w4.x, fmaf(s4.y, w4.y, fmaf(s4.z, w4.z, fmaf(s4.w, w4.w, acc[i]))));
            }
        }
        float bco = bias[co];
#pragma unroll
        for (int i = 0; i < 8; i++) sx[i][co] = acc[i] + bco;
    }
    __syncthreads();
    {
        const float4* w0 = (const float4*)(qkw + (size_t)co * DIM);
        const float4* w1 = (const float4*)(qkw + (size_t)(DIM + co) * DIM);
        float acc0[8] = {}, acc1[8] = {};
#pragma unroll 2
        for (int j4 = 0; j4 < 64; j4++) {
            float4 a = w0[j4];
            float4 bq = w1[j4];
#pragma unroll
            for (int i = 0; i < 8; i++) {
                float4 s4 = *(const float4*)&sx[i][j4 * 4];
                acc0[i] = fmaf(s4.x, a.x,  fmaf(s4.y, a.y,  fmaf(s4.z, a.z,  fmaf(s4.w, a.w,  acc0[i]))));
                acc1[i] = fmaf(s4.x, bq.x, fmaf(s4.y, bq.y, fmaf(s4.z, bq.z, fmaf(s4.w, bq.w, acc1[i]))));
            }
        }
        const int h = co >> 5, d = co & 31;
#pragma unroll
        for (int i = 0; i < 8; i++) {
            int bn = bn0 + i;
            int b = bn / NTOK, n = bn % NTOK;
            size_t off = (((size_t)b * HEADS + h) * NTOK + n) * HD + d;
            g_q[off] = acc0[i];
            g_k[off] = acc1[i];
        }
    }
}

// ---------------- 2) scores + softmax -> attn (fp16, pad zeroed) -------------
__global__ __launch_bounds__(256) void softmax_v2() {
    const int bh = blockIdx.x;
    __shared__ float sk[NTOK][33];
    const float* kb = g_k + (size_t)bh * NTOK * HD;
    for (int i = threadIdx.x; i < NTOK * HD; i += 256)
        sk[i >> 5][i & 31] = kb[i];
    __syncthreads();
    const int wid = threadIdx.x >> 5, lane = threadIdx.x & 31;
    for (int n = wid; n < NTOK; n += 8) {
        float qd = g_q[((size_t)bh * NTOK + n) * HD + lane];
        float acc[7] = {};
#pragma unroll
        for (int d = 0; d < HD; d++) {
            float qv = __shfl_sync(0xffffffffu, qd, d);
#pragma unroll
            for (int j = 0; j < 7; j++) {
                int m = j * 32 + lane;
                int mc = m < NTOK ? m : NTOK - 1;
                acc[j] = fmaf(qv, sk[mc][d], acc[j]);
            }
        }
        float sc[7], mx = -INFINITY;
#pragma unroll
        for (int j = 0; j < 7; j++) {
            int m = j * 32 + lane;
            sc[j] = (m < NTOK) ? acc[j] * 0.17677669529663687f : -INFINITY;
            mx = fmaxf(mx, sc[j]);
        }
#pragma unroll
        for (int off = 16; off > 0; off >>= 1)
            mx = fmaxf(mx, __shfl_xor_sync(0xffffffffu, mx, off));
        float sum = 0.f;
#pragma unroll
        for (int j = 0; j < 7; j++) {
            sc[j] = expf(sc[j] - mx);
            sum += sc[j];
        }
#pragma unroll
        for (int off = 16; off > 0; off >>= 1)
            sum += __shfl_xor_sync(0xffffffffu, sum, off);
        float inv = 1.f / sum;
        __half* arow = g_attn + ((size_t)bh * NTOK + n) * AK;
#pragma unroll
        for (int j = 0; j < 7; j++) {
            int m = j * 32 + lane;
            if (m < NTOK)      arow[m] = __float2half(sc[j] * inv);
            else if (m < AK)   arow[m] = __float2half(0.f);
        }
    }
}

// ---------------- 3) conv3x3 (V) + unfold -> vu (fp16, [m][d']) --------------
__global__ __launch_bounds__(256) void convv_unfold_kernel(
        const float* __restrict__ x,
        const float* __restrict__ vw,
        const float* __restrict__ vb) {
    const int y = blockIdx.x;
    const int b = blockIdx.y;
    __shared__ __align__(16) float srow[CIN][3][226];
    __shared__ __align__(16) float sw[DIM][28];
    __shared__ float sb[DIM];
    const int t = threadIdx.x;
    {
#pragma unroll
        for (int j = 0; j < 27; j++) sw[t][j] = vw[t * 27 + j];
        sw[t][27] = 0.f;
        sb[t] = vb[t];
    }
    for (int i = t; i < CIN * 3 * 226; i += 256) {
        int ci = i / (3 * 226);
        int r  = (i / 226) % 3;
        int xx = i % 226;
        int yy = y + r - 1;
        int xc = xx - 1;
        float v = 0.f;
        if (yy >= 0 && yy < HW && xc >= 0 && xc < HW)
            v = x[(((size_t)b * CIN + ci) * HW + yy) * HW + xc];
        srow[ci][r][xx] = v;
    }
    __syncthreads();
    if (t >= HW) return;

    float xv[28];
#pragma unroll
    for (int ci = 0; ci < CIN; ci++)
#pragma unroll
        for (int r = 0; r < 3; r++)
#pragma unroll
            for (int dx = 0; dx < 3; dx++)
                xv[(ci * 3 + r) * 3 + dx] = srow[ci][r][t + dx];
    xv[27] = 0.f;

    const int hp = y >> 4, pi = y & 15;
    const int wp = t >> 4, pj = t & 15;
    const int n = hp * HP + wp;
#pragma unroll 1
    for (int h = 0; h < HEADS; h++) {
        const int bh = b * HEADS + h;
        size_t base = ((size_t)bh * NTOK + n) * DP + pi * PATCH + pj;
#pragma unroll 4
        for (int cr = 0; cr < 32; cr++) {
            const int c = h * 32 + cr;
            float acc = sb[c];
#pragma unroll
            for (int q = 0; q < 7; q++) {
                float4 w4 = *(const float4*)&sw[c][q * 4];
                acc = fmaf(xv[q * 4 + 0], w4.x, acc);
                acc = fmaf(xv[q * 4 + 1], w4.y, acc);
                acc = fmaf(xv[q * 4 + 2], w4.z, acc);
                acc = fmaf(xv[q * 4 + 3], w4.w, acc);
            }
            g_vu[base + (size_t)cr * 256] = __float2half(acc);
        }
    }
}

// ====== fp16 GEMM: m16n8k16, 256x128 tile, 512 thr, 4-stage x 32k, ldmatrix ==
// A smem: [256 m][20 words]  (16 data words = 32 halves k, 4 pad)
// B smem: [32 k][68 words]   (64 data words = 128 halves n, 4 pad)
#define STAGES  4
#define A_ST_W  5120        // 256*20
#define B_ST_W  2176        // 32*68
#define GEMM_SMEM (STAGES * (A_ST_W + B_ST_W) * 4)   // 116736 B

// one 16-k block of MMAs (kb_ in {0,16})
#define GEMM_KBLOCK(a_st_, b_st_, kb_)                                        \
    do {                                                                      \
        uint32_t af[4][4], bf[4][2];                                          \
        _Pragma("unroll")                                                     \
        for (int mi = 0; mi < 4; mi++) {                                      \
            uint32_t ad = (a_st_) + (((wm * 64 + mi * 16) * 20 + ((kb_) >> 1) + a_lane) << 2); \
            ldsm_x4(af[mi][0], af[mi][1], af[mi][2], af[mi][3], ad);          \
        }                                                                     \
        {                                                                     \
            uint32_t bd0 = (b_st_) + (((kb_) * 68 + b_lane + wn * 16) << 2);  \
            ldsm_x4_t(bf[0][0], bf[0][1], bf[1][0], bf[1][1], bd0);           \
            ldsm_x4_t(bf[2][0], bf[2][1], bf[3][0], bf[3][1], bd0 + 32);      \
        }                                                                     \
        _Pragma("unroll")                                                     \
        for (int mi = 0; mi < 4; mi++)                                        \
            _Pragma("unroll")                                                 \
            for (int ni = 0; ni < 4; ni++)                                    \
                mma_f16(acc[mi][ni], af[mi][0], af[mi][1], af[mi][2],         \
                        af[mi][3], bf[ni][0], bf[ni][1]);                     \
    } while (0)

// lane offsets (words):
//  A (x4): a_lane = ((lane&7)+((lane>>3)&1)*8)*20 + ((lane>>4)&1)*4
//  B (x4.trans): b_lane = ((lane&7)+((lane>>3)&1)*8)*68 + ((lane>>4)&1)*4

// ---------------- 4) attn @ vu -> pre ----------------------------------------
__global__ __launch_bounds__(512) void gemm_attn_vu_f16() {
    extern __shared__ __align__(16) uint32_t dynw[];
    const uint32_t a_u32 = smem_u32(dynw);
    const uint32_t b_u32 = a_u32 + STAGES * A_ST_W * 4;

    const int bh = blockIdx.y;
    const int b = bh >> 3, h = bh & 7;
    const __half* __restrict__ Ah = g_attn + (size_t)bh * NTOK * AK;
    const __half* __restrict__ Bh = g_vu + (size_t)bh * NTOK * DP;
    const int col0 = blockIdx.x * 128;
    const int t = threadIdx.x;
    const int lane = t & 31, w = t >> 5;
    const int wm = w & 3, wn = w >> 2;
    const int fg = lane >> 2, ftg = lane & 3;
    const int a_lane = ((lane & 7) + ((lane >> 3) & 1) * 8) * 20 + ((lane >> 4) & 1) * 4;
    const int b_lane = ((lane & 7) + ((lane >> 3) & 1) * 8) * 68 + ((lane >> 4) & 1) * 4;
    const int arow = t >> 1, aq = (t & 1) * 2;    // A loader: 256 rows x 2 chunks/thr
    const int bkr = t >> 4, bnc = t & 15;         // B loader: 32 rows x 16 chunks
    float acc[4][4][4] = {};

#define AVU_ISSUE(st_, kt_)                                                   \
    do {                                                                      \
        uint32_t ad = a_u32 + ((st_) * A_ST_W + arow * 20 + aq * 4) * 4;      \
        const char* asrc = (const char*)Ah + arow * (AK * 2) + (kt_) * 64 + aq * 16; \
        bool pm = (arow < NTOK);                                              \
        cp16(ad,      asrc,      pm && ((kt_) * 64 + aq * 16)      < AK * 2); \
        cp16(ad + 16, asrc + 16, pm && ((kt_) * 64 + aq * 16 + 16) < AK * 2); \
        int gk = (kt_) * 32 + bkr;                                            \
        uint32_t bd = b_u32 + ((st_) * B_ST_W + bkr * 68 + bnc * 4) * 4;      \
        cp16(bd, Bh + (size_t)gk * DP + col0 + bnc * 8, gk < NTOK);           \
    } while (0)

    const int NK = 7;   // ceil(196/32)
#pragma unroll
    for (int p = 0; p < STAGES - 1; p++) { AVU_ISSUE(p, p); CP_COMMIT(); }
    CP_WAIT2();
    __syncthreads();
#pragma unroll 1
    for (int it = 0; it < NK; it++) {
        int pf = it + STAGES - 1;
        if (pf < NK) AVU_ISSUE(pf & 3, pf);
        CP_COMMIT();
        uint32_t a_st = a_u32 + (it & 3) * A_ST_W * 4;
        uint32_t b_st = b_u32 + (it & 3) * B_ST_W * 4;
        GEMM_KBLOCK(a_st, b_st, 0);
        GEMM_KBLOCK(a_st, b_st, 16);
        CP_WAIT2();
        __syncthreads();
    }
#undef AVU_ISSUE

    // epilogue: fold-scatter into fp16 NCHW pre (__half2 per dp-pair)
#pragma unroll
    for (int mi = 0; mi < 4; mi++) {
#pragma unroll
        for (int half = 0; half < 2; half++) {
            int m = wm * 64 + mi * 16 + fg + half * 8;
            if (m >= NTOK) continue;
            int hp = m / HP, wp = m % HP;
#pragma unroll
            for (int ni = 0; ni < 4; ni++) {
                int dp = col0 + wn * 32 + ni * 8 + ftg * 2;
                int cr = dp >> 8, rem = dp & 255;
                int pi = rem >> 4, pj = rem & 15;
                int c = h * 32 + cr;
                int pix = (hp * PATCH + pi) * HW + wp * PATCH + pj;
                __half2 v = __floats2half2_rn(acc[mi][ni][half * 2 + 0],
                                              acc[mi][ni][half * 2 + 1]);
                *(__half2*)&g_pre[((size_t)b * DIM + c) * PIX + pix] = v;
            }
        }
    }
}

// ---------------- 5) 1x1 proj -------------------------------------------------
__global__ __launch_bounds__(512) void gemm_proj_f16(
        const float* __restrict__ pb,
        float* __restrict__ out) {
    extern __shared__ __align__(16) uint32_t dynw[];
    const uint32_t a_u32 = smem_u32(dynw);
    const uint32_t b_u32 = a_u32 + STAGES * A_ST_W * 4;

    const int b = blockIdx.y;
    const __half* __restrict__ Bh = g_pre + (size_t)b * DIM * PIX;
    float* __restrict__ C = out + (size_t)b * DIM * PIX;
    const int col0 = blockIdx.x * 128;
    const int t = threadIdx.x;
    const int lane = t & 31, w = t >> 5;
    const int wm = w & 3, wn = w >> 2;
    const int fg = lane >> 2, ftg = lane & 3;
    const int a_lane = ((lane & 7) + ((lane >> 3) & 1) * 8) * 20 + ((lane >> 4) & 1) * 4;
    const int b_lane = ((lane & 7) + ((lane >> 3) & 1) * 8) * 68 + ((lane >> 4) & 1) * 4;
    const int arow = t >> 1, aq = (t & 1) * 2;
    const int bkr = t >> 4, bnc = t & 15;
    float acc[4][4][4] = {};

#define PROJ_ISSUE(st_, kt_)                                                  \
    do {                                                                      \
        uint32_t ad = a_u32 + ((st_) * A_ST_W + arow * 20 + aq * 4) * 4;      \
        const char* asrc = (const char*)g_pw + arow * (DIM * 2) + (kt_) * 64 + aq * 16; \
        cp16(ad,      asrc,      true);                                       \
        cp16(ad + 16, asrc + 16, true);                                       \
        int gk = (kt_) * 32 + bkr;                                            \
        uint32_t bd = b_u32 + ((st_) * B_ST_W + bkr * 68 + bnc * 4) * 4;      \
        cp16(bd, Bh + (size_t)gk * PIX + col0 + bnc * 8, true);               \
    } while (0)

    const int NK = 8;   // 256/32
#pragma unroll
    for (int p = 0; p < STAGES - 1; p++) { PROJ_ISSUE(p, p); CP_COMMIT(); }
    CP_WAIT2();
    __syncthreads();
#pragma unroll 1
    for (int it = 0; it < NK; it++) {
        int pf = it + STAGES - 1;
        if (pf < NK) PROJ_ISSUE(pf & 3, pf);
        CP_COMMIT();
        uint32_t a_st = a_u32 + (it & 3) * A_ST_W * 4;
        uint32_t b_st = b_u32 + (it & 3) * B_ST_W * 4;
        GEMM_KBLOCK(a_st, b_st, 0);
        GEMM_KBLOCK(a_st, b_st, 16);
        CP_WAIT2();
        __syncthreads();
    }
#undef PROJ_ISSUE

#pragma unroll
    for (int mi = 0; mi < 4; mi++) {
#pragma unroll
        for (int half = 0; half < 2; half++) {
            int co = wm * 64 + mi * 16 + fg + half * 8;
            float bias = pb[co];
            float* crow = &C[(size_t)co * PIX + col0 + wn * 32 + ftg * 2];
#pragma unroll
            for (int ni = 0; ni < 4; ni++) {
                float2 v = make_float2(acc[mi][ni][half * 2 + 0] + bias,
                                       acc[mi][ni][half * 2 + 1] + bias);
                *(float2*)&crow[ni * 8] = v;
            }
        }
    }
}

// ---------------- launch -----------------------------------------------------
extern "C" void kernel_launch(void* const* d_in, const int* in_sizes, int n_in,
                              void* d_out, int out_size) {
    const float* x       = (const float*)d_in[0];
    const float* patch_w = (const float*)d_in[1];
    const float* patch_b = (const float*)d_in[2];
    const float* qk_w    = (const float*)d_in[3];
    const float* v_w     = (const float*)d_in[4];
    const float* v_b     = (const float*)d_in[5];
    const float* proj_w  = (const float*)d_in[6];
    const float* proj_b  = (const float*)d_in[7];
    float* out = (float*)d_out;

    cudaFuncSetAttribute(gemm_attn_vu_f16,
                         cudaFuncAttributeMaxDynamicSharedMemorySize, GEMM_SMEM);
    cudaFuncSetAttribute(gemm_proj_f16,
                         cudaFuncAttributeMaxDynamicSharedMemorySize, GEMM_SMEM);

    patchqk16<<<BATCH * NTOK / 8, 256>>>(x, patch_w, patch_b, qk_w);
    softmax_v2<<<BATCH * HEADS, 256>>>();
    convv_unfold_kernel<<<dim3(HW, BATCH), 256>>>(x, v_w, v_b);
    gemm_attn_vu_f16<<<dim3(DP / 128, BATCH * HEADS), 512, GEMM_SMEM>>>();
    cvt_pw_kernel<<<DIM * DIM / 256, 256>>>(proj_w);
    gemm_proj_f16<<<dim3(PIX / 128, BATCH), 512, GEMM_SMEM>>>(proj_b, out);
}

// round 12
// speedup vs baseline: 8.6201x; 1.1068x over previous
#include <cuda_runtime.h>
#include <cuda_fp16.h>
#include <math.h>
#include <cstdint>

// Problem constants
#define BATCH 4
#define CIN   3
#define HW    224
#define PATCH 16
#define DIM   256
#define HEADS 8
#define HD    32
#define HP    14
#define NTOK  196
#define DP    8192
#define PIX   50176
#define AK    208          // padded k-stride for g_attn rows (halves), zero-filled

// ---------------- scratch (device globals) ----------------------------------
__device__ __align__(16) float  g_q[BATCH * HEADS * NTOK * HD];
__device__ __align__(16) float  g_k[BATCH * HEADS * NTOK * HD];
__device__ __align__(16) __half g_attn[(size_t)BATCH * HEADS * NTOK * AK];   // [n][k]
__device__ __align__(16) __half g_vu[(size_t)BATCH * HEADS * NTOK * DP];     // [m][d']
__device__ __align__(16) __half g_pre[(size_t)BATCH * DIM * PIX];            // [c][pix]
__device__ __align__(16) __half g_pw[DIM * DIM];                             // [co][c]

__device__ __forceinline__ uint32_t smem_u32(const void* p) {
    uint32_t a;
    asm("{ .reg .u64 t; cvta.to.shared.u64 t, %1; cvt.u32.u64 %0, t; }" : "=r"(a) : "l"(p));
    return a;
}
__device__ __forceinline__ void mma_f16(float d[4],
        uint32_t a0, uint32_t a1, uint32_t a2, uint32_t a3,
        uint32_t b0, uint32_t b1) {
    asm volatile(
        "mma.sync.aligned.m16n8k16.row.col.f32.f16.f16.f32 "
        "{%0,%1,%2,%3}, {%4,%5,%6,%7}, {%8,%9}, {%0,%1,%2,%3};"
        : "+f"(d[0]), "+f"(d[1]), "+f"(d[2]), "+f"(d[3])
        : "r"(a0), "r"(a1), "r"(a2), "r"(a3), "r"(b0), "r"(b1));
}
__device__ __forceinline__ void ldsm_x4(uint32_t& r0, uint32_t& r1,
                                        uint32_t& r2, uint32_t& r3, uint32_t addr) {
    asm volatile("ldmatrix.sync.aligned.m8n8.x4.shared.b16 {%0,%1,%2,%3}, [%4];"
                 : "=r"(r0), "=r"(r1), "=r"(r2), "=r"(r3) : "r"(addr));
}
__device__ __forceinline__ void ldsm_x4_t(uint32_t& r0, uint32_t& r1,
                                          uint32_t& r2, uint32_t& r3, uint32_t addr) {
    asm volatile("ldmatrix.sync.aligned.m8n8.x4.trans.shared.b16 {%0,%1,%2,%3}, [%4];"
                 : "=r"(r0), "=r"(r1), "=r"(r2), "=r"(r3) : "r"(addr));
}
__device__ __forceinline__ void cp16(uint32_t dst, const void* src, bool pred) {
    asm volatile("cp.async.cg.shared.global [%0], [%1], 16, %2;"
                 :: "r"(dst), "l"(src), "r"(pred ? 16 : 0) : "memory");
}
#define CP_COMMIT() asm volatile("cp.async.commit_group;" ::: "memory")
#define CP_WAIT2()  asm volatile("cp.async.wait_group 2;" ::: "memory")

// ---------------- 0) round proj_w to fp16 ------------------------------------
__global__ void cvt_pw_kernel(const float* __restrict__ pw) {
    int i = blockIdx.x * 256 + threadIdx.x;
    g_pw[i] = __float2half(pw[i]);
}

// ---------------- 1) fused patch embed + qk ----------------------------------
__global__ __launch_bounds__(256) void patchqk16(const float* __restrict__ x,
                                                 const float* __restrict__ w,
                                                 const float* __restrict__ bias,
                                                 const float* __restrict__ qkw) {
    const int bn0 = blockIdx.x * 8;
    __shared__ __align__(16) float sp[8][768];
    __shared__ __align__(16) float sx[8][256];
    for (int idx = threadIdx.x; idx < 8 * 768; idx += 256) {
        int i = idx / 768, j = idx - (idx / 768) * 768;
        int bn = bn0 + i;
        int b = bn / NTOK, n = bn % NTOK;
        int hp = n / HP, wp = n % HP;
        int ci = j >> 8, r = (j >> 4) & 15, cc = j & 15;
        sp[i][j] = x[(((size_t)b * CIN + ci) * HW + hp * PATCH + r) * HW + wp * PATCH + cc];
    }
    __syncthreads();
    const int co = threadIdx.x;
    {
        const float4* wr = (const float4*)(w + (size_t)co * 768);
        float acc[8] = {};
#pragma unroll 2
        for (int j4 = 0; j4 < 192; j4++) {
            float4 w4 = wr[j4];
#pragma unroll
            for (int i = 0; i < 8; i++) {
                float4 s4 = *(const float4*)&sp[i][j4 * 4];
                acc[i] = fmaf(s4.x, w4.x, fmaf(s4.y, w4.y, fmaf(s4.z, w4.z, fmaf(s4.w, w4.w, acc[i]))));
            }
        }
        float bco = bias[co];
#pragma unroll
        for (int i = 0; i < 8; i++) sx[i][co] = acc[i] + bco;
    }
    __syncthreads();
    {
        const float4* w0 = (const float4*)(qkw + (size_t)co * DIM);
        const float4* w1 = (const float4*)(qkw + (size_t)(DIM + co) * DIM);
        float acc0[8] = {}, acc1[8] = {};
#pragma unroll 2
        for (int j4 = 0; j4 < 64; j4++) {
            float4 a = w0[j4];
            float4 bq = w1[j4];
#pragma unroll
            for (int i = 0; i < 8; i++) {
                float4 s4 = *(const float4*)&sx[i][j4 * 4];
                acc0[i] = fmaf(s4.x, a.x,  fmaf(s4.y, a.y,  fmaf(s4.z, a.z,  fmaf(s4.w, a.w,  acc0[i]))));
                acc1[i] = fmaf(s4.x, bq.x, fmaf(s4.y, bq.y, fmaf(s4.z, bq.z, fmaf(s4.w, bq.w, acc1[i]))));
            }
        }
        const int h = co >> 5, d = co & 31;
#pragma unroll
        for (int i = 0; i < 8; i++) {
            int bn = bn0 + i;
            int b = bn / NTOK, n = bn % NTOK;
            size_t off = (((size_t)b * HEADS + h) * NTOK + n) * HD + d;
            g_q[off] = acc0[i];
            g_k[off] = acc1[i];
        }
    }
}

// ---------------- 2) scores + softmax -> attn (fp16, pad zeroed) -------------
__global__ __launch_bounds__(256) void softmax_v2() {
    const int bh = blockIdx.x;
    __shared__ float sk[NTOK][33];
    const float* kb = g_k + (size_t)bh * NTOK * HD;
    for (int i = threadIdx.x; i < NTOK * HD; i += 256)
        sk[i >> 5][i & 31] = kb[i];
    __syncthreads();
    const int wid = threadIdx.x >> 5, lane = threadIdx.x & 31;
    for (int n = wid; n < NTOK; n += 8) {
        float qd = g_q[((size_t)bh * NTOK + n) * HD + lane];
        float acc[7] = {};
#pragma unroll
        for (int d = 0; d < HD; d++) {
            float qv = __shfl_sync(0xffffffffu, qd, d);
#pragma unroll
            for (int j = 0; j < 7; j++) {
                int m = j * 32 + lane;
                int mc = m < NTOK ? m : NTOK - 1;
                acc[j] = fmaf(qv, sk[mc][d], acc[j]);
            }
        }
        float sc[7], mx = -INFINITY;
#pragma unroll
        for (int j = 0; j < 7; j++) {
            int m = j * 32 + lane;
            sc[j] = (m < NTOK) ? acc[j] * 0.17677669529663687f : -INFINITY;
            mx = fmaxf(mx, sc[j]);
        }
#pragma unroll
        for (int off = 16; off > 0; off >>= 1)
            mx = fmaxf(mx, __shfl_xor_sync(0xffffffffu, mx, off));
        float sum = 0.f;
#pragma unroll
        for (int j = 0; j < 7; j++) {
            sc[j] = expf(sc[j] - mx);
            sum += sc[j];
        }
#pragma unroll
        for (int off = 16; off > 0; off >>= 1)
            sum += __shfl_xor_sync(0xffffffffu, sum, off);
        float inv = 1.f / sum;
        __half* arow = g_attn + ((size_t)bh * NTOK + n) * AK;
#pragma unroll
        for (int j = 0; j < 7; j++) {
            int m = j * 32 + lane;
            if (m < NTOK)      arow[m] = __float2half(sc[j] * inv);
            else if (m < AK)   arow[m] = __float2half(0.f);
        }
    }
}

// ---------------- 3) conv3x3 (V) + unfold -> vu (fp16, [m][d']) --------------
__global__ __launch_bounds__(256) void convv_unfold_kernel(
        const float* __restrict__ x,
        const float* __restrict__ vw,
        const float* __restrict__ vb) {
    const int y = blockIdx.x;
    const int b = blockIdx.y;
    __shared__ __align__(16) float srow[CIN][3][226];
    __shared__ __align__(16) float sw[DIM][28];
    __shared__ float sb[DIM];
    const int t = threadIdx.x;
    {
#pragma unroll
        for (int j = 0; j < 27; j++) sw[t][j] = vw[t * 27 + j];
        sw[t][27] = 0.f;
        sb[t] = vb[t];
    }
    for (int i = t; i < CIN * 3 * 226; i += 256) {
        int ci = i / (3 * 226);
        int r  = (i / 226) % 3;
        int xx = i % 226;
        int yy = y + r - 1;
        int xc = xx - 1;
        float v = 0.f;
        if (yy >= 0 && yy < HW && xc >= 0 && xc < HW)
            v = x[(((size_t)b * CIN + ci) * HW + yy) * HW + xc];
        srow[ci][r][xx] = v;
    }
    __syncthreads();
    if (t >= HW) return;

    float xv[28];
#pragma unroll
    for (int ci = 0; ci < CIN; ci++)
#pragma unroll
        for (int r = 0; r < 3; r++)
#pragma unroll
            for (int dx = 0; dx < 3; dx++)
                xv[(ci * 3 + r) * 3 + dx] = srow[ci][r][t + dx];
    xv[27] = 0.f;

    const int hp = y >> 4, pi = y & 15;
    const int wp = t >> 4, pj = t & 15;
    const int n = hp * HP + wp;
#pragma unroll 1
    for (int h = 0; h < HEADS; h++) {
        const int bh = b * HEADS + h;
        size_t base = ((size_t)bh * NTOK + n) * DP + pi * PATCH + pj;
#pragma unroll 4
        for (int cr = 0; cr < 32; cr++) {
            const int c = h * 32 + cr;
            float acc = sb[c];
#pragma unroll
            for (int q = 0; q < 7; q++) {
                float4 w4 = *(const float4*)&sw[c][q * 4];
                acc = fmaf(xv[q * 4 + 0], w4.x, acc);
                acc = fmaf(xv[q * 4 + 1], w4.y, acc);
                acc = fmaf(xv[q * 4 + 2], w4.z, acc);
                acc = fmaf(xv[q * 4 + 3], w4.w, acc);
            }
            g_vu[base + (size_t)cr * 256] = __float2half(acc);
        }
    }
}

// == fp16 GEMM: m16n8k16, 128x128 tile, 256 thr (2 CTA/SM), 4-stage x 32k ====
// A smem: [128 m][20 words]  (16 data words = 32 halves k, 4 pad)
// B smem: [32 k][68 words]   (64 data words = 128 halves n, 4 pad)
#define STAGES  4
#define A_ST_W  2560        // 128*20
#define B_ST_W  2176        // 32*68
#define GEMM_SMEM (STAGES * (A_ST_W + B_ST_W) * 4)   // 75776 B

// one 16-k block of MMAs (kb_ in {0,16}); 8 warps: wm = w&1, wn = w>>1
#define GEMM_KBLOCK(a_st_, b_st_, kb_)                                        \
    do {                                                                      \
        uint32_t af[4][4], bf[4][2];                                          \
        _Pragma("unroll")                                                     \
        for (int mi = 0; mi < 4; mi++) {                                      \
            uint32_t ad = (a_st_) + (((wm * 64 + mi * 16) * 20 + ((kb_) >> 1) + a_lane) << 2); \
            ldsm_x4(af[mi][0], af[mi][1], af[mi][2], af[mi][3], ad);          \
        }                                                                     \
        {                                                                     \
            uint32_t bd0 = (b_st_) + (((kb_) * 68 + b_lane + wn * 16) << 2);  \
            ldsm_x4_t(bf[0][0], bf[0][1], bf[1][0], bf[1][1], bd0);           \
            ldsm_x4_t(bf[2][0], bf[2][1], bf[3][0], bf[3][1], bd0 + 32);      \
        }                                                                     \
        _Pragma("unroll")                                                     \
        for (int mi = 0; mi < 4; mi++)                                        \
            _Pragma("unroll")                                                 \
            for (int ni = 0; ni < 4; ni++)                                    \
                mma_f16(acc[mi][ni], af[mi][0], af[mi][1], af[mi][2],         \
                        af[mi][3], bf[ni][0], bf[ni][1]);                     \
    } while (0)

// ---------------- 4) attn @ vu -> pre ----------------------------------------
__global__ __launch_bounds__(256, 2) void gemm_attn_vu_f16() {
    extern __shared__ __align__(16) uint32_t dynw[];
    const uint32_t a_u32 = smem_u32(dynw);
    const uint32_t b_u32 = a_u32 + STAGES * A_ST_W * 4;

    const int bh = blockIdx.z;
    const int b = bh >> 3, h = bh & 7;
    const __half* __restrict__ Ah = g_attn + (size_t)bh * NTOK * AK;
    const __half* __restrict__ Bh = g_vu + (size_t)bh * NTOK * DP;
    const int row0 = blockIdx.y * 128;
    const int col0 = blockIdx.x * 128;
    const int t = threadIdx.x;
    const int lane = t & 31, w = t >> 5;
    const int wm = w & 1, wn = w >> 1;
    const int fg = lane >> 2, ftg = lane & 3;
    const int a_lane = ((lane & 7) + ((lane >> 3) & 1) * 8) * 20 + ((lane >> 4) & 1) * 4;
    const int b_lane = ((lane & 7) + ((lane >> 3) & 1) * 8) * 68 + ((lane >> 4) & 1) * 4;
    const int arow = t >> 1, aq = (t & 1) * 2;    // A loader: 128 rows x 2 chunks/thr
    const int bkr = t >> 4, bnc = t & 15;         // B loader: rows bkr, bkr+16
    float acc[4][4][4] = {};

#define AVU_ISSUE(st_, kt_)                                                   \
    do {                                                                      \
        int gm = row0 + arow;                                                 \
        uint32_t ad = a_u32 + ((st_) * A_ST_W + arow * 20 + aq * 4) * 4;      \
        const char* asrc = (const char*)Ah + gm * (AK * 2) + (kt_) * 64 + aq * 16; \
        bool pm = (gm < NTOK);                                                \
        cp16(ad,      asrc,      pm && ((kt_) * 64 + aq * 16)      < AK * 2); \
        cp16(ad + 16, asrc + 16, pm && ((kt_) * 64 + aq * 16 + 16) < AK * 2); \
        int gk0 = (kt_) * 32 + bkr;                                           \
        int gk1 = gk0 + 16;                                                   \
        uint32_t bd = b_u32 + ((st_) * B_ST_W + bkr * 68 + bnc * 4) * 4;      \
        cp16(bd, Bh + (size_t)gk0 * DP + col0 + bnc * 8, gk0 < NTOK);         \
        cp16(bd + 16 * 68 * 4, Bh + (size_t)gk1 * DP + col0 + bnc * 8, gk1 < NTOK); \
    } while (0)

    const int NK = 7;   // ceil(196/32)
#pragma unroll
    for (int p = 0; p < STAGES - 1; p++) { AVU_ISSUE(p, p); CP_COMMIT(); }
    CP_WAIT2();
    __syncthreads();
#pragma unroll 1
    for (int it = 0; it < NK; it++) {
        int pf = it + STAGES - 1;
        if (pf < NK) AVU_ISSUE(pf & 3, pf);
        CP_COMMIT();
        uint32_t a_st = a_u32 + (it & 3) * A_ST_W * 4;
        uint32_t b_st = b_u32 + (it & 3) * B_ST_W * 4;
        GEMM_KBLOCK(a_st, b_st, 0);
        GEMM_KBLOCK(a_st, b_st, 16);
        CP_WAIT2();
        __syncthreads();
    }
#undef AVU_ISSUE

    // epilogue: fold-scatter into fp16 NCHW pre (__half2 per dp-pair)
#pragma unroll
    for (int mi = 0; mi < 4; mi++) {
#pragma unroll
        for (int half = 0; half < 2; half++) {
            int m = row0 + wm * 64 + mi * 16 + fg + half * 8;
            if (m >= NTOK) continue;
            int hp = m / HP, wp = m % HP;
#pragma unroll
            for (int ni = 0; ni < 4; ni++) {
                int dp = col0 + wn * 32 + ni * 8 + ftg * 2;
                int cr = dp >> 8, rem = dp & 255;
                int pi = rem >> 4, pj = rem & 15;
                int c = h * 32 + cr;
                int pix = (hp * PATCH + pi) * HW + wp * PATCH + pj;
                __half2 v = __floats2half2_rn(acc[mi][ni][half * 2 + 0],
                                              acc[mi][ni][half * 2 + 1]);
                *(__half2*)&g_pre[((size_t)b * DIM + c) * PIX + pix] = v;
            }
        }
    }
}

// ---------------- 5) 1x1 proj -------------------------------------------------
__global__ __launch_bounds__(256, 2) void gemm_proj_f16(
        const float* __restrict__ pb,
        float* __restrict__ out) {
    extern __shared__ __align__(16) uint32_t dynw[];
    const uint32_t a_u32 = smem_u32(dynw);
    const uint32_t b_u32 = a_u32 + STAGES * A_ST_W * 4;

    const int b = blockIdx.z;
    const __half* __restrict__ Bh = g_pre + (size_t)b * DIM * PIX;
    float* __restrict__ C = out + (size_t)b * DIM * PIX;
    const int row0 = blockIdx.y * 128;
    const int col0 = blockIdx.x * 128;
    const int t = threadIdx.x;
    const int lane = t & 31, w = t >> 5;
    const int wm = w & 1, wn = w >> 1;
    const int fg = lane >> 2, ftg = lane & 3;
    const int a_lane = ((lane & 7) + ((lane >> 3) & 1) * 8) * 20 + ((lane >> 4) & 1) * 4;
    const int b_lane = ((lane & 7) + ((lane >> 3) & 1) * 8) * 68 + ((lane >> 4) & 1) * 4;
    const int arow = t >> 1, aq = (t & 1) * 2;
    const int bkr = t >> 4, bnc = t & 15;
    float acc[4][4][4] = {};

#define PROJ_ISSUE(st_, kt_)                                                  \
    do {                                                                      \
        uint32_t ad = a_u32 + ((st_) * A_ST_W + arow * 20 + aq * 4) * 4;      \
        const char* asrc = (const char*)g_pw + (row0 + arow) * (DIM * 2) + (kt_) * 64 + aq * 16; \
        cp16(ad,      asrc,      true);                                       \
        cp16(ad + 16, asrc + 16, true);                                       \
        int gk0 = (kt_) * 32 + bkr;                                           \
        uint32_t bd = b_u32 + ((st_) * B_ST_W + bkr * 68 + bnc * 4) * 4;      \
        cp16(bd, Bh + (size_t)gk0 * PIX + col0 + bnc * 8, true);              \
        cp16(bd + 16 * 68 * 4, Bh + (size_t)(gk0 + 16) * PIX + col0 + bnc * 8, true); \
    } while (0)

    const int NK = 8;   // 256/32
#pragma unroll
    for (int p = 0; p < STAGES - 1; p++) { PROJ_ISSUE(p, p); CP_COMMIT(); }
    CP_WAIT2();
    __syncthreads();
#pragma unroll 1
    for (int it = 0; it < NK; it++) {
        int pf = it + STAGES - 1;
        if (pf < NK) PROJ_ISSUE(pf & 3, pf);
        CP_COMMIT();
        uint32_t a_st = a_u32 + (it & 3) * A_ST_W * 4;
        uint32_t b_st = b_u32 + (it & 3) * B_ST_W * 4;
        GEMM_KBLOCK(a_st, b_st, 0);
        GEMM_KBLOCK(a_st, b_st, 16);
        CP_WAIT2();
        __syncthreads();
    }
#undef PROJ_ISSUE

#pragma unroll
    for (int mi = 0; mi < 4; mi++) {
#pragma unroll
        for (int half = 0; half < 2; half++) {
            int co = row0 + wm * 64 + mi * 16 + fg + half * 8;
            float bias = pb[co];
            float* crow = &C[(size_t)co * PIX + col0 + wn * 32 + ftg * 2];
#pragma unroll
            for (int ni = 0; ni < 4; ni++) {
                float2 v = make_float2(acc[mi][ni][half * 2 + 0] + bias,
                                       acc[mi][ni][half * 2 + 1] + bias);
                *(float2*)&crow[ni * 8] = v;
            }
        }
    }
}

// ---------------- launch -----------------------------------------------------
extern "C" void kernel_launch(void* const* d_in, const int* in_sizes, int n_in,
                              void* d_out, int out_size) {
    const float* x       = (const float*)d_in[0];
    const float* patch_w = (const float*)d_in[1];
    const float* patch_b = (const float*)d_in[2];
    const float* qk_w    = (const float*)d_in[3];
    const float* v_w     = (const float*)d_in[4];
    const float* v_b     = (const float*)d_in[5];
    const float* proj_w  = (const float*)d_in[6];
    const float* proj_b  = (const float*)d_in[7];
    float* out = (float*)d_out;

    cudaFuncSetAttribute(gemm_attn_vu_f16,
                         cudaFuncAttributeMaxDynamicSharedMemorySize, GEMM_SMEM);
    cudaFuncSetAttribute(gemm_proj_f16,
                         cudaFuncAttributeMaxDynamicSharedMemorySize, GEMM_SMEM);

    patchqk16<<<BATCH * NTOK / 8, 256>>>(x, patch_w, patch_b, qk_w);
    softmax_v2<<<BATCH * HEADS, 256>>>();
    convv_unfold_kernel<<<dim3(HW, BATCH), 256>>>(x, v_w, v_b);
    gemm_attn_vu_f16<<<dim3(DP / 128, 2, BATCH * HEADS), 256, GEMM_SMEM>>>();
    cvt_pw_kernel<<<DIM * DIM / 256, 256>>>(proj_w);
    gemm_proj_f16<<<dim3(PIX / 128, 2, BATCH), 256, GEMM_SMEM>>>(proj_b, out);
}